// round 1
// baseline (speedup 1.0000x reference)
#include <cuda_runtime.h>
#include <math.h>

#define BQ   32768
#define NND  5
#define DDIM 32
#define HDIM 128
#define NE   10
#define TH3  384

#define OFF_V    (BQ*NND*DDIM)              /* 5242880  */
#define OFF_HID  (2*BQ*NND*DDIM)            /* 10485760 */
#define OFF_LOSS (OFF_HID + 2*BQ*HDIM)      /* 18874368 */

#define ZALPHA 1.959963984540054f

// ----------------------------- device scratch -----------------------------
__device__ float g_bufA[BQ*NND*HDIM];
__device__ float g_bufB[BQ*NND*HDIM];
__device__ float g_mean[BQ*NND*HDIM];
__device__ float g_z  [BQ*NND*HDIM];
__device__ float g_ps [BQ*NND*HDIM];
__device__ float g_m1 [BQ*NND*HDIM];
__device__ float g_d1 [BQ*NND*HDIM];
__device__ float g_gf [BQ*HDIM];
__device__ float g_WihT[2*HDIM*TH3];
__device__ float g_WhhT[2*HDIM*TH3];
__device__ float g_klpart[4096];
__device__ float g_lzpart[10240];
__device__ float g_losspart[2560*132];

// ------------------------------- helpers ----------------------------------
__device__ __forceinline__ float warp_sum(float v){
#pragma unroll
  for (int o=16;o>0;o>>=1) v += __shfl_xor_sync(0xffffffffu, v, o);
  return v;
}
__device__ __forceinline__ float softplusf(float x){
  return fmaxf(x,0.f) + log1pf(expf(-fabsf(x)));
}
__device__ __forceinline__ float mishf(float x){ return x*tanhf(softplusf(x)); }
__device__ __forceinline__ float sigmf(float x){ return 1.f/(1.f+expf(-x)); }

// cross-warp (4 warps) deterministic scalar reduce -> part[blockIdx.x]
#define BLOCK_REDUCE_TO(part, val)                                      \
  do {                                                                  \
    float _v = warp_sum(val);                                           \
    __shared__ float _sred[4];                                          \
    if ((threadIdx.x & 31) == 0) _sred[threadIdx.x >> 5] = _v;          \
    __syncthreads();                                                    \
    if (threadIdx.x == 0)                                               \
      part[blockIdx.x] = (_sred[0]+_sred[1]) + (_sred[2]+_sred[3]);     \
  } while (0)

// --------------------------- 0: GRU weight transpose -----------------------
__global__ void k_transpose(const float* __restrict__ Wih,
                            const float* __restrict__ Whh){
  int idx = blockIdx.x*blockDim.x + threadIdx.x;
  if (idx >= 2*2*TH3*HDIM) return;
  int which = idx / (2*TH3*HDIM);
  int r = idx % (2*TH3*HDIM);
  int l = r / (TH3*HDIM);
  int jr = r % (TH3*HDIM);
  int j = jr / HDIM, k = jr % HDIM;
  const float* src = which ? Whh : Wih;
  float* dst = which ? g_WhhT : g_WihT;
  dst[l*HDIM*TH3 + k*TH3 + j] = src[r];
}

// ------------------------------ 1: encoder ---------------------------------
__global__ __launch_bounds__(128) void k_enc(
    const float* __restrict__ x, const float* __restrict__ W1,
    const float* __restrict__ b1, const float* __restrict__ W2,
    const float* __restrict__ b2){
  const int BT = 16;
  int n = blockIdx.y, b0 = blockIdx.x*BT, t = threadIdx.x;
  __shared__ float s_x[BT*DDIM];
  __shared__ float s_h[BT*HDIM];
  for (int idx=t; idx<BT*DDIM; idx+=128){
    int r = idx/DDIM, d = idx%DDIM;
    s_x[idx] = x[(b0+r)*NND*DDIM + n*DDIM + d];
  }
  __syncthreads();
  float acc[BT];
  float bb = b1[n*HDIM + t];
#pragma unroll
  for (int r=0;r<BT;r++) acc[r] = bb;
  for (int d=0; d<DDIM; d++){
    float w = W1[(n*DDIM + d)*HDIM + t];
#pragma unroll
    for (int r=0;r<BT;r++) acc[r] += s_x[r*DDIM+d]*w;
  }
#pragma unroll
  for (int r=0;r<BT;r++) s_h[r*HDIM+t] = fmaxf(acc[r], 0.f);
  __syncthreads();
  float b2v = b2[n*HDIM + t];
#pragma unroll
  for (int r=0;r<BT;r++) acc[r] = b2v;
  for (int k=0;k<HDIM;k++){
    float w = W2[(n*HDIM + k)*HDIM + t];
#pragma unroll
    for (int r=0;r<BT;r++) acc[r] += s_h[r*HDIM+k]*w;
  }
#pragma unroll
  for (int r=0;r<BT;r++)
    g_bufA[(b0+r)*NND*HDIM + n*HDIM + t] = acc[r];
}

// ------------------------------- 2: GCN ------------------------------------
__global__ __launch_bounds__(128) void k_gcn(
    int l, const float* __restrict__ ew,
    const int* __restrict__ esrc, const int* __restrict__ edst,
    const float* __restrict__ W, const float* __restrict__ bias){
  const int BT = 8;
  int b0 = blockIdx.x*BT, t = threadIdx.x;
  const float* gin  = (l==0) ? g_bufA : g_bufB;
  float*       gout = (l==0) ? g_bufB : g_bufA;
  __shared__ float s_g[NND*BT*HDIM];
  __shared__ float s_a[NND*BT*HDIM];
  __shared__ float s_ew[BT*NE];
  __shared__ int s_src[NE], s_dst[NE];
  for (int idx=t; idx<NND*BT*HDIM; idx+=128){
    int r = idx/(NND*HDIM), rem = idx%(NND*HDIM);
    int v = rem/HDIM, k = rem%HDIM;
    s_g[(v*BT+r)*HDIM + k] = gin[(b0+r)*NND*HDIM + rem];
  }
  if (t < BT*NE) s_ew[t] = ew[(b0 + t/NE)*NE + (t%NE)];
  if (t < NE){ s_src[t] = esrc[t]; s_dst[t] = edst[t]; }
  __syncthreads();
  // agg[v] = g[v] + sum_{e: dst_e==v} ew[e]*g[src_e]
  for (int vr=0; vr<NND*BT; vr++){
    int v = vr/BT, r = vr%BT;
    float a = s_g[vr*HDIM + t];
#pragma unroll
    for (int e=0;e<NE;e++)
      if (s_dst[e] == v) a += s_ew[r*NE+e]*s_g[(s_src[e]*BT+r)*HDIM + t];
    s_a[vr*HDIM + t] = a;
  }
  __syncthreads();
  float acc[NND*BT];
  float bb = bias[l*HDIM + t];
#pragma unroll
  for (int i=0;i<NND*BT;i++) acc[i] = bb;
  for (int k=0;k<HDIM;k++){
    float w = W[l*HDIM*HDIM + k*HDIM + t];
#pragma unroll
    for (int i=0;i<NND*BT;i++) acc[i] += s_a[i*HDIM+k]*w;
  }
#pragma unroll
  for (int i=0;i<NND*BT;i++){
    int v = i/BT, r = i%BT;
    gout[(b0+r)*NND*HDIM + v*HDIM + t] = fmaxf(acc[i], 0.f);
  }
}

// -------------------- 3: mu/sig heads + KL + graph_feat --------------------
__global__ __launch_bounds__(128) void k_musig(
    const float* __restrict__ muW, const float* __restrict__ mub,
    const float* __restrict__ sigW, const float* __restrict__ sigb){
  const int BT = 8;
  int b0 = blockIdx.x*BT, t = threadIdx.x;
  __shared__ float s_g[NND*BT*HDIM];
  for (int idx=t; idx<NND*BT*HDIM; idx+=128){
    int r = idx/(NND*HDIM), rem = idx%(NND*HDIM);
    int v = rem/HDIM, k = rem%HDIM;
    s_g[(v*BT+r)*HDIM + k] = g_bufA[(b0+r)*NND*HDIM + rem];
  }
  __syncthreads();
  float gf[BT];
#pragma unroll
  for (int r=0;r<BT;r++) gf[r] = 0.f;
  float kll = 0.f;
  float mb = mub[t], sb = sigb[t];
  for (int v=0; v<NND; v++){
    float am[BT], as_[BT];
#pragma unroll
    for (int r=0;r<BT;r++){ am[r]=mb; as_[r]=sb; }
    for (int k=0;k<HDIM;k++){
      float wm = muW[k*HDIM+t], ws = sigW[k*HDIM+t];
#pragma unroll
      for (int r=0;r<BT;r++){
        float f = s_g[(v*BT+r)*HDIM + k];
        am[r]  += f*wm;
        as_[r] += f*ws;
      }
    }
#pragma unroll
    for (int r=0;r<BT;r++){
      float mean = am[r];
      g_mean[(b0+r)*NND*HDIM + v*HDIM + t] = mean;
      float sp  = softplusf(as_[r]);
      float var = sp*sp;
      kll += mean*mean + var - logf(var + 1e-8f) - 1.f;
      gf[r] += mean;
    }
  }
#pragma unroll
  for (int r=0;r<BT;r++) g_gf[(b0+r)*HDIM + t] = gf[r]*(1.f/NND);
  BLOCK_REDUCE_TO(g_klpart, kll);
}

// -------------------------------- 4: GRU -----------------------------------
__global__ __launch_bounds__(128) void k_gru(
    int l, const float* __restrict__ xin_opt, const float* __restrict__ hist,
    const float* __restrict__ bih, const float* __restrict__ bhh,
    float* __restrict__ hout){
  const int BT = 4;
  int b0 = blockIdx.x*BT, t = threadIdx.x;
  const float* xin = xin_opt ? xin_opt : g_gf;
  __shared__ float s_x[BT*HDIM], s_h[BT*HDIM];
  for (int idx=t; idx<BT*HDIM; idx+=128){
    int r = idx/HDIM, k = idx%HDIM;
    s_x[idx] = xin[(b0+r)*HDIM + k];
    s_h[idx] = hist[l*BQ*HDIM + (b0+r)*HDIM + k];
  }
  __syncthreads();
  float air[BT], aiz[BT], ain[BT], ahr[BT], ahz[BT], ahn[BT];
#pragma unroll
  for (int r=0;r<BT;r++){ air[r]=aiz[r]=ain[r]=ahr[r]=ahz[r]=ahn[r]=0.f; }
  const float* WiT = g_WihT + l*HDIM*TH3;
  const float* WhT = g_WhhT + l*HDIM*TH3;
  for (int k=0;k<HDIM;k++){
    float wir = WiT[k*TH3 + t];
    float wiz = WiT[k*TH3 + HDIM + t];
    float win = WiT[k*TH3 + 2*HDIM + t];
    float whr = WhT[k*TH3 + t];
    float whz = WhT[k*TH3 + HDIM + t];
    float whn = WhT[k*TH3 + 2*HDIM + t];
#pragma unroll
    for (int r=0;r<BT;r++){
      float xv = s_x[r*HDIM+k], hv = s_h[r*HDIM+k];
      air[r] += xv*wir; aiz[r] += xv*wiz; ain[r] += xv*win;
      ahr[r] += hv*whr; ahz[r] += hv*whz; ahn[r] += hv*whn;
    }
  }
  float bir = bih[l*TH3 + t], biz = bih[l*TH3 + HDIM + t], bin_ = bih[l*TH3 + 2*HDIM + t];
  float bhr = bhh[l*TH3 + t], bhz = bhh[l*TH3 + HDIM + t], bhn = bhh[l*TH3 + 2*HDIM + t];
#pragma unroll
  for (int r=0;r<BT;r++){
    float rg = sigmf(air[r]+bir + ahr[r]+bhr);
    float zg = sigmf(aiz[r]+biz + ahz[r]+bhz);
    float ng = tanhf(ain[r]+bin_ + rg*(ahn[r]+bhn));
    float hp = s_h[r*HDIM + t];
    hout[l*BQ*HDIM + (b0+r)*HDIM + t] = (1.f-zg)*ng + zg*hp;
  }
}

// --------------- 5: causal solve (fwd subst) + parent_sum ------------------
__global__ __launch_bounds__(128) void k_causal(
    const float* __restrict__ ew, const float* __restrict__ cm,
    const int* __restrict__ esrc, const int* __restrict__ edst){
  int b = blockIdx.x, t = threadIdx.x;
  __shared__ float s_ew[NE], s_cm[NND*NND];
  __shared__ int s_src[NE], s_dst[NE];
  if (t < NE){ s_ew[t] = ew[b*NE + t]; s_src[t] = esrc[t]; s_dst[t] = edst[t]; }
  if (t < NND*NND) s_cm[t] = cm[t];
  __syncthreads();
  int base = b*NND*HDIM + t;
  float z[NND];
#pragma unroll
  for (int j=0;j<NND;j++) z[j] = g_mean[base + j*HDIM];
#pragma unroll
  for (int j=1;j<NND;j++){
    float add = 0.f;
#pragma unroll
    for (int e=0;e<NE;e++){
      if (s_dst[e] == j){
        int s = s_src[e];
        float zs = (s==0)?z[0]:((s==1)?z[1]:((s==2)?z[2]:z[3]));
        add += s_ew[e]*s_cm[s*NND + j]*zs;
      }
    }
    z[j] += add;
  }
#pragma unroll
  for (int j=0;j<NND;j++) g_z[base + j*HDIM] = z[j];
#pragma unroll
  for (int j=0;j<NND;j++){
    float ps = 0.f;
#pragma unroll
    for (int i=0;i<NND;i++)
      if (s_cm[i*NND + j] != 0.f) ps += z[i];
    g_ps[base + j*HDIM] = ps;
  }
}

// --------------- 6: cm MLP layer 1 (ps -> mish hidden) ---------------------
__global__ __launch_bounds__(128) void k_cm1(
    const float* __restrict__ W, const float* __restrict__ bias){
  const int BT = 16;
  int r0 = blockIdx.x*BT, t = threadIdx.x;
  __shared__ float s_in[BT*HDIM];
  for (int idx=t; idx<BT*HDIM; idx+=128)
    s_in[idx] = g_ps[r0*HDIM + idx];
  __syncthreads();
  float acc[BT];
  float bb = bias[t];
#pragma unroll
  for (int r=0;r<BT;r++) acc[r] = bb;
  for (int k=0;k<HDIM;k++){
    float w = W[k*HDIM + t];
#pragma unroll
    for (int r=0;r<BT;r++) acc[r] += s_in[r*HDIM+k]*w;
  }
#pragma unroll
  for (int r=0;r<BT;r++) g_m1[(r0+r)*HDIM + t] = mishf(acc[r]);
}

// --------------- 7: cm MLP layer 2 + l_z partial ---------------------------
__global__ __launch_bounds__(128) void k_cm2(
    const float* __restrict__ W, const float* __restrict__ bias){
  const int BT = 16;
  int r0 = blockIdx.x*BT, t = threadIdx.x;
  __shared__ float s_in[BT*HDIM];
  for (int idx=t; idx<BT*HDIM; idx+=128)
    s_in[idx] = g_m1[r0*HDIM + idx];
  __syncthreads();
  float acc[BT];
  float bb = bias[t];
#pragma unroll
  for (int r=0;r<BT;r++) acc[r] = bb;
  for (int k=0;k<HDIM;k++){
    float w = W[k*HDIM + t];
#pragma unroll
    for (int r=0;r<BT;r++) acc[r] += s_in[r*HDIM+k]*w;
  }
  float lz = 0.f;
#pragma unroll
  for (int r=0;r<BT;r++){
    float df = g_z[(r0+r)*HDIM + t] - acc[r];
    lz += df*df;
  }
  BLOCK_REDUCE_TO(g_lzpart, lz);
}

// --------------- 8: decoder layer 1 (z -> mish d1) -------------------------
__global__ __launch_bounds__(128) void k_dec1(
    const float* __restrict__ W, const float* __restrict__ bias){
  const int BT = 16;
  int n = blockIdx.y, b0 = blockIdx.x*BT, t = threadIdx.x;
  __shared__ float s_in[BT*HDIM];
  for (int idx=t; idx<BT*HDIM; idx+=128){
    int r = idx/HDIM, k = idx%HDIM;
    s_in[idx] = g_z[(b0+r)*NND*HDIM + n*HDIM + k];
  }
  __syncthreads();
  float acc[BT];
  float bb = bias[n*HDIM + t];
#pragma unroll
  for (int r=0;r<BT;r++) acc[r] = bb;
  const float* Wp = W + n*HDIM*HDIM;
  for (int k=0;k<HDIM;k++){
    float w = Wp[k*HDIM + t];
#pragma unroll
    for (int r=0;r<BT;r++) acc[r] += s_in[r*HDIM+k]*w;
  }
#pragma unroll
  for (int r=0;r<BT;r++)
    g_d1[(b0+r)*NND*HDIM + n*HDIM + t] = mishf(acc[r]);
}

// --------------- 9: decoder layer 2 + per-element losses -------------------
__global__ __launch_bounds__(128) void k_dec2(
    const float* __restrict__ W2, const float* __restrict__ b2,
    const float* __restrict__ yt_g, float* __restrict__ out){
  const int BT = 64;
  int n = blockIdx.y, b0 = blockIdx.x*BT;
  int tid = threadIdx.x, w = tid >> 5, d = tid & 31;
  __shared__ float s_d1[BT*HDIM];
  for (int idx=tid; idx<BT*HDIM; idx+=128){
    int r = idx/HDIM, k = idx%HDIM;
    s_d1[idx] = g_d1[(b0+r)*NND*HDIM + n*HDIM + k];
  }
  __syncthreads();
  float accm[16], accv[16];
#pragma unroll
  for (int r=0;r<16;r++){ accm[r]=0.f; accv[r]=0.f; }
  const float* Wp = W2 + n*HDIM*2*DDIM;
  int rbase = w*16;
  for (int k=0;k<HDIM;k++){
    float wm = Wp[k*2*DDIM + d];
    float wv = Wp[k*2*DDIM + DDIM + d];
#pragma unroll
    for (int r=0;r<16;r++){
      float f = s_d1[(rbase+r)*HDIM + k];
      accm[r] += f*wm;
      accv[r] += f*wv;
    }
  }
  float bm = b2[n*2*DDIM + d], bv = b2[n*2*DDIM + DDIM + d];
  float ll=0.f, sq4=0.f, bce=0.f;
  float piw=0.f, kd=0.f, mn=1e30f, mx=-1e30f;
#pragma unroll
  for (int r=0;r<16;r++){
    int b = b0 + rbase + r;
    float ym = accm[r] + bm;
    float yv = expf(accv[r] + bv);
    int oidx = b*NND*DDIM + n*DDIM + d;
    out[oidx] = ym;
    out[OFF_V + oidx] = yv;
    float yt = yt_g[oidx];
    float vs = yv + 1e-6f;
    float diff = yt - ym;
    ll += -0.5f*(diff*diff/vs + logf(6.2831853071795864f*vs));
    if (n < 4) sq4 += diff*diff;
    if (n == 4){
      float lg = ym;
      bce += fmaxf(lg,0.f) - lg*yt + log1pf(expf(-fabsf(lg)));
    }
    float s  = sqrtf(vs);
    float lo = ym - ZALPHA*s, up = ym + ZALPHA*s;
    float kf = (yt >= lo && yt <= up) ? 1.f : 0.f;
    kd  += kf;
    piw += (up-lo)*kf;
    mn = fminf(mn, yt);
    mx = fmaxf(mx, yt);
  }
  ll  = warp_sum(ll);
  sq4 = warp_sum(sq4);
  bce = warp_sum(bce);
  __shared__ float s_sc[3][4];
  __shared__ float s_vec[4][4][32];
  if (d == 0){ s_sc[0][w]=ll; s_sc[1][w]=sq4; s_sc[2][w]=bce; }
  s_vec[0][w][d]=piw; s_vec[1][w][d]=kd; s_vec[2][w][d]=mn; s_vec[3][w][d]=mx;
  __syncthreads();
  int blk = blockIdx.y*gridDim.x + blockIdx.x;
  float* P = g_losspart + blk*132;
  if (tid == 0){
    P[0] = (s_sc[0][0]+s_sc[0][1]) + (s_sc[0][2]+s_sc[0][3]);
    P[1] = (s_sc[1][0]+s_sc[1][1]) + (s_sc[1][2]+s_sc[1][3]);
    P[2] = (s_sc[2][0]+s_sc[2][1]) + (s_sc[2][2]+s_sc[2][3]);
    P[3] = 0.f;
  }
  if (w == 0){
    P[4+d]   = (s_vec[0][0][d]+s_vec[0][1][d]) + (s_vec[0][2][d]+s_vec[0][3][d]);
    P[36+d]  = (s_vec[1][0][d]+s_vec[1][1][d]) + (s_vec[1][2][d]+s_vec[1][3][d]);
    P[68+d]  = fminf(fminf(s_vec[2][0][d],s_vec[2][1][d]), fminf(s_vec[2][2][d],s_vec[2][3][d]));
    P[100+d] = fmaxf(fmaxf(s_vec[3][0][d],s_vec[3][1][d]), fmaxf(s_vec[3][2][d],s_vec[3][3][d]));
  }
}

// --------------- 10: final deterministic reduce + losses -------------------
__global__ void k_final(float* __restrict__ out){
  int t = threadIdx.x;
  __shared__ float s_acc[136];
  if (t < 132){
    bool ismin = (t >= 68 && t < 100), ismax = (t >= 100);
    float s0,s1,s2,s3;
    if (ismin){ s0=s1=s2=s3=1e30f; }
    else if (ismax){ s0=s1=s2=s3=-1e30f; }
    else { s0=s1=s2=s3=0.f; }
    for (int i=0; i<2560; i+=4){
      float a = g_losspart[(i+0)*132 + t];
      float b = g_losspart[(i+1)*132 + t];
      float c = g_losspart[(i+2)*132 + t];
      float e = g_losspart[(i+3)*132 + t];
      if (ismin){ s0=fminf(s0,a); s1=fminf(s1,b); s2=fminf(s2,c); s3=fminf(s3,e); }
      else if (ismax){ s0=fmaxf(s0,a); s1=fmaxf(s1,b); s2=fmaxf(s2,c); s3=fmaxf(s3,e); }
      else { s0+=a; s1+=b; s2+=c; s3+=e; }
    }
    s_acc[t] = ismin ? fminf(fminf(s0,s1),fminf(s2,s3))
             : ismax ? fmaxf(fmaxf(s0,s1),fmaxf(s2,s3))
             : (s0+s1)+(s2+s3);
  } else if (t == 132){
    float s0=0,s1=0,s2=0,s3=0;
    for (int i=0;i<4096;i+=4){
      s0+=g_klpart[i]; s1+=g_klpart[i+1]; s2+=g_klpart[i+2]; s3+=g_klpart[i+3];
    }
    s_acc[132] = (s0+s1)+(s2+s3);
  } else if (t == 133){
    float s0=0,s1=0,s2=0,s3=0;
    for (int i=0;i<10240;i+=4){
      s0+=g_lzpart[i]; s1+=g_lzpart[i+1]; s2+=g_lzpart[i+2]; s3+=g_lzpart[i+3];
    }
    s_acc[133] = (s0+s1)+(s2+s3);
  }
  __syncthreads();
  if (t == 0){
    float S_ll = s_acc[0], S_sq4 = s_acc[1], S_bce = s_acc[2];
    float kl = 0.5f*s_acc[132];
    float S_lz = s_acc[133];
    float mean_ll = S_ll / 5242880.0f;                 // B*N*D
    float elbo = kl/32768.0f - mean_ll;
    float l_reg = (S_sq4/32.0f) / (4.0f*32768.0f + 1e-6f);
    float l_cls = (S_bce/32.0f) / (32768.0f + 1e-6f);
    float l_rec = l_reg + l_cls;
    float Sk = 0.f, pin = 0.f;
    for (int d=0; d<32; d++){
      float kdv = s_acc[36+d];
      Sk += kdv;
      pin += s_acc[4+d] / (kdv + 1e-6f) / (s_acc[100+d] - s_acc[68+d] + 1e-6f);
    }
    float picp  = Sk / 5242880.0f;
    float pinaw = pin / 32.0f;
    float l_pi  = pinaw - sqrtf(5.0f)*picp;
    float l_z   = S_lz / 20971520.0f;                  // B*N*CD
    float dag   = 0.0f;                                // exact: unit-triangular power
    float total = powf(elbo*l_rec*l_pi*l_z*(dag + 1e-6f), 0.2f);
    out[OFF_LOSS+0] = total;
    out[OFF_LOSS+1] = elbo;
    out[OFF_LOSS+2] = l_rec;
    out[OFF_LOSS+3] = l_pi;
    out[OFF_LOSS+4] = l_z;
    out[OFF_LOSS+5] = dag;
  }
}

// ------------------------------ launcher -----------------------------------
extern "C" void kernel_launch(void* const* d_in, const int* in_sizes, int n_in,
                              void* d_out, int out_size){
  const float* x       = (const float*)d_in[0];
  const float* y_true  = (const float*)d_in[1];
  const float* ew      = (const float*)d_in[2];
  const float* hist    = (const float*)d_in[3];
  const float* enc_W1  = (const float*)d_in[4];
  const float* enc_b1  = (const float*)d_in[5];
  const float* enc_W2  = (const float*)d_in[6];
  const float* enc_b2  = (const float*)d_in[7];
  const float* gcn_W   = (const float*)d_in[8];
  const float* gcn_b   = (const float*)d_in[9];
  const float* mu_W    = (const float*)d_in[10];
  const float* mu_b    = (const float*)d_in[11];
  const float* sig_W   = (const float*)d_in[12];
  const float* sig_b   = (const float*)d_in[13];
  const float* gru_Wih = (const float*)d_in[14];
  const float* gru_Whh = (const float*)d_in[15];
  const float* gru_bih = (const float*)d_in[16];
  const float* gru_bhh = (const float*)d_in[17];
  const float* cm      = (const float*)d_in[18];
  const float* cm_W1   = (const float*)d_in[19];
  const float* cm_b1   = (const float*)d_in[20];
  const float* cm_W2   = (const float*)d_in[21];
  const float* cm_b2   = (const float*)d_in[22];
  const float* dec_W1  = (const float*)d_in[23];
  const float* dec_b1  = (const float*)d_in[24];
  const float* dec_W2  = (const float*)d_in[25];
  const float* dec_b2  = (const float*)d_in[26];
  const int*   esrc    = (const int*)d_in[27];
  const int*   edst    = (const int*)d_in[28];
  float* out = (float*)d_out;

  k_transpose<<<(2*2*TH3*HDIM + 255)/256, 256>>>(gru_Wih, gru_Whh);
  k_enc<<<dim3(BQ/16, NND), 128>>>(x, enc_W1, enc_b1, enc_W2, enc_b2);
  k_gcn<<<BQ/8, 128>>>(0, ew, esrc, edst, gcn_W, gcn_b);
  k_gcn<<<BQ/8, 128>>>(1, ew, esrc, edst, gcn_W, gcn_b);
  k_musig<<<BQ/8, 128>>>(mu_W, mu_b, sig_W, sig_b);
  k_gru<<<BQ/4, 128>>>(0, nullptr, hist, gru_bih, gru_bhh, out + OFF_HID);
  k_gru<<<BQ/4, 128>>>(1, out + OFF_HID, hist, gru_bih, gru_bhh, out + OFF_HID);
  k_causal<<<BQ, 128>>>(ew, cm, esrc, edst);
  k_cm1<<<(BQ*NND)/16, 128>>>(cm_W1, cm_b1);
  k_cm2<<<(BQ*NND)/16, 128>>>(cm_W2, cm_b2);
  k_dec1<<<dim3(BQ/16, NND), 128>>>(dec_W1, dec_b1);
  k_dec2<<<dim3(BQ/64, NND), 128>>>(dec_W2, dec_b2, y_true, out);
  k_final<<<1, 192>>>(out);
}

// round 2
// speedup vs baseline: 1.0593x; 1.0593x over previous
#include <cuda_runtime.h>
#include <math.h>

#define BQ   32768
#define NND  5
#define DDIM 32
#define HDIM 128
#define NE   10
#define TH3  384

#define OFF_V    (BQ*NND*DDIM)              /* 5242880  */
#define OFF_HID  (2*BQ*NND*DDIM)            /* 10485760 */
#define OFF_LOSS (OFF_HID + 2*BQ*HDIM)      /* 18874368 */

#define ZALPHA 1.959963984540054f

typedef unsigned long long ull;

// ----------------------------- device scratch -----------------------------
__device__ float g_bufA[BQ*NND*HDIM];
__device__ float g_bufB[BQ*NND*HDIM];
__device__ float g_mean[BQ*NND*HDIM];
__device__ float g_z  [BQ*NND*HDIM];
__device__ float g_ps [BQ*NND*HDIM];
__device__ float g_d1 [BQ*NND*HDIM];
__device__ float g_gf [BQ*HDIM];
__device__ float g_WihT[2*HDIM*TH3];
__device__ float g_WhhT[2*HDIM*TH3];
__device__ float g_klpart[8192];
__device__ float g_lzpart[10240];
__device__ float g_losspart[5120*132];

// ------------------------------- helpers ----------------------------------
__device__ __forceinline__ ull fma2(ull a, ull b, ull c){
  ull d;
  asm("fma.rn.f32x2 %0, %1, %2, %3;" : "=l"(d) : "l"(a), "l"(b), "l"(c));
  return d;
}
__device__ __forceinline__ ull dupf(float v){
  unsigned u = __float_as_uint(v);
  return ((ull)u << 32) | (ull)u;
}
__device__ __forceinline__ float f2lo(ull u){ return __uint_as_float((unsigned)u); }
__device__ __forceinline__ float f2hi(ull u){ return __uint_as_float((unsigned)(u>>32)); }

__device__ __forceinline__ float warp_sum(float v){
#pragma unroll
  for (int o=16;o>0;o>>=1) v += __shfl_xor_sync(0xffffffffu, v, o);
  return v;
}
__device__ __forceinline__ float softplusf(float x){
  return fmaxf(x,0.f) + log1pf(expf(-fabsf(x)));
}
__device__ __forceinline__ float mishf(float x){ return x*tanhf(softplusf(x)); }
__device__ __forceinline__ float sigmf(float x){ return 1.f/(1.f+expf(-x)); }

#define BLOCK_REDUCE_TO(part, val)                                      \
  do {                                                                  \
    float _v = warp_sum(val);                                           \
    __shared__ float _sred[4];                                          \
    if ((threadIdx.x & 31) == 0) _sred[threadIdx.x >> 5] = _v;          \
    __syncthreads();                                                    \
    if (threadIdx.x == 0)                                               \
      part[blockIdx.x] = (_sred[0]+_sred[1]) + (_sred[2]+_sred[3]);     \
  } while (0)

// --------------------------- 0: GRU weight transpose -----------------------
__global__ void k_transpose(const float* __restrict__ Wih,
                            const float* __restrict__ Whh){
  int idx = blockIdx.x*blockDim.x + threadIdx.x;
  if (idx >= 2*2*TH3*HDIM) return;
  int which = idx / (2*TH3*HDIM);
  int r = idx % (2*TH3*HDIM);
  int l = r / (TH3*HDIM);
  int jr = r % (TH3*HDIM);
  int j = jr / HDIM, k = jr % HDIM;
  const float* src = which ? Whh : Wih;
  float* dst = which ? g_WhhT : g_WihT;
  dst[l*HDIM*TH3 + k*TH3 + j] = src[r];
}

// ------------------------------ 1: encoder ---------------------------------
__global__ __launch_bounds__(128) void k_enc(
    const float* __restrict__ x, const float* __restrict__ W1,
    const float* __restrict__ b1, const float* __restrict__ W2,
    const float* __restrict__ b2){
  const int BT = 16;
  int n = blockIdx.y, b0 = blockIdx.x*BT, t = threadIdx.x;
  __shared__ __align__(16) ull s_x[BT*DDIM];
  __shared__ __align__(16) ull s_h[BT*HDIM];
  // stage x (dup)
  {
    int flat = t*4;               // 128 float4s total
    int r = flat / DDIM, d = flat % DDIM;
    float4 v = *(const float4*)&x[(b0+r)*NND*DDIM + n*DDIM + d];
    ull* p = &s_x[r*DDIM + d];
    p[0]=dupf(v.x); p[1]=dupf(v.y); p[2]=dupf(v.z); p[3]=dupf(v.w);
  }
  __syncthreads();
  int cp = t & 63, rg = t >> 6;
  const float* W1p = W1 + n*DDIM*HDIM;
  ull acc[8];
#pragma unroll
  for (int i=0;i<8;i++) acc[i]=0ull;
#pragma unroll 2
  for (int k=0;k<DDIM;k+=2){
    ull w0 = *(const ull*)&W1p[k*HDIM + 2*cp];
    ull w1 = *(const ull*)&W1p[(k+1)*HDIM + 2*cp];
#pragma unroll
    for (int i=0;i<8;i++){
      ulonglong2 a = *(const ulonglong2*)&s_x[(rg*8+i)*DDIM + k];
      acc[i] = fma2(w0, a.x, acc[i]);
      acc[i] = fma2(w1, a.y, acc[i]);
    }
  }
  float2 bb1 = *(const float2*)&b1[n*HDIM + 2*cp];
#pragma unroll
  for (int i=0;i<8;i++){
    int row = rg*8+i;
    float h0 = fmaxf(f2lo(acc[i]) + bb1.x, 0.f);
    float h1 = fmaxf(f2hi(acc[i]) + bb1.y, 0.f);
    s_h[row*HDIM + 2*cp]   = dupf(h0);
    s_h[row*HDIM + 2*cp+1] = dupf(h1);
  }
  __syncthreads();
  const float* W2p = W2 + n*HDIM*HDIM;
#pragma unroll
  for (int i=0;i<8;i++) acc[i]=0ull;
#pragma unroll 2
  for (int k=0;k<HDIM;k+=2){
    ull w0 = *(const ull*)&W2p[k*HDIM + 2*cp];
    ull w1 = *(const ull*)&W2p[(k+1)*HDIM + 2*cp];
#pragma unroll
    for (int i=0;i<8;i++){
      ulonglong2 a = *(const ulonglong2*)&s_h[(rg*8+i)*HDIM + k];
      acc[i] = fma2(w0, a.x, acc[i]);
      acc[i] = fma2(w1, a.y, acc[i]);
    }
  }
  float2 bb2 = *(const float2*)&b2[n*HDIM + 2*cp];
#pragma unroll
  for (int i=0;i<8;i++){
    int row = rg*8+i;
    float2 o; o.x = f2lo(acc[i]) + bb2.x; o.y = f2hi(acc[i]) + bb2.y;
    *(float2*)&g_bufA[(b0+row)*NND*HDIM + n*HDIM + 2*cp] = o;
  }
}

// ------------------------------- 2: GCN ------------------------------------
__global__ __launch_bounds__(128) void k_gcn(
    int l, const float* __restrict__ ew,
    const int* __restrict__ esrc, const int* __restrict__ edst,
    const float* __restrict__ W, const float* __restrict__ bias){
  const int BT = 4;
  int b0 = blockIdx.x*BT, t = threadIdx.x;
  const float* gin  = (l==0) ? g_bufA : g_bufB;
  float*       gout = (l==0) ? g_bufB : g_bufA;
  __shared__ __align__(16) ull s_g[NND*BT*HDIM];   // 20KB, dup
  __shared__ float s_ew[BT*NE];
  __shared__ int s_src[NE], s_dst[NE];
  // stage (dup): 20*128 floats = 640 float4
#pragma unroll
  for (int f=t; f<640; f+=128){
    int flat = f*4;
    int r = flat / (NND*HDIM), rem = flat % (NND*HDIM);
    int v = rem / HDIM, k = rem % HDIM;
    float4 val = *(const float4*)&gin[(b0+r)*NND*HDIM + rem];
    ull* p = &s_g[(v*BT+r)*HDIM + k];
    p[0]=dupf(val.x); p[1]=dupf(val.y); p[2]=dupf(val.z); p[3]=dupf(val.w);
  }
  if (t < BT*NE) s_ew[t] = ew[(b0 + t/NE)*NE + (t%NE)];
  if (t < NE){ s_src[t] = esrc[t]; s_dst[t] = edst[t]; }
  __syncthreads();
  // in-place agg on column k=t (thread-exclusive), reads original values from regs
  {
    float gv[NND*BT];
#pragma unroll
    for (int i=0;i<NND*BT;i++) gv[i] = f2lo(s_g[i*HDIM + t]);
#pragma unroll
    for (int v=NND-1; v>=1; v--){
#pragma unroll
      for (int r=0;r<BT;r++){
        float a = gv[v*BT+r];
#pragma unroll
        for (int e=0;e<NE;e++){
          if (s_dst[e] == v){
            int s = s_src[e];
            float zs = (s==0)?gv[r]:((s==1)?gv[BT+r]:((s==2)?gv[2*BT+r]:gv[3*BT+r]));
            a += s_ew[r*NE+e]*zs;
          }
        }
        s_g[(v*BT+r)*HDIM + t] = dupf(a);
      }
    }
  }
  __syncthreads();
  int cp = t & 63, rg = t >> 6;
  const float* Wp = W + l*HDIM*HDIM;
  const ull* sb = &s_g[rg*10*HDIM];
  ull acc[10];
#pragma unroll
  for (int i=0;i<10;i++) acc[i]=0ull;
#pragma unroll 2
  for (int k=0;k<HDIM;k+=2){
    ull w0 = *(const ull*)&Wp[k*HDIM + 2*cp];
    ull w1 = *(const ull*)&Wp[(k+1)*HDIM + 2*cp];
#pragma unroll
    for (int i=0;i<10;i++){
      ulonglong2 a = *(const ulonglong2*)&sb[i*HDIM + k];
      acc[i] = fma2(w0, a.x, acc[i]);
      acc[i] = fma2(w1, a.y, acc[i]);
    }
  }
  float2 bb = *(const float2*)&bias[l*HDIM + 2*cp];
#pragma unroll
  for (int i=0;i<10;i++){
    int row = rg*10 + i;
    int v = row >> 2, r = row & 3;
    float2 o;
    o.x = fmaxf(f2lo(acc[i]) + bb.x, 0.f);
    o.y = fmaxf(f2hi(acc[i]) + bb.y, 0.f);
    *(float2*)&gout[(b0+r)*NND*HDIM + v*HDIM + 2*cp] = o;
  }
}

// -------------------- 3: mu/sig heads + KL + graph_feat --------------------
__global__ __launch_bounds__(128) void k_musig(
    const float* __restrict__ muW, const float* __restrict__ mub,
    const float* __restrict__ sigW, const float* __restrict__ sigb){
  const int BT = 4;
  int b0 = blockIdx.x*BT, t = threadIdx.x;
  __shared__ __align__(16) ull s_g[NND*BT*HDIM];   // 20KB
  __shared__ float2 s_gf[2][BT][64];
#pragma unroll
  for (int f=t; f<640; f+=128){
    int flat = f*4;
    int r = flat / (NND*HDIM), rem = flat % (NND*HDIM);
    int v = rem / HDIM, k = rem % HDIM;
    float4 val = *(const float4*)&g_bufA[(b0+r)*NND*HDIM + rem];
    ull* p = &s_g[(v*BT+r)*HDIM + k];
    p[0]=dupf(val.x); p[1]=dupf(val.y); p[2]=dupf(val.z); p[3]=dupf(val.w);
  }
  __syncthreads();
  int cp = t & 63, rg = t >> 6;
  const ull* sb = &s_g[rg*10*HDIM];
  ull accm[10], accs[10];
#pragma unroll
  for (int i=0;i<10;i++){ accm[i]=0ull; accs[i]=0ull; }
  for (int k=0;k<HDIM;k+=2){
    ull wm0 = *(const ull*)&muW [k*HDIM + 2*cp];
    ull wm1 = *(const ull*)&muW [(k+1)*HDIM + 2*cp];
    ull ws0 = *(const ull*)&sigW[k*HDIM + 2*cp];
    ull ws1 = *(const ull*)&sigW[(k+1)*HDIM + 2*cp];
#pragma unroll
    for (int i=0;i<10;i++){
      ulonglong2 a = *(const ulonglong2*)&sb[i*HDIM + k];
      accm[i] = fma2(wm0, a.x, accm[i]);
      accm[i] = fma2(wm1, a.y, accm[i]);
      accs[i] = fma2(ws0, a.x, accs[i]);
      accs[i] = fma2(ws1, a.y, accs[i]);
    }
  }
  float2 mb = *(const float2*)&mub [2*cp];
  float2 sb2 = *(const float2*)&sigb[2*cp];
  float kll = 0.f;
  float2 gf4[BT];
#pragma unroll
  for (int r=0;r<BT;r++){ gf4[r].x = 0.f; gf4[r].y = 0.f; }
#pragma unroll
  for (int i=0;i<10;i++){
    int row = rg*10 + i;
    int v = row >> 2, r = row & 3;
    float m0 = f2lo(accm[i]) + mb.x, m1 = f2hi(accm[i]) + mb.y;
    float2 mo; mo.x = m0; mo.y = m1;
    *(float2*)&g_mean[(b0+r)*NND*HDIM + v*HDIM + 2*cp] = mo;
    float sp0 = softplusf(f2lo(accs[i]) + sb2.x);
    float sp1 = softplusf(f2hi(accs[i]) + sb2.y);
    float var0 = sp0*sp0, var1 = sp1*sp1;
    kll += m0*m0 + var0 - logf(var0 + 1e-8f) - 1.f;
    kll += m1*m1 + var1 - logf(var1 + 1e-8f) - 1.f;
    gf4[r].x += m0; gf4[r].y += m1;
  }
#pragma unroll
  for (int r=0;r<BT;r++) s_gf[rg][r][cp] = gf4[r];
  __syncthreads();
  if (rg == 0){
#pragma unroll
    for (int r=0;r<BT;r++){
      float2 a = s_gf[0][r][cp], b = s_gf[1][r][cp];
      float2 o; o.x = (a.x+b.x)*0.2f; o.y = (a.y+b.y)*0.2f;
      *(float2*)&g_gf[(b0+r)*HDIM + 2*cp] = o;
    }
  }
  BLOCK_REDUCE_TO(g_klpart, kll);
}

// -------------------------------- 4: GRU -----------------------------------
__global__ __launch_bounds__(128) void k_gru(
    int l, const float* __restrict__ xin_opt, const float* __restrict__ hist,
    const float* __restrict__ bih, const float* __restrict__ bhh,
    float* __restrict__ hout){
  const int BT = 8;
  int b0 = blockIdx.x*BT, t = threadIdx.x;
  const float* xin = xin_opt ? xin_opt : g_gf;
  __shared__ __align__(16) ull s_x[BT*HDIM], s_h[BT*HDIM];  // 8KB + 8KB
#pragma unroll
  for (int f=t; f<512; f+=128){
    int arr = f >> 8;                     // 0: x, 1: h
    int flat = (f & 255)*4;
    int r = flat / HDIM, k = flat % HDIM;
    float4 v;
    if (arr == 0) v = *(const float4*)&xin[(b0+r)*HDIM + k];
    else          v = *(const float4*)&hist[l*BQ*HDIM + (b0+r)*HDIM + k];
    ull* p = (arr==0) ? &s_x[r*HDIM+k] : &s_h[r*HDIM+k];
    p[0]=dupf(v.x); p[1]=dupf(v.y); p[2]=dupf(v.z); p[3]=dupf(v.w);
  }
  __syncthreads();
  int cp = t & 63, rg = t >> 6;
  const float* WiT = g_WihT + l*HDIM*TH3;
  const float* WhT = g_WhhT + l*HDIM*TH3;
  ull air[4], aiz[4], ain[4], ahr[4], ahz[4], ahn[4];
#pragma unroll
  for (int r=0;r<4;r++){ air[r]=aiz[r]=ain[r]=ahr[r]=ahz[r]=ahn[r]=0ull; }
#pragma unroll 2
  for (int k=0;k<HDIM;k++){
    ull wir = *(const ull*)&WiT[k*TH3 + 2*cp];
    ull wiz = *(const ull*)&WiT[k*TH3 + HDIM + 2*cp];
    ull win = *(const ull*)&WiT[k*TH3 + 2*HDIM + 2*cp];
    ull whr = *(const ull*)&WhT[k*TH3 + 2*cp];
    ull whz = *(const ull*)&WhT[k*TH3 + HDIM + 2*cp];
    ull whn = *(const ull*)&WhT[k*TH3 + 2*HDIM + 2*cp];
#pragma unroll
    for (int r=0;r<4;r++){
      int row = rg*4 + r;
      ull ax = s_x[row*HDIM + k];
      ull ah = s_h[row*HDIM + k];
      air[r] = fma2(wir, ax, air[r]);
      aiz[r] = fma2(wiz, ax, aiz[r]);
      ain[r] = fma2(win, ax, ain[r]);
      ahr[r] = fma2(whr, ah, ahr[r]);
      ahz[r] = fma2(whz, ah, ahz[r]);
      ahn[r] = fma2(whn, ah, ahn[r]);
    }
  }
  float2 bir = *(const float2*)&bih[l*TH3 + 2*cp];
  float2 biz = *(const float2*)&bih[l*TH3 + HDIM + 2*cp];
  float2 bin_= *(const float2*)&bih[l*TH3 + 2*HDIM + 2*cp];
  float2 bhr = *(const float2*)&bhh[l*TH3 + 2*cp];
  float2 bhz = *(const float2*)&bhh[l*TH3 + HDIM + 2*cp];
  float2 bhn = *(const float2*)&bhh[l*TH3 + 2*HDIM + 2*cp];
#pragma unroll
  for (int r=0;r<4;r++){
    int row = rg*4 + r;
    float hp0 = f2lo(s_h[row*HDIM + 2*cp]);
    float hp1 = f2lo(s_h[row*HDIM + 2*cp+1]);
    float r0 = sigmf(f2lo(air[r])+bir.x + f2lo(ahr[r])+bhr.x);
    float r1 = sigmf(f2hi(air[r])+bir.y + f2hi(ahr[r])+bhr.y);
    float z0 = sigmf(f2lo(aiz[r])+biz.x + f2lo(ahz[r])+bhz.x);
    float z1 = sigmf(f2hi(aiz[r])+biz.y + f2hi(ahz[r])+bhz.y);
    float n0 = tanhf(f2lo(ain[r])+bin_.x + r0*(f2lo(ahn[r])+bhn.x));
    float n1 = tanhf(f2hi(ain[r])+bin_.y + r1*(f2hi(ahn[r])+bhn.y));
    float2 o;
    o.x = (1.f-z0)*n0 + z0*hp0;
    o.y = (1.f-z1)*n1 + z1*hp1;
    *(float2*)&hout[l*BQ*HDIM + (b0+row)*HDIM + 2*cp] = o;
  }
}

// --------------- 5: causal solve (fwd subst) + parent_sum ------------------
__global__ __launch_bounds__(128) void k_causal(
    const float* __restrict__ ew, const float* __restrict__ cm,
    const int* __restrict__ esrc, const int* __restrict__ edst){
  int b = blockIdx.x, t = threadIdx.x;
  __shared__ float s_ew[NE], s_cm[NND*NND];
  __shared__ int s_src[NE], s_dst[NE];
  if (t < NE){ s_ew[t] = ew[b*NE + t]; s_src[t] = esrc[t]; s_dst[t] = edst[t]; }
  if (t < NND*NND) s_cm[t] = cm[t];
  __syncthreads();
  int base = b*NND*HDIM + t;
  float z[NND];
#pragma unroll
  for (int j=0;j<NND;j++) z[j] = g_mean[base + j*HDIM];
#pragma unroll
  for (int j=1;j<NND;j++){
    float add = 0.f;
#pragma unroll
    for (int e=0;e<NE;e++){
      if (s_dst[e] == j){
        int s = s_src[e];
        float zs = (s==0)?z[0]:((s==1)?z[1]:((s==2)?z[2]:z[3]));
        add += s_ew[e]*s_cm[s*NND + j]*zs;
      }
    }
    z[j] += add;
  }
#pragma unroll
  for (int j=0;j<NND;j++) g_z[base + j*HDIM] = z[j];
#pragma unroll
  for (int j=0;j<NND;j++){
    float ps = 0.f;
#pragma unroll
    for (int i=0;i<NND;i++)
      if (s_cm[i*NND + j] != 0.f) ps += z[i];
    g_ps[base + j*HDIM] = ps;
  }
}

// --------------- 6: cm MLP (fused: ps -> mish -> lin) + l_z ----------------
__global__ __launch_bounds__(128) void k_cm(
    const float* __restrict__ W1, const float* __restrict__ b1,
    const float* __restrict__ W2, const float* __restrict__ b2){
  const int BT = 16;
  int r0 = blockIdx.x*BT, t = threadIdx.x;
  __shared__ __align__(16) ull s_a[BT*HDIM];   // 16KB
  __shared__ __align__(16) ull s_b[BT*HDIM];   // 16KB
#pragma unroll
  for (int f=t; f<512; f+=128){
    int flat = f*4;
    float4 v = *(const float4*)&g_ps[r0*HDIM + flat];
    ull* p = &s_a[flat];
    p[0]=dupf(v.x); p[1]=dupf(v.y); p[2]=dupf(v.z); p[3]=dupf(v.w);
  }
  __syncthreads();
  int cp = t & 63, rg = t >> 6;
  ull acc[8];
#pragma unroll
  for (int i=0;i<8;i++) acc[i]=0ull;
#pragma unroll 2
  for (int k=0;k<HDIM;k+=2){
    ull w0 = *(const ull*)&W1[k*HDIM + 2*cp];
    ull w1 = *(const ull*)&W1[(k+1)*HDIM + 2*cp];
#pragma unroll
    for (int i=0;i<8;i++){
      ulonglong2 a = *(const ulonglong2*)&s_a[(rg*8+i)*HDIM + k];
      acc[i] = fma2(w0, a.x, acc[i]);
      acc[i] = fma2(w1, a.y, acc[i]);
    }
  }
  float2 bb1 = *(const float2*)&b1[2*cp];
#pragma unroll
  for (int i=0;i<8;i++){
    int row = rg*8+i;
    s_b[row*HDIM + 2*cp]   = dupf(mishf(f2lo(acc[i]) + bb1.x));
    s_b[row*HDIM + 2*cp+1] = dupf(mishf(f2hi(acc[i]) + bb1.y));
  }
  __syncthreads();
#pragma unroll
  for (int i=0;i<8;i++) acc[i]=0ull;
#pragma unroll 2
  for (int k=0;k<HDIM;k+=2){
    ull w0 = *(const ull*)&W2[k*HDIM + 2*cp];
    ull w1 = *(const ull*)&W2[(k+1)*HDIM + 2*cp];
#pragma unroll
    for (int i=0;i<8;i++){
      ulonglong2 a = *(const ulonglong2*)&s_b[(rg*8+i)*HDIM + k];
      acc[i] = fma2(w0, a.x, acc[i]);
      acc[i] = fma2(w1, a.y, acc[i]);
    }
  }
  float2 bb2 = *(const float2*)&b2[2*cp];
  float lz = 0.f;
#pragma unroll
  for (int i=0;i<8;i++){
    int row = rg*8+i;
    float2 z2 = *(const float2*)&g_z[(r0+row)*HDIM + 2*cp];
    float d0 = z2.x - (f2lo(acc[i]) + bb2.x);
    float d1 = z2.y - (f2hi(acc[i]) + bb2.y);
    lz += d0*d0 + d1*d1;
  }
  BLOCK_REDUCE_TO(g_lzpart, lz);
}

// --------------- 8: decoder layer 1 (z -> mish d1) -------------------------
__global__ __launch_bounds__(128) void k_dec1(
    const float* __restrict__ W, const float* __restrict__ bias){
  const int BT = 16;
  int n = blockIdx.y, b0 = blockIdx.x*BT, t = threadIdx.x;
  __shared__ __align__(16) ull s_in[BT*HDIM];  // 16KB
#pragma unroll
  for (int f=t; f<512; f+=128){
    int flat = f*4;
    int r = flat / HDIM, k = flat % HDIM;
    float4 v = *(const float4*)&g_z[(b0+r)*NND*HDIM + n*HDIM + k];
    ull* p = &s_in[r*HDIM + k];
    p[0]=dupf(v.x); p[1]=dupf(v.y); p[2]=dupf(v.z); p[3]=dupf(v.w);
  }
  __syncthreads();
  int cp = t & 63, rg = t >> 6;
  const float* Wp = W + n*HDIM*HDIM;
  ull acc[8];
#pragma unroll
  for (int i=0;i<8;i++) acc[i]=0ull;
#pragma unroll 2
  for (int k=0;k<HDIM;k+=2){
    ull w0 = *(const ull*)&Wp[k*HDIM + 2*cp];
    ull w1 = *(const ull*)&Wp[(k+1)*HDIM + 2*cp];
#pragma unroll
    for (int i=0;i<8;i++){
      ulonglong2 a = *(const ulonglong2*)&s_in[(rg*8+i)*HDIM + k];
      acc[i] = fma2(w0, a.x, acc[i]);
      acc[i] = fma2(w1, a.y, acc[i]);
    }
  }
  float2 bb = *(const float2*)&bias[n*HDIM + 2*cp];
#pragma unroll
  for (int i=0;i<8;i++){
    int row = rg*8+i;
    float2 o;
    o.x = mishf(f2lo(acc[i]) + bb.x);
    o.y = mishf(f2hi(acc[i]) + bb.y);
    *(float2*)&g_d1[(b0+row)*NND*HDIM + n*HDIM + 2*cp] = o;
  }
}

// --------------- 9: decoder layer 2 + per-element losses -------------------
__global__ __launch_bounds__(128) void k_dec2(
    const float* __restrict__ W2, const float* __restrict__ b2,
    const float* __restrict__ yt_g, float* __restrict__ out){
  const int BT = 32;
  int n = blockIdx.y, b0 = blockIdx.x*BT;
  int t = threadIdx.x;
  int cp = t & 15, rg = t >> 4;   // 16 d-pairs x 8 row-groups of 4
  __shared__ __align__(16) ull s_d[BT*HDIM];   // 32KB
#pragma unroll
  for (int f=t; f<1024; f+=128){
    int flat = f*4;
    int r = flat / HDIM, k = flat % HDIM;
    float4 v = *(const float4*)&g_d1[(b0+r)*NND*HDIM + n*HDIM + k];
    ull* p = &s_d[r*HDIM + k];
    p[0]=dupf(v.x); p[1]=dupf(v.y); p[2]=dupf(v.z); p[3]=dupf(v.w);
  }
  __syncthreads();
  const float* Wp = W2 + n*HDIM*2*DDIM;
  ull accm[4], accv[4];
#pragma unroll
  for (int r=0;r<4;r++){ accm[r]=0ull; accv[r]=0ull; }
#pragma unroll 2
  for (int k=0;k<HDIM;k+=2){
    ull wm0 = *(const ull*)&Wp[k*2*DDIM + 2*cp];
    ull wm1 = *(const ull*)&Wp[(k+1)*2*DDIM + 2*cp];
    ull wv0 = *(const ull*)&Wp[k*2*DDIM + DDIM + 2*cp];
    ull wv1 = *(const ull*)&Wp[(k+1)*2*DDIM + DDIM + 2*cp];
#pragma unroll
    for (int r=0;r<4;r++){
      ulonglong2 a = *(const ulonglong2*)&s_d[(rg*4+r)*HDIM + k];
      accm[r] = fma2(wm0, a.x, accm[r]);
      accm[r] = fma2(wm1, a.y, accm[r]);
      accv[r] = fma2(wv0, a.x, accv[r]);
      accv[r] = fma2(wv1, a.y, accv[r]);
    }
  }
  float2 bm = *(const float2*)&b2[n*2*DDIM + 2*cp];
  float2 bv = *(const float2*)&b2[n*2*DDIM + DDIM + 2*cp];
  float ll=0.f, sq4=0.f, bce=0.f;
  float2 piw2, kd2, mn2, mx2;
  piw2.x=piw2.y=0.f; kd2.x=kd2.y=0.f;
  mn2.x=mn2.y=1e30f; mx2.x=mx2.y=-1e30f;
#pragma unroll
  for (int r=0;r<4;r++){
    int row = rg*4 + r;
    int b = b0 + row;
    int oidx = b*NND*DDIM + n*DDIM + 2*cp;
    float ym0 = f2lo(accm[r]) + bm.x, ym1 = f2hi(accm[r]) + bm.y;
    float yv0 = expf(f2lo(accv[r]) + bv.x), yv1 = expf(f2hi(accv[r]) + bv.y);
    float2 om; om.x=ym0; om.y=ym1;
    float2 ov; ov.x=yv0; ov.y=yv1;
    *(float2*)&out[oidx] = om;
    *(float2*)&out[OFF_V + oidx] = ov;
    float2 yt2 = *(const float2*)&yt_g[oidx];
    // lane 0
    {
      float vs = yv0 + 1e-6f, df = yt2.x - ym0;
      ll += -0.5f*(df*df/vs + logf(6.2831853071795864f*vs));
      if (n < 4) sq4 += df*df;
      if (n == 4) bce += fmaxf(ym0,0.f) - ym0*yt2.x + log1pf(expf(-fabsf(ym0)));
      float s = sqrtf(vs);
      float lo_ = ym0 - ZALPHA*s, up_ = ym0 + ZALPHA*s;
      float kf = (yt2.x >= lo_ && yt2.x <= up_) ? 1.f : 0.f;
      kd2.x += kf; piw2.x += (up_-lo_)*kf;
      mn2.x = fminf(mn2.x, yt2.x); mx2.x = fmaxf(mx2.x, yt2.x);
    }
    // lane 1
    {
      float vs = yv1 + 1e-6f, df = yt2.y - ym1;
      ll += -0.5f*(df*df/vs + logf(6.2831853071795864f*vs));
      if (n < 4) sq4 += df*df;
      if (n == 4) bce += fmaxf(ym1,0.f) - ym1*yt2.y + log1pf(expf(-fabsf(ym1)));
      float s = sqrtf(vs);
      float lo_ = ym1 - ZALPHA*s, up_ = ym1 + ZALPHA*s;
      float kf = (yt2.y >= lo_ && yt2.y <= up_) ? 1.f : 0.f;
      kd2.y += kf; piw2.y += (up_-lo_)*kf;
      mn2.y = fminf(mn2.y, yt2.y); mx2.y = fmaxf(mx2.y, yt2.y);
    }
  }
  // scalar reductions (warp + cross-warp, fixed order)
  ll  = warp_sum(ll);
  sq4 = warp_sum(sq4);
  bce = warp_sum(bce);
  __shared__ float s_sc[3][4];
  __shared__ float2 s_piw[8][16], s_kd[8][16], s_mn[8][16], s_mx[8][16];
  int w = t >> 5;
  if ((t & 31) == 0){ s_sc[0][w]=ll; s_sc[1][w]=sq4; s_sc[2][w]=bce; }
  s_piw[rg][cp]=piw2; s_kd[rg][cp]=kd2; s_mn[rg][cp]=mn2; s_mx[rg][cp]=mx2;
  __syncthreads();
  int blk = blockIdx.y*gridDim.x + blockIdx.x;
  float* P = g_losspart + blk*132;
  if (t == 0){
    P[0] = (s_sc[0][0]+s_sc[0][1]) + (s_sc[0][2]+s_sc[0][3]);
    P[1] = (s_sc[1][0]+s_sc[1][1]) + (s_sc[1][2]+s_sc[1][3]);
    P[2] = (s_sc[2][0]+s_sc[2][1]) + (s_sc[2][2]+s_sc[2][3]);
    P[3] = 0.f;
  }
  if (t < 16){
    float p0=0.f,p1=0.f,k0=0.f,k1=0.f;
    float m0=1e30f,m1=1e30f,x0=-1e30f,x1=-1e30f;
#pragma unroll
    for (int g=0; g<8; g++){
      p0 += s_piw[g][t].x; p1 += s_piw[g][t].y;
      k0 += s_kd[g][t].x;  k1 += s_kd[g][t].y;
      m0 = fminf(m0, s_mn[g][t].x); m1 = fminf(m1, s_mn[g][t].y);
      x0 = fmaxf(x0, s_mx[g][t].x); x1 = fmaxf(x1, s_mx[g][t].y);
    }
    P[4  + 2*t] = p0;  P[4  + 2*t+1] = p1;
    P[36 + 2*t] = k0;  P[36 + 2*t+1] = k1;
    P[68 + 2*t] = m0;  P[68 + 2*t+1] = m1;
    P[100+ 2*t] = x0;  P[100+ 2*t+1] = x1;
  }
}

// --------------- 10: final deterministic reduce + losses -------------------
__global__ void k_final(float* __restrict__ out){
  int t = threadIdx.x;
  __shared__ float s_acc[136];
  if (t < 132){
    bool ismin = (t >= 68 && t < 100), ismax = (t >= 100);
    float s0,s1,s2,s3;
    if (ismin){ s0=s1=s2=s3=1e30f; }
    else if (ismax){ s0=s1=s2=s3=-1e30f; }
    else { s0=s1=s2=s3=0.f; }
    for (int i=0; i<5120; i+=4){
      float a = g_losspart[(i+0)*132 + t];
      float b = g_losspart[(i+1)*132 + t];
      float c = g_losspart[(i+2)*132 + t];
      float e = g_losspart[(i+3)*132 + t];
      if (ismin){ s0=fminf(s0,a); s1=fminf(s1,b); s2=fminf(s2,c); s3=fminf(s3,e); }
      else if (ismax){ s0=fmaxf(s0,a); s1=fmaxf(s1,b); s2=fmaxf(s2,c); s3=fmaxf(s3,e); }
      else { s0+=a; s1+=b; s2+=c; s3+=e; }
    }
    s_acc[t] = ismin ? fminf(fminf(s0,s1),fminf(s2,s3))
             : ismax ? fmaxf(fmaxf(s0,s1),fmaxf(s2,s3))
             : (s0+s1)+(s2+s3);
  } else if (t == 132){
    float s0=0,s1=0,s2=0,s3=0;
    for (int i=0;i<8192;i+=4){
      s0+=g_klpart[i]; s1+=g_klpart[i+1]; s2+=g_klpart[i+2]; s3+=g_klpart[i+3];
    }
    s_acc[132] = (s0+s1)+(s2+s3);
  } else if (t == 133){
    float s0=0,s1=0,s2=0,s3=0;
    for (int i=0;i<10240;i+=4){
      s0+=g_lzpart[i]; s1+=g_lzpart[i+1]; s2+=g_lzpart[i+2]; s3+=g_lzpart[i+3];
    }
    s_acc[133] = (s0+s1)+(s2+s3);
  }
  __syncthreads();
  if (t == 0){
    float S_ll = s_acc[0], S_sq4 = s_acc[1], S_bce = s_acc[2];
    float kl = 0.5f*s_acc[132];
    float S_lz = s_acc[133];
    float mean_ll = S_ll / 5242880.0f;                 // B*N*D
    float elbo = kl/32768.0f - mean_ll;
    float l_reg = (S_sq4/32.0f) / (4.0f*32768.0f + 1e-6f);
    float l_cls = (S_bce/32.0f) / (32768.0f + 1e-6f);
    float l_rec = l_reg + l_cls;
    float Sk = 0.f, pin = 0.f;
    for (int d=0; d<32; d++){
      float kdv = s_acc[36+d];
      Sk += kdv;
      pin += s_acc[4+d] / (kdv + 1e-6f) / (s_acc[100+d] - s_acc[68+d] + 1e-6f);
    }
    float picp  = Sk / 5242880.0f;
    float pinaw = pin / 32.0f;
    float l_pi  = pinaw - sqrtf(5.0f)*picp;
    float l_z   = S_lz / 20971520.0f;                  // B*N*CD
    float dag   = 0.0f;                                // exact: unit-triangular power
    float total = powf(elbo*l_rec*l_pi*l_z*(dag + 1e-6f), 0.2f);
    out[OFF_LOSS+0] = total;
    out[OFF_LOSS+1] = elbo;
    out[OFF_LOSS+2] = l_rec;
    out[OFF_LOSS+3] = l_pi;
    out[OFF_LOSS+4] = l_z;
    out[OFF_LOSS+5] = dag;
  }
}

// ------------------------------ launcher -----------------------------------
extern "C" void kernel_launch(void* const* d_in, const int* in_sizes, int n_in,
                              void* d_out, int out_size){
  const float* x       = (const float*)d_in[0];
  const float* y_true  = (const float*)d_in[1];
  const float* ew      = (const float*)d_in[2];
  const float* hist    = (const float*)d_in[3];
  const float* enc_W1  = (const float*)d_in[4];
  const float* enc_b1  = (const float*)d_in[5];
  const float* enc_W2  = (const float*)d_in[6];
  const float* enc_b2  = (const float*)d_in[7];
  const float* gcn_W   = (const float*)d_in[8];
  const float* gcn_b   = (const float*)d_in[9];
  const float* mu_W    = (const float*)d_in[10];
  const float* mu_b    = (const float*)d_in[11];
  const float* sig_W   = (const float*)d_in[12];
  const float* sig_b   = (const float*)d_in[13];
  const float* gru_Wih = (const float*)d_in[14];
  const float* gru_Whh = (const float*)d_in[15];
  const float* gru_bih = (const float*)d_in[16];
  const float* gru_bhh = (const float*)d_in[17];
  const float* cm      = (const float*)d_in[18];
  const float* cm_W1   = (const float*)d_in[19];
  const float* cm_b1   = (const float*)d_in[20];
  const float* cm_W2   = (const float*)d_in[21];
  const float* cm_b2   = (const float*)d_in[22];
  const float* dec_W1  = (const float*)d_in[23];
  const float* dec_b1  = (const float*)d_in[24];
  const float* dec_W2  = (const float*)d_in[25];
  const float* dec_b2  = (const float*)d_in[26];
  const int*   esrc    = (const int*)d_in[27];
  const int*   edst    = (const int*)d_in[28];
  float* out = (float*)d_out;

  k_transpose<<<(2*2*TH3*HDIM + 255)/256, 256>>>(gru_Wih, gru_Whh);
  k_enc<<<dim3(BQ/16, NND), 128>>>(x, enc_W1, enc_b1, enc_W2, enc_b2);
  k_gcn<<<BQ/4, 128>>>(0, ew, esrc, edst, gcn_W, gcn_b);
  k_gcn<<<BQ/4, 128>>>(1, ew, esrc, edst, gcn_W, gcn_b);
  k_musig<<<BQ/4, 128>>>(mu_W, mu_b, sig_W, sig_b);
  k_gru<<<BQ/8, 128>>>(0, nullptr, hist, gru_bih, gru_bhh, out + OFF_HID);
  k_gru<<<BQ/8, 128>>>(1, out + OFF_HID, hist, gru_bih, gru_bhh, out + OFF_HID);
  k_causal<<<BQ, 128>>>(ew, cm, esrc, edst);
  k_cm<<<(BQ*NND)/16, 128>>>(cm_W1, cm_b1, cm_W2, cm_b2);
  k_dec1<<<dim3(BQ/16, NND), 128>>>(dec_W1, dec_b1);
  k_dec2<<<dim3(BQ/32, NND), 128>>>(dec_W2, dec_b2, y_true, out);
  k_final<<<1, 192>>>(out);
}

// round 3
// speedup vs baseline: 1.6343x; 1.5428x over previous
#include <cuda_runtime.h>
#include <math.h>

#define BQ   32768
#define NND  5
#define DDIM 32
#define HDIM 128
#define NE   10

#define OFF_V    (BQ*NND*DDIM)              /* 5242880  */
#define OFF_HID  (2*BQ*NND*DDIM)            /* 10485760 */
#define OFF_LOSS (OFF_HID + 2*BQ*HDIM)      /* 18874368 */

#define ZALPHA 1.959963984540054f

typedef unsigned long long ull;

// ----------------------------- device scratch -----------------------------
__device__ float g_bufA[BQ*NND*HDIM];
__device__ float g_bufB[BQ*NND*HDIM];
__device__ float g_mean[BQ*NND*HDIM];
__device__ float g_z  [BQ*NND*HDIM];
__device__ float g_ps [BQ*NND*HDIM];
__device__ float g_d1 [BQ*NND*HDIM];
__device__ float g_gf [BQ*HDIM];
__device__ float g_gi [BQ*3*HDIM];
__device__ float g_gh [BQ*3*HDIM];
// parity-packed weights: Wp[kk][2c+p] = W[2kk+p][c]
__device__ float g_Wp_enc1[5*16*256];
__device__ float g_Wp_enc2[5*64*256];
__device__ float g_Wp_gcn [2*64*256];
__device__ float g_Wp_mu  [64*256];
__device__ float g_Wp_sig [64*256];
__device__ float g_Wp_cm1 [64*256];
__device__ float g_Wp_cm2 [64*256];
__device__ float g_Wp_dec1[5*64*256];
__device__ float g_Wp_dec2[5*64*128];
__device__ float g_Wp_gi  [2*64*768];
__device__ float g_Wp_gh  [2*64*768];
__device__ float g_klpart[8192];
__device__ float g_lzpart[5120];
__device__ float g_losspart[5120*132];
__device__ float g_facc[134];

// ------------------------------- helpers ----------------------------------
__device__ __forceinline__ ull fma2(ull a, ull b, ull c){
  ull d;
  asm("fma.rn.f32x2 %0, %1, %2, %3;" : "=l"(d) : "l"(a), "l"(b), "l"(c));
  return d;
}
__device__ __forceinline__ float f2lo(ull u){ return __uint_as_float((unsigned)u); }
__device__ __forceinline__ float f2hi(ull u){ return __uint_as_float((unsigned)(u>>32)); }
__device__ __forceinline__ float accv(ull u){ return f2lo(u) + f2hi(u); }

__device__ __forceinline__ float warp_sum(float v){
#pragma unroll
  for (int o=16;o>0;o>>=1) v += __shfl_xor_sync(0xffffffffu, v, o);
  return v;
}
__device__ __forceinline__ float softplusf(float x){
  return fmaxf(x,0.f) + log1pf(expf(-fabsf(x)));
}
__device__ __forceinline__ float mishf(float x){ return x*tanhf(softplusf(x)); }
__device__ __forceinline__ float sigmf(float x){ return 1.f/(1.f+expf(-x)); }

#define BLOCK_REDUCE_TO(part, val)                                      \
  do {                                                                  \
    float _v = warp_sum(val);                                           \
    __shared__ float _sred[4];                                          \
    if ((threadIdx.x & 31) == 0) _sred[threadIdx.x >> 5] = _v;          \
    __syncthreads();                                                    \
    if (threadIdx.x == 0)                                               \
      part[blockIdx.x] = (_sred[0]+_sred[1]) + (_sred[2]+_sred[3]);     \
  } while (0)

// parity split-K GEMM core: acc[i][j] = (even-k partial, odd-k partial)
template<int R, int C, int K, int CS, int LDA>
__device__ __forceinline__ void gcore(const float* __restrict__ sA,
                                      const float* __restrict__ Wp,
                                      int ldw, int cb, ull (&acc)[R][C]){
#pragma unroll
  for (int i=0;i<R;i++)
#pragma unroll
    for (int j=0;j<C;j++) acc[i][j] = 0ull;
#pragma unroll 2
  for (int kk=0; kk<K/2; kk+=2){
    ull w0[C], w1[C];
#pragma unroll
    for (int j=0;j<C;j++){
      w0[j] = *(const ull*)&Wp[kk*ldw + cb + CS*j];
      w1[j] = *(const ull*)&Wp[(kk+1)*ldw + cb + CS*j];
    }
#pragma unroll
    for (int i=0;i<R;i++){
      ulonglong2 a = *(const ulonglong2*)&sA[i*LDA + 2*kk];
#pragma unroll
      for (int j=0;j<C;j++){
        acc[i][j] = fma2(w0[j], a.x, acc[i][j]);
        acc[i][j] = fma2(w1[j], a.y, acc[i][j]);
      }
    }
  }
}

__device__ __forceinline__ void stage(float* s, const float* g, int n4, int t){
  for (int f=t; f<n4; f+=128)
    ((float4*)s)[f] = ((const float4*)g)[f];
}

// --------------------------- pack kernels ----------------------------------
// src[m][k][n] -> dst[m][kk][2n+p] = src[m][2kk+p][n]
__global__ void k_pack_kn(const float* __restrict__ src, float* __restrict__ dst,
                          int K, int Nc, int total){
  int idx = blockIdx.x*256 + threadIdx.x;
  if (idx >= total) return;
  int per = K*Nc;
  int m = idx / per, rem = idx % per;
  int ldw = 2*Nc;
  int kk = rem / ldw, q = rem % ldw;
  int n = q >> 1, p = q & 1;
  dst[idx] = src[m*per + (2*kk+p)*Nc + n];
}
// src[m][n][k] -> dst[m][kk][2n+p] = src[m][n][2kk+p]   (transposing pack)
__global__ void k_pack_nk(const float* __restrict__ src, float* __restrict__ dst,
                          int K, int Nc, int total){
  int idx = blockIdx.x*256 + threadIdx.x;
  if (idx >= total) return;
  int per = K*Nc;
  int m = idx / per, rem = idx % per;
  int ldw = 2*Nc;
  int kk = rem / ldw, q = rem % ldw;
  int n = q >> 1, p = q & 1;
  dst[idx] = src[m*per + n*K + (2*kk+p)];
}

// ------------------------------ 1: encoder ---------------------------------
__global__ __launch_bounds__(128,4) void k_enc(
    const float* __restrict__ x, const float* __restrict__ b1,
    const float* __restrict__ b2){
  int n = blockIdx.y, b0 = blockIdx.x*32, t = threadIdx.x;
  __shared__ float s_x[32*32];
  __shared__ float s_h[32*128];
  for (int f=t; f<256; f+=128){
    int r = f>>3, c = (f&7)<<2;
    *(float4*)&s_x[r*32+c] = *(const float4*)&x[(b0+r)*160 + n*32 + c];
  }
  __syncthreads();
  int cp = t&31, rg = t>>5;
  ull acc[8][4];
  gcore<8,4,32,64,32>(&s_x[rg*8*32], &g_Wp_enc1[n*16*256], 256, 2*cp, acc);
  {
    float bb[4];
#pragma unroll
    for (int j=0;j<4;j++) bb[j] = b1[n*128 + cp + 32*j];
#pragma unroll
    for (int i=0;i<8;i++)
#pragma unroll
      for (int j=0;j<4;j++)
        s_h[(rg*8+i)*128 + cp + 32*j] = fmaxf(accv(acc[i][j]) + bb[j], 0.f);
  }
  __syncthreads();
  gcore<8,4,128,64,128>(&s_h[rg*8*128], &g_Wp_enc2[n*64*256], 256, 2*cp, acc);
  {
    float bb[4];
#pragma unroll
    for (int j=0;j<4;j++) bb[j] = b2[n*128 + cp + 32*j];
#pragma unroll
    for (int i=0;i<8;i++)
#pragma unroll
      for (int j=0;j<4;j++)
        g_bufA[(b0+rg*8+i)*640 + n*128 + cp + 32*j] = accv(acc[i][j]) + bb[j];
  }
}

// ------------------------------- 2: GCN ------------------------------------
__global__ __launch_bounds__(128,4) void k_gcn(
    int l, const float* __restrict__ ew,
    const int* __restrict__ esrc, const int* __restrict__ edst,
    const float* __restrict__ bias){
  int b0 = blockIdx.x*4, t = threadIdx.x;      // 4 batches = 20 rows
  const float* gin  = (l==0) ? g_bufA : g_bufB;
  float*       gout = (l==0) ? g_bufB : g_bufA;
  const float* Wp = &g_Wp_gcn[l*64*256];
  __shared__ float s_g[20*128];
  __shared__ float s_ew[4*NE];
  __shared__ int s_src[NE], s_dst[NE];
  stage(s_g, gin + b0*640, 640, t);
  if (t < 4*NE) s_ew[t] = ew[(b0 + t/NE)*NE + (t%NE)];
  if (t < NE){ s_src[t] = esrc[t]; s_dst[t] = edst[t]; }
  __syncthreads();
  // agg per column t
  {
#pragma unroll
    for (int b=0;b<4;b++){
      float g0 = s_g[(b*5+0)*128 + t];
      float g1 = s_g[(b*5+1)*128 + t];
      float g2 = s_g[(b*5+2)*128 + t];
      float g3 = s_g[(b*5+3)*128 + t];
      float g4 = s_g[(b*5+4)*128 + t];
#pragma unroll
      for (int v=1; v<5; v++){
        float a = (v==1)?g1:((v==2)?g2:((v==3)?g3:g4));
#pragma unroll
        for (int e=0;e<NE;e++){
          if (s_dst[e] == v){
            int s = s_src[e];
            float gs = (s==0)?g0:((s==1)?g1:((s==2)?g2:g3));
            a += s_ew[b*NE+e]*gs;
          }
        }
        s_g[(b*5+v)*128 + t] = a;
      }
    }
  }
  __syncthreads();
  int cp = t&31, rg = t>>5;
  ull acc[5][4];
  gcore<5,4,128,64,128>(&s_g[rg*5*128], Wp, 256, 2*cp, acc);
  float bb[4];
#pragma unroll
  for (int j=0;j<4;j++) bb[j] = bias[l*128 + cp + 32*j];
#pragma unroll
  for (int i=0;i<5;i++)
#pragma unroll
    for (int j=0;j<4;j++)
      gout[b0*640 + (rg*5+i)*128 + cp + 32*j] = fmaxf(accv(acc[i][j]) + bb[j], 0.f);
}

// -------------------- 3: mu/sig heads + KL + graph_feat --------------------
__global__ __launch_bounds__(128,4) void k_musig(
    const float* __restrict__ mub, const float* __restrict__ sigb){
  int b0 = blockIdx.x*4, t = threadIdx.x;
  __shared__ float s_g[20*128];
  stage(s_g, g_bufA + b0*640, 640, t);
  __syncthreads();
  int cp = t&31, rg = t>>5;
  ull acc[5][4];
  gcore<5,4,128,64,128>(&s_g[rg*5*128], g_Wp_mu, 256, 2*cp, acc);
  float m[5][4];
  {
    float bb[4];
#pragma unroll
    for (int j=0;j<4;j++) bb[j] = mub[cp + 32*j];
#pragma unroll
    for (int i=0;i<5;i++)
#pragma unroll
      for (int j=0;j<4;j++){
        m[i][j] = accv(acc[i][j]) + bb[j];
        g_mean[(b0+rg)*640 + i*128 + cp + 32*j] = m[i][j];
      }
#pragma unroll
    for (int j=0;j<4;j++){
      float gf = (m[0][j]+m[1][j]+m[2][j]+m[3][j]+m[4][j])*0.2f;
      g_gf[(b0+rg)*128 + cp + 32*j] = gf;
    }
  }
  gcore<5,4,128,64,128>(&s_g[rg*5*128], g_Wp_sig, 256, 2*cp, acc);
  float kll = 0.f;
  {
    float bb[4];
#pragma unroll
    for (int j=0;j<4;j++) bb[j] = sigb[cp + 32*j];
#pragma unroll
    for (int i=0;i<5;i++)
#pragma unroll
      for (int j=0;j<4;j++){
        float sp = softplusf(accv(acc[i][j]) + bb[j]);
        float var = sp*sp;
        kll += m[i][j]*m[i][j] + var - logf(var + 1e-8f) - 1.f;
      }
  }
  BLOCK_REDUCE_TO(g_klpart, kll);
}

// ---------------------- 4: GRU GEMM (N=384 tiles) --------------------------
__global__ __launch_bounds__(128,4) void k_grug(
    const float* __restrict__ A, const float* __restrict__ Wp,
    float* __restrict__ outb){
  int b0 = blockIdx.x*32, tile = blockIdx.y, t = threadIdx.x;
  __shared__ float s_a[32*128];
  stage(s_a, A + b0*128, 1024, t);
  __syncthreads();
  int cp = t&31, rg = t>>5;
  ull acc[8][4];
  gcore<8,4,128,64,128>(&s_a[rg*8*128], Wp, 768, tile*256 + 2*cp, acc);
#pragma unroll
  for (int i=0;i<8;i++)
#pragma unroll
    for (int j=0;j<4;j++)
      outb[(b0+rg*8+i)*384 + tile*128 + cp + 32*j] = accv(acc[i][j]);
}

// ---------------------- 4b: GRU gate elementwise ---------------------------
__global__ void k_gates(int l, const float* __restrict__ hist,
    const float* __restrict__ bih, const float* __restrict__ bhh,
    float* __restrict__ hout){
  int idx = blockIdx.x*256 + threadIdx.x;      // BQ*32
  int b = idx>>5, h4 = (idx&31)<<2;
  float4 gir = *(const float4*)&g_gi[b*384 + h4];
  float4 giz = *(const float4*)&g_gi[b*384 + 128 + h4];
  float4 gin_= *(const float4*)&g_gi[b*384 + 256 + h4];
  float4 ghr = *(const float4*)&g_gh[b*384 + h4];
  float4 ghz = *(const float4*)&g_gh[b*384 + 128 + h4];
  float4 ghn = *(const float4*)&g_gh[b*384 + 256 + h4];
  float4 hp  = *(const float4*)&hist[l*BQ*128 + b*128 + h4];
  float4 bir = *(const float4*)&bih[l*384 + h4];
  float4 biz = *(const float4*)&bih[l*384 + 128 + h4];
  float4 bin_= *(const float4*)&bih[l*384 + 256 + h4];
  float4 bhr = *(const float4*)&bhh[l*384 + h4];
  float4 bhz = *(const float4*)&bhh[l*384 + 128 + h4];
  float4 bhn = *(const float4*)&bhh[l*384 + 256 + h4];
  float4 o;
  {
    float r = sigmf(gir.x+bir.x + ghr.x+bhr.x);
    float z = sigmf(giz.x+biz.x + ghz.x+bhz.x);
    float nn = tanhf(gin_.x+bin_.x + r*(ghn.x+bhn.x));
    o.x = (1.f-z)*nn + z*hp.x;
  }{
    float r = sigmf(gir.y+bir.y + ghr.y+bhr.y);
    float z = sigmf(giz.y+biz.y + ghz.y+bhz.y);
    float nn = tanhf(gin_.y+bin_.y + r*(ghn.y+bhn.y));
    o.y = (1.f-z)*nn + z*hp.y;
  }{
    float r = sigmf(gir.z+bir.z + ghr.z+bhr.z);
    float z = sigmf(giz.z+biz.z + ghz.z+bhz.z);
    float nn = tanhf(gin_.z+bin_.z + r*(ghn.z+bhn.z));
    o.z = (1.f-z)*nn + z*hp.z;
  }{
    float r = sigmf(gir.w+bir.w + ghr.w+bhr.w);
    float z = sigmf(giz.w+biz.w + ghz.w+bhz.w);
    float nn = tanhf(gin_.w+bin_.w + r*(ghn.w+bhn.w));
    o.w = (1.f-z)*nn + z*hp.w;
  }
  *(float4*)&hout[b*128 + h4] = o;
}

// --------------- 5: causal solve (fwd subst) + parent_sum ------------------
__global__ __launch_bounds__(128) void k_causal(
    const float* __restrict__ ew, const float* __restrict__ cm,
    const int* __restrict__ esrc, const int* __restrict__ edst){
  int b = blockIdx.x, t = threadIdx.x;
  __shared__ float s_ew[NE], s_cm[NND*NND];
  __shared__ int s_src[NE], s_dst[NE];
  if (t < NE){ s_ew[t] = ew[b*NE + t]; s_src[t] = esrc[t]; s_dst[t] = edst[t]; }
  if (t < NND*NND) s_cm[t] = cm[t];
  __syncthreads();
  int base = b*NND*HDIM + t;
  float z[NND];
#pragma unroll
  for (int j=0;j<NND;j++) z[j] = g_mean[base + j*HDIM];
#pragma unroll
  for (int j=1;j<NND;j++){
    float add = 0.f;
#pragma unroll
    for (int e=0;e<NE;e++){
      if (s_dst[e] == j){
        int s = s_src[e];
        float zs = (s==0)?z[0]:((s==1)?z[1]:((s==2)?z[2]:z[3]));
        add += s_ew[e]*s_cm[s*NND + j]*zs;
      }
    }
    z[j] += add;
  }
#pragma unroll
  for (int j=0;j<NND;j++) g_z[base + j*HDIM] = z[j];
#pragma unroll
  for (int j=0;j<NND;j++){
    float ps = 0.f;
#pragma unroll
    for (int i=0;i<NND;i++)
      if (s_cm[i*NND + j] != 0.f) ps += z[i];
    g_ps[base + j*HDIM] = ps;
  }
}

// --------------------------- 6: cm layer 1 ---------------------------------
__global__ __launch_bounds__(128,4) void k_cm1(const float* __restrict__ b1){
  int r0 = blockIdx.x*32, t = threadIdx.x;
  __shared__ float s_a[32*128];
  stage(s_a, g_ps + r0*128, 1024, t);
  __syncthreads();
  int cp = t&31, rg = t>>5;
  ull acc[8][4];
  gcore<8,4,128,64,128>(&s_a[rg*8*128], g_Wp_cm1, 256, 2*cp, acc);
  float bb[4];
#pragma unroll
  for (int j=0;j<4;j++) bb[j] = b1[cp + 32*j];
#pragma unroll
  for (int i=0;i<8;i++)
#pragma unroll
    for (int j=0;j<4;j++)
      g_bufB[(r0+rg*8+i)*128 + cp + 32*j] = mishf(accv(acc[i][j]) + bb[j]);
}

// --------------------- 7: cm layer 2 + l_z ---------------------------------
__global__ __launch_bounds__(128,4) void k_cm2(const float* __restrict__ b2){
  int r0 = blockIdx.x*32, t = threadIdx.x;
  __shared__ float s_a[32*128];
  stage(s_a, g_bufB + r0*128, 1024, t);
  __syncthreads();
  int cp = t&31, rg = t>>5;
  ull acc[8][4];
  gcore<8,4,128,64,128>(&s_a[rg*8*128], g_Wp_cm2, 256, 2*cp, acc);
  float bb[4];
#pragma unroll
  for (int j=0;j<4;j++) bb[j] = b2[cp + 32*j];
  float lz = 0.f;
#pragma unroll
  for (int i=0;i<8;i++)
#pragma unroll
    for (int j=0;j<4;j++){
      float d = g_z[(r0+rg*8+i)*128 + cp + 32*j] - (accv(acc[i][j]) + bb[j]);
      lz += d*d;
    }
  BLOCK_REDUCE_TO(g_lzpart, lz);
}

// --------------------------- 8: decoder layer 1 ----------------------------
__global__ __launch_bounds__(128,4) void k_dec1(const float* __restrict__ bias){
  int n = blockIdx.y, b0 = blockIdx.x*32, t = threadIdx.x;
  __shared__ float s_a[32*128];
  for (int f=t; f<1024; f+=128){
    int r = f>>5, c = (f&31)<<2;
    *(float4*)&s_a[r*128+c] = *(const float4*)&g_z[(b0+r)*640 + n*128 + c];
  }
  __syncthreads();
  int cp = t&31, rg = t>>5;
  ull acc[8][4];
  gcore<8,4,128,64,128>(&s_a[rg*8*128], &g_Wp_dec1[n*64*256], 256, 2*cp, acc);
  float bb[4];
#pragma unroll
  for (int j=0;j<4;j++) bb[j] = bias[n*128 + cp + 32*j];
#pragma unroll
  for (int i=0;i<8;i++)
#pragma unroll
    for (int j=0;j<4;j++)
      g_d1[(b0+rg*8+i)*640 + n*128 + cp + 32*j] = mishf(accv(acc[i][j]) + bb[j]);
}

// --------------- 9: decoder layer 2 + per-element losses -------------------
__global__ __launch_bounds__(128,4) void k_dec2(
    const float* __restrict__ b2, const float* __restrict__ yt,
    float* __restrict__ out){
  int n = blockIdx.y, b0 = blockIdx.x*32, t = threadIdx.x;
  __shared__ float s_d[32*128];
  for (int f=t; f<1024; f+=128){
    int r = f>>5, c = (f&31)<<2;
    *(float4*)&s_d[r*128+c] = *(const float4*)&g_d1[(b0+r)*640 + n*128 + c];
  }
  __syncthreads();
  int cp = t&15, rg = t>>4;    // cols cp+16j, rows rg*4..+3
  ull acc[4][4];
  gcore<4,4,128,32,128>(&s_d[rg*4*128], &g_Wp_dec2[n*64*128], 128, 2*cp, acc);
  float ll=0.f, sq4=0.f, bce=0.f;
  float piw[2]={0.f,0.f}, kd[2]={0.f,0.f}, mn[2]={1e30f,1e30f}, mx[2]={-1e30f,-1e30f};
#pragma unroll
  for (int jj=0;jj<2;jj++){
    int d = cp + 16*jj;
    float bm = b2[n*64 + d], bv = b2[n*64 + 32 + d];
#pragma unroll
    for (int r=0;r<4;r++){
      int b = b0 + rg*4 + r;
      int oidx = b*160 + n*32 + d;
      float ym = accv(acc[r][jj]) + bm;
      float yv = expf(accv(acc[r][jj+2]) + bv);
      out[oidx] = ym;
      out[OFF_V + oidx] = yv;
      float ytv = yt[oidx];
      float vs = yv + 1e-6f;
      float df = ytv - ym;
      ll += -0.5f*(df*df/vs + logf(6.2831853071795864f*vs));
      if (n < 4) sq4 += df*df;
      if (n == 4) bce += fmaxf(ym,0.f) - ym*ytv + log1pf(expf(-fabsf(ym)));
      float s  = sqrtf(vs);
      float lo_ = ym - ZALPHA*s, up_ = ym + ZALPHA*s;
      float kf = (ytv >= lo_ && ytv <= up_) ? 1.f : 0.f;
      kd[jj]  += kf;
      piw[jj] += (up_-lo_)*kf;
      mn[jj] = fminf(mn[jj], ytv);
      mx[jj] = fmaxf(mx[jj], ytv);
    }
  }
  ll  = warp_sum(ll);
  sq4 = warp_sum(sq4);
  bce = warp_sum(bce);
  __shared__ float s_sc[3][4];
  __shared__ float2 s_piw[8][16], s_kd[8][16], s_mn[8][16], s_mx[8][16];
  int w = t >> 5;
  if ((t & 31) == 0){ s_sc[0][w]=ll; s_sc[1][w]=sq4; s_sc[2][w]=bce; }
  s_piw[rg][cp] = make_float2(piw[0], piw[1]);
  s_kd [rg][cp] = make_float2(kd[0],  kd[1]);
  s_mn [rg][cp] = make_float2(mn[0],  mn[1]);
  s_mx [rg][cp] = make_float2(mx[0],  mx[1]);
  __syncthreads();
  int blk = blockIdx.y*gridDim.x + blockIdx.x;
  float* P = g_losspart + blk*132;
  if (t == 0){
    P[0] = (s_sc[0][0]+s_sc[0][1]) + (s_sc[0][2]+s_sc[0][3]);
    P[1] = (s_sc[1][0]+s_sc[1][1]) + (s_sc[1][2]+s_sc[1][3]);
    P[2] = (s_sc[2][0]+s_sc[2][1]) + (s_sc[2][2]+s_sc[2][3]);
    P[3] = 0.f;
  }
  if (t < 16){
    float p0=0.f,p1=0.f,k0=0.f,k1=0.f;
    float m0=1e30f,m1=1e30f,x0=-1e30f,x1=-1e30f;
#pragma unroll
    for (int g=0; g<8; g++){
      p0 += s_piw[g][t].x; p1 += s_piw[g][t].y;
      k0 += s_kd[g][t].x;  k1 += s_kd[g][t].y;
      m0 = fminf(m0, s_mn[g][t].x); m1 = fminf(m1, s_mn[g][t].y);
      x0 = fmaxf(x0, s_mx[g][t].x); x1 = fmaxf(x1, s_mx[g][t].y);
    }
    P[4   + t] = p0;  P[4   + 16 + t] = p1;
    P[36  + t] = k0;  P[36  + 16 + t] = k1;
    P[68  + t] = m0;  P[68  + 16 + t] = m1;
    P[100 + t] = x0;  P[100 + 16 + t] = x1;
  }
}

// ----------------- 10: stage-1 reduce (one block per column) ---------------
__global__ void k_reduce1(){
  int col = blockIdx.x, t = threadIdx.x;
  bool ismin = (col >= 68 && col < 100);
  bool ismax = (col >= 100 && col < 132);
  float v = ismin ? 1e30f : (ismax ? -1e30f : 0.f);
  if (col < 132){
    for (int i=t; i<5120; i+=256){
      float x = g_losspart[i*132 + col];
      v = ismin ? fminf(v,x) : (ismax ? fmaxf(v,x) : v + x);
    }
  } else if (col == 132){
    for (int i=t; i<8192; i+=256) v += g_klpart[i];
  } else {
    for (int i=t; i<5120; i+=256) v += g_lzpart[i];
  }
  __shared__ float sm[256];
  sm[t] = v;
  __syncthreads();
  for (int s=128; s>0; s>>=1){
    if (t < s){
      float a = sm[t], b = sm[t+s];
      sm[t] = ismin ? fminf(a,b) : (ismax ? fmaxf(a,b) : a + b);
    }
    __syncthreads();
  }
  if (t == 0) g_facc[col] = sm[0];
}

// ------------------------ 11: final scalar losses --------------------------
__global__ void k_final(float* __restrict__ out){
  if (threadIdx.x != 0 || blockIdx.x != 0) return;
  float S_ll = g_facc[0], S_sq4 = g_facc[1], S_bce = g_facc[2];
  float kl = 0.5f*g_facc[132];
  float S_lz = g_facc[133];
  float mean_ll = S_ll / 5242880.0f;
  float elbo = kl/32768.0f - mean_ll;
  float l_reg = (S_sq4/32.0f) / (4.0f*32768.0f + 1e-6f);
  float l_cls = (S_bce/32.0f) / (32768.0f + 1e-6f);
  float l_rec = l_reg + l_cls;
  float Sk = 0.f, pin = 0.f;
  for (int d=0; d<32; d++){
    float kdv = g_facc[36+d];
    Sk += kdv;
    pin += g_facc[4+d] / (kdv + 1e-6f) / (g_facc[100+d] - g_facc[68+d] + 1e-6f);
  }
  float picp  = Sk / 5242880.0f;
  float pinaw = pin / 32.0f;
  float l_pi  = pinaw - sqrtf(5.0f)*picp;
  float l_z   = S_lz / 20971520.0f;
  float dag   = 0.0f;   // exact: diag((I+ac)^5) == 1 for strictly-upper ac
  float total = powf(elbo*l_rec*l_pi*l_z*(dag + 1e-6f), 0.2f);
  out[OFF_LOSS+0] = total;
  out[OFF_LOSS+1] = elbo;
  out[OFF_LOSS+2] = l_rec;
  out[OFF_LOSS+3] = l_pi;
  out[OFF_LOSS+4] = l_z;
  out[OFF_LOSS+5] = dag;
}

// ------------------------------ launcher -----------------------------------
extern "C" void kernel_launch(void* const* d_in, const int* in_sizes, int n_in,
                              void* d_out, int out_size){
  const float* x       = (const float*)d_in[0];
  const float* y_true  = (const float*)d_in[1];
  const float* ew      = (const float*)d_in[2];
  const float* hist    = (const float*)d_in[3];
  const float* enc_W1  = (const float*)d_in[4];
  const float* enc_b1  = (const float*)d_in[5];
  const float* enc_W2  = (const float*)d_in[6];
  const float* enc_b2  = (const float*)d_in[7];
  const float* gcn_W   = (const float*)d_in[8];
  const float* gcn_b   = (const float*)d_in[9];
  const float* mu_W    = (const float*)d_in[10];
  const float* mu_b    = (const float*)d_in[11];
  const float* sig_W   = (const float*)d_in[12];
  const float* sig_b   = (const float*)d_in[13];
  const float* gru_Wih = (const float*)d_in[14];
  const float* gru_Whh = (const float*)d_in[15];
  const float* gru_bih = (const float*)d_in[16];
  const float* gru_bhh = (const float*)d_in[17];
  const float* cm      = (const float*)d_in[18];
  const float* cm_W1   = (const float*)d_in[19];
  const float* cm_b1   = (const float*)d_in[20];
  const float* cm_W2   = (const float*)d_in[21];
  const float* cm_b2   = (const float*)d_in[22];
  const float* dec_W1  = (const float*)d_in[23];
  const float* dec_b1  = (const float*)d_in[24];
  const float* dec_W2  = (const float*)d_in[25];
  const float* dec_b2  = (const float*)d_in[26];
  const int*   esrc    = (const int*)d_in[27];
  const int*   edst    = (const int*)d_in[28];
  float* out = (float*)d_out;

  float *p;
  cudaGetSymbolAddress((void**)&p, g_Wp_enc1);
  k_pack_kn<<<(5*32*128+255)/256,256>>>(enc_W1, p, 32, 128, 5*32*128);
  cudaGetSymbolAddress((void**)&p, g_Wp_enc2);
  k_pack_kn<<<(5*128*128+255)/256,256>>>(enc_W2, p, 128, 128, 5*128*128);
  cudaGetSymbolAddress((void**)&p, g_Wp_gcn);
  k_pack_kn<<<(2*128*128+255)/256,256>>>(gcn_W, p, 128, 128, 2*128*128);
  cudaGetSymbolAddress((void**)&p, g_Wp_mu);
  k_pack_kn<<<(128*128+255)/256,256>>>(mu_W, p, 128, 128, 128*128);
  cudaGetSymbolAddress((void**)&p, g_Wp_sig);
  k_pack_kn<<<(128*128+255)/256,256>>>(sig_W, p, 128, 128, 128*128);
  cudaGetSymbolAddress((void**)&p, g_Wp_cm1);
  k_pack_kn<<<(128*128+255)/256,256>>>(cm_W1, p, 128, 128, 128*128);
  cudaGetSymbolAddress((void**)&p, g_Wp_cm2);
  k_pack_kn<<<(128*128+255)/256,256>>>(cm_W2, p, 128, 128, 128*128);
  cudaGetSymbolAddress((void**)&p, g_Wp_dec1);
  k_pack_kn<<<(5*128*128+255)/256,256>>>(dec_W1, p, 128, 128, 5*128*128);
  cudaGetSymbolAddress((void**)&p, g_Wp_dec2);
  k_pack_kn<<<(5*128*64+255)/256,256>>>(dec_W2, p, 128, 64, 5*128*64);
  cudaGetSymbolAddress((void**)&p, g_Wp_gi);
  k_pack_nk<<<(2*128*384+255)/256,256>>>(gru_Wih, p, 128, 384, 2*128*384);
  cudaGetSymbolAddress((void**)&p, g_Wp_gh);
  k_pack_nk<<<(2*128*384+255)/256,256>>>(gru_Whh, p, 128, 384, 2*128*384);

  k_enc<<<dim3(BQ/32, NND), 128>>>(x, enc_b1, enc_b2);
  k_gcn<<<BQ/4, 128>>>(0, ew, esrc, edst, gcn_b);
  k_gcn<<<BQ/4, 128>>>(1, ew, esrc, edst, gcn_b);
  k_musig<<<BQ/4, 128>>>(mu_b, sig_b);

  float *gf, *gi_w, *gh_w, *gi_b, *gh_b;
  cudaGetSymbolAddress((void**)&gf, g_gf);
  cudaGetSymbolAddress((void**)&gi_w, g_Wp_gi);
  cudaGetSymbolAddress((void**)&gh_w, g_Wp_gh);
  cudaGetSymbolAddress((void**)&gi_b, g_gi);
  cudaGetSymbolAddress((void**)&gh_b, g_gh);

  k_grug<<<dim3(BQ/32,3), 128>>>(gf, gi_w, gi_b);
  k_grug<<<dim3(BQ/32,3), 128>>>(hist, gh_w, gh_b);
  k_gates<<<BQ*32/256, 256>>>(0, hist, gru_bih, gru_bhh, out + OFF_HID);
  k_grug<<<dim3(BQ/32,3), 128>>>(out + OFF_HID, gi_w + 64*768, gi_b);
  k_grug<<<dim3(BQ/32,3), 128>>>(hist + BQ*128, gh_w + 64*768, gh_b);
  k_gates<<<BQ*32/256, 256>>>(1, hist, gru_bih, gru_bhh, out + OFF_HID + BQ*128);

  k_causal<<<BQ, 128>>>(ew, cm, esrc, edst);
  k_cm1<<<(BQ*NND)/32, 128>>>(cm_b1);
  k_cm2<<<(BQ*NND)/32, 128>>>(cm_b2);
  k_dec1<<<dim3(BQ/32, NND), 128>>>(dec_b1);
  k_dec2<<<dim3(BQ/32, NND), 128>>>(dec_b2, y_true, out);
  k_reduce1<<<134, 256>>>();
  k_final<<<1, 32>>>(out);
}

// round 4
// speedup vs baseline: 1.6352x; 1.0006x over previous
#include <cuda_runtime.h>
#include <math.h>

#define BQ   32768
#define NND  5
#define DDIM 32
#define HDIM 128
#define NE   10

#define OFF_V    (BQ*NND*DDIM)              /* 5242880  */
#define OFF_HID  (2*BQ*NND*DDIM)            /* 10485760 */
#define OFF_LOSS (OFF_HID + 2*BQ*HDIM)      /* 18874368 */

#define ZALPHA 1.959963984540054f

typedef unsigned long long ull;

// ----------------------------- device scratch -----------------------------
__device__ float g_bufA[BQ*NND*HDIM];
__device__ float g_bufB[BQ*NND*HDIM];
__device__ float g_mean[BQ*NND*HDIM];
__device__ float g_z  [BQ*NND*HDIM];
__device__ float g_ps [BQ*NND*HDIM];
__device__ float g_d1 [BQ*NND*HDIM];
__device__ float g_gf [BQ*HDIM];
__device__ float g_gi [BQ*3*HDIM];
__device__ float g_gh [BQ*3*HDIM];
// parity-packed weights: Wp[kk][2c+p] = W[2kk+p][c]
__device__ float g_Wp_enc1[5*16*256];
__device__ float g_Wp_enc2[5*64*256];
__device__ float g_Wp_gcn [2*64*256];
__device__ float g_Wp_mu  [64*256];
__device__ float g_Wp_sig [64*256];
__device__ float g_Wp_cm1 [64*256];
__device__ float g_Wp_cm2 [64*256];
__device__ float g_Wp_dec1[5*64*256];
__device__ float g_Wp_dec2[5*64*128];
__device__ float g_Wp_gi  [2*64*768];
__device__ float g_Wp_gh  [2*64*768];
__device__ float g_klpart[8192];
__device__ float g_lzpart[5120];
__device__ float g_losspart[5120*132];
__device__ float g_facc[134];

// ------------------------------- helpers ----------------------------------
__device__ __forceinline__ ull fma2(ull a, ull b, ull c){
  ull d;
  asm("fma.rn.f32x2 %0, %1, %2, %3;" : "=l"(d) : "l"(a), "l"(b), "l"(c));
  return d;
}
__device__ __forceinline__ float f2lo(ull u){ return __uint_as_float((unsigned)u); }
__device__ __forceinline__ float f2hi(ull u){ return __uint_as_float((unsigned)(u>>32)); }
__device__ __forceinline__ float accv(ull u){ return f2lo(u) + f2hi(u); }

__device__ __forceinline__ float warp_sum(float v){
#pragma unroll
  for (int o=16;o>0;o>>=1) v += __shfl_xor_sync(0xffffffffu, v, o);
  return v;
}
__device__ __forceinline__ float softplusf(float x){
  return fmaxf(x,0.f) + log1pf(expf(-fabsf(x)));
}
__device__ __forceinline__ float mishf(float x){ return x*tanhf(softplusf(x)); }
__device__ __forceinline__ float sigmf(float x){ return 1.f/(1.f+expf(-x)); }

#define BLOCK_REDUCE_TO(part, val)                                      \
  do {                                                                  \
    float _v = warp_sum(val);                                           \
    __shared__ float _sred[4];                                          \
    if ((threadIdx.x & 31) == 0) _sred[threadIdx.x >> 5] = _v;          \
    __syncthreads();                                                    \
    if (threadIdx.x == 0)                                               \
      part[blockIdx.x] = (_sred[0]+_sred[1]) + (_sred[2]+_sred[3]);     \
  } while (0)

// parity split-K GEMM core: acc[i][j] = (even-k partial, odd-k partial)
template<int R, int C, int K, int CS, int LDA>
__device__ __forceinline__ void gcore(const float* __restrict__ sA,
                                      const float* __restrict__ Wp,
                                      int ldw, int cb, ull (&acc)[R][C]){
#pragma unroll
  for (int i=0;i<R;i++)
#pragma unroll
    for (int j=0;j<C;j++) acc[i][j] = 0ull;
#pragma unroll 2
  for (int kk=0; kk<K/2; kk+=2){
    ull w0[C], w1[C];
#pragma unroll
    for (int j=0;j<C;j++){
      w0[j] = *(const ull*)&Wp[kk*ldw + cb + CS*j];
      w1[j] = *(const ull*)&Wp[(kk+1)*ldw + cb + CS*j];
    }
#pragma unroll
    for (int i=0;i<R;i++){
      ulonglong2 a = *(const ulonglong2*)&sA[i*LDA + 2*kk];
#pragma unroll
      for (int j=0;j<C;j++){
        acc[i][j] = fma2(w0[j], a.x, acc[i][j]);
        acc[i][j] = fma2(w1[j], a.y, acc[i][j]);
      }
    }
  }
}

__device__ __forceinline__ void stage(float* s, const float* g, int n4, int t){
  for (int f=t; f<n4; f+=128)
    ((float4*)s)[f] = ((const float4*)g)[f];
}

// --------------------------- pack kernels ----------------------------------
// src[m][k][n] -> dst[m][kk][2n+p] = src[m][2kk+p][n]
__global__ void k_pack_kn(const float* __restrict__ src, float* __restrict__ dst,
                          int K, int Nc, int total){
  int idx = blockIdx.x*256 + threadIdx.x;
  if (idx >= total) return;
  int per = K*Nc;
  int m = idx / per, rem = idx % per;
  int ldw = 2*Nc;
  int kk = rem / ldw, q = rem % ldw;
  int n = q >> 1, p = q & 1;
  dst[idx] = src[m*per + (2*kk+p)*Nc + n];
}
// src[m][n][k] -> dst[m][kk][2n+p] = src[m][n][2kk+p]   (transposing pack)
__global__ void k_pack_nk(const float* __restrict__ src, float* __restrict__ dst,
                          int K, int Nc, int total){
  int idx = blockIdx.x*256 + threadIdx.x;
  if (idx >= total) return;
  int per = K*Nc;
  int m = idx / per, rem = idx % per;
  int ldw = 2*Nc;
  int kk = rem / ldw, q = rem % ldw;
  int n = q >> 1, p = q & 1;
  dst[idx] = src[m*per + n*K + (2*kk+p)];
}

// ------------------------------ 1: encoder ---------------------------------
__global__ __launch_bounds__(128,4) void k_enc(
    const float* __restrict__ x, const float* __restrict__ b1,
    const float* __restrict__ b2){
  int n = blockIdx.y, b0 = blockIdx.x*32, t = threadIdx.x;
  __shared__ float s_x[32*32];
  __shared__ float s_h[32*128];
  for (int f=t; f<256; f+=128){
    int r = f>>3, c = (f&7)<<2;
    *(float4*)&s_x[r*32+c] = *(const float4*)&x[(b0+r)*160 + n*32 + c];
  }
  __syncthreads();
  int cp = t&31, rg = t>>5;
  ull acc[8][4];
  gcore<8,4,32,64,32>(&s_x[rg*8*32], &g_Wp_enc1[n*16*256], 256, 2*cp, acc);
  {
    float bb[4];
#pragma unroll
    for (int j=0;j<4;j++) bb[j] = b1[n*128 + cp + 32*j];
#pragma unroll
    for (int i=0;i<8;i++)
#pragma unroll
      for (int j=0;j<4;j++)
        s_h[(rg*8+i)*128 + cp + 32*j] = fmaxf(accv(acc[i][j]) + bb[j], 0.f);
  }
  __syncthreads();
  gcore<8,4,128,64,128>(&s_h[rg*8*128], &g_Wp_enc2[n*64*256], 256, 2*cp, acc);
  {
    float bb[4];
#pragma unroll
    for (int j=0;j<4;j++) bb[j] = b2[n*128 + cp + 32*j];
#pragma unroll
    for (int i=0;i<8;i++)
#pragma unroll
      for (int j=0;j<4;j++)
        g_bufA[(b0+rg*8+i)*640 + n*128 + cp + 32*j] = accv(acc[i][j]) + bb[j];
  }
}

// ------------------------------- 2: GCN ------------------------------------
__global__ __launch_bounds__(128,4) void k_gcn(
    int l, const float* __restrict__ ew,
    const int* __restrict__ esrc, const int* __restrict__ edst,
    const float* __restrict__ bias){
  int b0 = blockIdx.x*4, t = threadIdx.x;      // 4 batches = 20 rows
  const float* gin  = (l==0) ? g_bufA : g_bufB;
  float*       gout = (l==0) ? g_bufB : g_bufA;
  const float* Wp = &g_Wp_gcn[l*64*256];
  __shared__ float s_g[20*128];
  __shared__ float s_ew[4*NE];
  __shared__ int s_src[NE], s_dst[NE];
  stage(s_g, gin + b0*640, 640, t);
  if (t < 4*NE) s_ew[t] = ew[(b0 + t/NE)*NE + (t%NE)];
  if (t < NE){ s_src[t] = esrc[t]; s_dst[t] = edst[t]; }
  __syncthreads();
  // agg per column t
  {
#pragma unroll
    for (int b=0;b<4;b++){
      float g0 = s_g[(b*5+0)*128 + t];
      float g1 = s_g[(b*5+1)*128 + t];
      float g2 = s_g[(b*5+2)*128 + t];
      float g3 = s_g[(b*5+3)*128 + t];
      float g4 = s_g[(b*5+4)*128 + t];
#pragma unroll
      for (int v=1; v<5; v++){
        float a = (v==1)?g1:((v==2)?g2:((v==3)?g3:g4));
#pragma unroll
        for (int e=0;e<NE;e++){
          if (s_dst[e] == v){
            int s = s_src[e];
            float gs = (s==0)?g0:((s==1)?g1:((s==2)?g2:g3));
            a += s_ew[b*NE+e]*gs;
          }
        }
        s_g[(b*5+v)*128 + t] = a;
      }
    }
  }
  __syncthreads();
  int cp = t&31, rg = t>>5;
  ull acc[5][4];
  gcore<5,4,128,64,128>(&s_g[rg*5*128], Wp, 256, 2*cp, acc);
  float bb[4];
#pragma unroll
  for (int j=0;j<4;j++) bb[j] = bias[l*128 + cp + 32*j];
#pragma unroll
  for (int i=0;i<5;i++)
#pragma unroll
    for (int j=0;j<4;j++)
      gout[b0*640 + (rg*5+i)*128 + cp + 32*j] = fmaxf(accv(acc[i][j]) + bb[j], 0.f);
}

// -------------------- 3: mu/sig heads + KL + graph_feat --------------------
__global__ __launch_bounds__(128,4) void k_musig(
    const float* __restrict__ mub, const float* __restrict__ sigb){
  int b0 = blockIdx.x*4, t = threadIdx.x;
  __shared__ float s_g[20*128];
  stage(s_g, g_bufA + b0*640, 640, t);
  __syncthreads();
  int cp = t&31, rg = t>>5;
  ull acc[5][4];
  gcore<5,4,128,64,128>(&s_g[rg*5*128], g_Wp_mu, 256, 2*cp, acc);
  float m[5][4];
  {
    float bb[4];
#pragma unroll
    for (int j=0;j<4;j++) bb[j] = mub[cp + 32*j];
#pragma unroll
    for (int i=0;i<5;i++)
#pragma unroll
      for (int j=0;j<4;j++){
        m[i][j] = accv(acc[i][j]) + bb[j];
        g_mean[(b0+rg)*640 + i*128 + cp + 32*j] = m[i][j];
      }
#pragma unroll
    for (int j=0;j<4;j++){
      float gf = (m[0][j]+m[1][j]+m[2][j]+m[3][j]+m[4][j])*0.2f;
      g_gf[(b0+rg)*128 + cp + 32*j] = gf;
    }
  }
  gcore<5,4,128,64,128>(&s_g[rg*5*128], g_Wp_sig, 256, 2*cp, acc);
  float kll = 0.f;
  {
    float bb[4];
#pragma unroll
    for (int j=0;j<4;j++) bb[j] = sigb[cp + 32*j];
#pragma unroll
    for (int i=0;i<5;i++)
#pragma unroll
      for (int j=0;j<4;j++){
        float sp = softplusf(accv(acc[i][j]) + bb[j]);
        float var = sp*sp;
        kll += m[i][j]*m[i][j] + var - logf(var + 1e-8f) - 1.f;
      }
  }
  BLOCK_REDUCE_TO(g_klpart, kll);
}

// ---------------------- 4: GRU GEMM (N=384 tiles) --------------------------
__global__ __launch_bounds__(128,4) void k_grug(
    const float* __restrict__ A, const float* __restrict__ Wp,
    float* __restrict__ outb){
  int b0 = blockIdx.x*32, tile = blockIdx.y, t = threadIdx.x;
  __shared__ float s_a[32*128];
  stage(s_a, A + b0*128, 1024, t);
  __syncthreads();
  int cp = t&31, rg = t>>5;
  ull acc[8][4];
  gcore<8,4,128,64,128>(&s_a[rg*8*128], Wp, 768, tile*256 + 2*cp, acc);
#pragma unroll
  for (int i=0;i<8;i++)
#pragma unroll
    for (int j=0;j<4;j++)
      outb[(b0+rg*8+i)*384 + tile*128 + cp + 32*j] = accv(acc[i][j]);
}

// ---------------------- 4b: GRU gate elementwise ---------------------------
__global__ void k_gates(int l, const float* __restrict__ hist,
    const float* __restrict__ bih, const float* __restrict__ bhh,
    float* __restrict__ hout){
  int idx = blockIdx.x*256 + threadIdx.x;      // BQ*32
  int b = idx>>5, h4 = (idx&31)<<2;
  float4 gir = *(const float4*)&g_gi[b*384 + h4];
  float4 giz = *(const float4*)&g_gi[b*384 + 128 + h4];
  float4 gin_= *(const float4*)&g_gi[b*384 + 256 + h4];
  float4 ghr = *(const float4*)&g_gh[b*384 + h4];
  float4 ghz = *(const float4*)&g_gh[b*384 + 128 + h4];
  float4 ghn = *(const float4*)&g_gh[b*384 + 256 + h4];
  float4 hp  = *(const float4*)&hist[l*BQ*128 + b*128 + h4];
  float4 bir = *(const float4*)&bih[l*384 + h4];
  float4 biz = *(const float4*)&bih[l*384 + 128 + h4];
  float4 bin_= *(const float4*)&bih[l*384 + 256 + h4];
  float4 bhr = *(const float4*)&bhh[l*384 + h4];
  float4 bhz = *(const float4*)&bhh[l*384 + 128 + h4];
  float4 bhn = *(const float4*)&bhh[l*384 + 256 + h4];
  float4 o;
  {
    float r = sigmf(gir.x+bir.x + ghr.x+bhr.x);
    float z = sigmf(giz.x+biz.x + ghz.x+bhz.x);
    float nn = tanhf(gin_.x+bin_.x + r*(ghn.x+bhn.x));
    o.x = (1.f-z)*nn + z*hp.x;
  }{
    float r = sigmf(gir.y+bir.y + ghr.y+bhr.y);
    float z = sigmf(giz.y+biz.y + ghz.y+bhz.y);
    float nn = tanhf(gin_.y+bin_.y + r*(ghn.y+bhn.y));
    o.y = (1.f-z)*nn + z*hp.y;
  }{
    float r = sigmf(gir.z+bir.z + ghr.z+bhr.z);
    float z = sigmf(giz.z+biz.z + ghz.z+bhz.z);
    float nn = tanhf(gin_.z+bin_.z + r*(ghn.z+bhn.z));
    o.z = (1.f-z)*nn + z*hp.z;
  }{
    float r = sigmf(gir.w+bir.w + ghr.w+bhr.w);
    float z = sigmf(giz.w+biz.w + ghz.w+bhz.w);
    float nn = tanhf(gin_.w+bin_.w + r*(ghn.w+bhn.w));
    o.w = (1.f-z)*nn + z*hp.w;
  }
  *(float4*)&hout[b*128 + h4] = o;
}

// --------------- 5: causal solve (fwd subst) + parent_sum ------------------
__global__ __launch_bounds__(128) void k_causal(
    const float* __restrict__ ew, const float* __restrict__ cm,
    const int* __restrict__ esrc, const int* __restrict__ edst){
  int b = blockIdx.x, t = threadIdx.x;
  __shared__ float s_ew[NE], s_cm[NND*NND];
  __shared__ int s_src[NE], s_dst[NE];
  if (t < NE){ s_ew[t] = ew[b*NE + t]; s_src[t] = esrc[t]; s_dst[t] = edst[t]; }
  if (t < NND*NND) s_cm[t] = cm[t];
  __syncthreads();
  int base = b*NND*HDIM + t;
  float z[NND];
#pragma unroll
  for (int j=0;j<NND;j++) z[j] = g_mean[base + j*HDIM];
#pragma unroll
  for (int j=1;j<NND;j++){
    float add = 0.f;
#pragma unroll
    for (int e=0;e<NE;e++){
      if (s_dst[e] == j){
        int s = s_src[e];
        float zs = (s==0)?z[0]:((s==1)?z[1]:((s==2)?z[2]:z[3]));
        add += s_ew[e]*s_cm[s*NND + j]*zs;
      }
    }
    z[j] += add;
  }
#pragma unroll
  for (int j=0;j<NND;j++) g_z[base + j*HDIM] = z[j];
#pragma unroll
  for (int j=0;j<NND;j++){
    float ps = 0.f;
#pragma unroll
    for (int i=0;i<NND;i++)
      if (s_cm[i*NND + j] != 0.f) ps += z[i];
    g_ps[base + j*HDIM] = ps;
  }
}

// --------------------------- 6: cm layer 1 ---------------------------------
__global__ __launch_bounds__(128,4) void k_cm1(const float* __restrict__ b1){
  int r0 = blockIdx.x*32, t = threadIdx.x;
  __shared__ float s_a[32*128];
  stage(s_a, g_ps + r0*128, 1024, t);
  __syncthreads();
  int cp = t&31, rg = t>>5;
  ull acc[8][4];
  gcore<8,4,128,64,128>(&s_a[rg*8*128], g_Wp_cm1, 256, 2*cp, acc);
  float bb[4];
#pragma unroll
  for (int j=0;j<4;j++) bb[j] = b1[cp + 32*j];
#pragma unroll
  for (int i=0;i<8;i++)
#pragma unroll
    for (int j=0;j<4;j++)
      g_bufB[(r0+rg*8+i)*128 + cp + 32*j] = mishf(accv(acc[i][j]) + bb[j]);
}

// --------------------- 7: cm layer 2 + l_z ---------------------------------
__global__ __launch_bounds__(128,4) void k_cm2(const float* __restrict__ b2){
  int r0 = blockIdx.x*32, t = threadIdx.x;
  __shared__ float s_a[32*128];
  stage(s_a, g_bufB + r0*128, 1024, t);
  __syncthreads();
  int cp = t&31, rg = t>>5;
  ull acc[8][4];
  gcore<8,4,128,64,128>(&s_a[rg*8*128], g_Wp_cm2, 256, 2*cp, acc);
  float bb[4];
#pragma unroll
  for (int j=0;j<4;j++) bb[j] = b2[cp + 32*j];
  float lz = 0.f;
#pragma unroll
  for (int i=0;i<8;i++)
#pragma unroll
    for (int j=0;j<4;j++){
      float d = g_z[(r0+rg*8+i)*128 + cp + 32*j] - (accv(acc[i][j]) + bb[j]);
      lz += d*d;
    }
  BLOCK_REDUCE_TO(g_lzpart, lz);
}

// --------------------------- 8: decoder layer 1 ----------------------------
__global__ __launch_bounds__(128,4) void k_dec1(const float* __restrict__ bias){
  int n = blockIdx.y, b0 = blockIdx.x*32, t = threadIdx.x;
  __shared__ float s_a[32*128];
  for (int f=t; f<1024; f+=128){
    int r = f>>5, c = (f&31)<<2;
    *(float4*)&s_a[r*128+c] = *(const float4*)&g_z[(b0+r)*640 + n*128 + c];
  }
  __syncthreads();
  int cp = t&31, rg = t>>5;
  ull acc[8][4];
  gcore<8,4,128,64,128>(&s_a[rg*8*128], &g_Wp_dec1[n*64*256], 256, 2*cp, acc);
  float bb[4];
#pragma unroll
  for (int j=0;j<4;j++) bb[j] = bias[n*128 + cp + 32*j];
#pragma unroll
  for (int i=0;i<8;i++)
#pragma unroll
    for (int j=0;j<4;j++)
      g_d1[(b0+rg*8+i)*640 + n*128 + cp + 32*j] = mishf(accv(acc[i][j]) + bb[j]);
}

// --------------- 9: decoder layer 2 + per-element losses -------------------
__global__ __launch_bounds__(128,4) void k_dec2(
    const float* __restrict__ b2, const float* __restrict__ yt,
    float* __restrict__ out){
  int n = blockIdx.y, b0 = blockIdx.x*32, t = threadIdx.x;
  __shared__ float s_d[32*128];
  for (int f=t; f<1024; f+=128){
    int r = f>>5, c = (f&31)<<2;
    *(float4*)&s_d[r*128+c] = *(const float4*)&g_d1[(b0+r)*640 + n*128 + c];
  }
  __syncthreads();
  int cp = t&15, rg = t>>4;    // cols cp+16j, rows rg*4..+3
  ull acc[4][4];
  gcore<4,4,128,32,128>(&s_d[rg*4*128], &g_Wp_dec2[n*64*128], 128, 2*cp, acc);
  float ll=0.f, sq4=0.f, bce=0.f;
  float piw[2]={0.f,0.f}, kd[2]={0.f,0.f}, mn[2]={1e30f,1e30f}, mx[2]={-1e30f,-1e30f};
#pragma unroll
  for (int jj=0;jj<2;jj++){
    int d = cp + 16*jj;
    float bm = b2[n*64 + d], bv = b2[n*64 + 32 + d];
#pragma unroll
    for (int r=0;r<4;r++){
      int b = b0 + rg*4 + r;
      int oidx = b*160 + n*32 + d;
      float ym = accv(acc[r][jj]) + bm;
      float yv = expf(accv(acc[r][jj+2]) + bv);
      out[oidx] = ym;
      out[OFF_V + oidx] = yv;
      float ytv = yt[oidx];
      float vs = yv + 1e-6f;
      float df = ytv - ym;
      ll += -0.5f*(df*df/vs + logf(6.2831853071795864f*vs));
      if (n < 4) sq4 += df*df;
      if (n == 4) bce += fmaxf(ym,0.f) - ym*ytv + log1pf(expf(-fabsf(ym)));
      float s  = sqrtf(vs);
      float lo_ = ym - ZALPHA*s, up_ = ym + ZALPHA*s;
      float kf = (ytv >= lo_ && ytv <= up_) ? 1.f : 0.f;
      kd[jj]  += kf;
      piw[jj] += (up_-lo_)*kf;
      mn[jj] = fminf(mn[jj], ytv);
      mx[jj] = fmaxf(mx[jj], ytv);
    }
  }
  ll  = warp_sum(ll);
  sq4 = warp_sum(sq4);
  bce = warp_sum(bce);
  __shared__ float s_sc[3][4];
  __shared__ float2 s_piw[8][16], s_kd[8][16], s_mn[8][16], s_mx[8][16];
  int w = t >> 5;
  if ((t & 31) == 0){ s_sc[0][w]=ll; s_sc[1][w]=sq4; s_sc[2][w]=bce; }
  s_piw[rg][cp] = make_float2(piw[0], piw[1]);
  s_kd [rg][cp] = make_float2(kd[0],  kd[1]);
  s_mn [rg][cp] = make_float2(mn[0],  mn[1]);
  s_mx [rg][cp] = make_float2(mx[0],  mx[1]);
  __syncthreads();
  int blk = blockIdx.y*gridDim.x + blockIdx.x;
  float* P = g_losspart + blk*132;
  if (t == 0){
    P[0] = (s_sc[0][0]+s_sc[0][1]) + (s_sc[0][2]+s_sc[0][3]);
    P[1] = (s_sc[1][0]+s_sc[1][1]) + (s_sc[1][2]+s_sc[1][3]);
    P[2] = (s_sc[2][0]+s_sc[2][1]) + (s_sc[2][2]+s_sc[2][3]);
    P[3] = 0.f;
  }
  if (t < 16){
    float p0=0.f,p1=0.f,k0=0.f,k1=0.f;
    float m0=1e30f,m1=1e30f,x0=-1e30f,x1=-1e30f;
#pragma unroll
    for (int g=0; g<8; g++){
      p0 += s_piw[g][t].x; p1 += s_piw[g][t].y;
      k0 += s_kd[g][t].x;  k1 += s_kd[g][t].y;
      m0 = fminf(m0, s_mn[g][t].x); m1 = fminf(m1, s_mn[g][t].y);
      x0 = fmaxf(x0, s_mx[g][t].x); x1 = fmaxf(x1, s_mx[g][t].y);
    }
    P[4   + t] = p0;  P[4   + 16 + t] = p1;
    P[36  + t] = k0;  P[36  + 16 + t] = k1;
    P[68  + t] = m0;  P[68  + 16 + t] = m1;
    P[100 + t] = x0;  P[100 + 16 + t] = x1;
  }
}

// ----------------- 10: stage-1 reduce (one block per column) ---------------
__global__ void k_reduce1(){
  int col = blockIdx.x, t = threadIdx.x;
  bool ismin = (col >= 68 && col < 100);
  bool ismax = (col >= 100 && col < 132);
  float v = ismin ? 1e30f : (ismax ? -1e30f : 0.f);
  if (col < 132){
    for (int i=t; i<5120; i+=256){
      float x = g_losspart[i*132 + col];
      v = ismin ? fminf(v,x) : (ismax ? fmaxf(v,x) : v + x);
    }
  } else if (col == 132){
    for (int i=t; i<8192; i+=256) v += g_klpart[i];
  } else {
    for (int i=t; i<5120; i+=256) v += g_lzpart[i];
  }
  __shared__ float sm[256];
  sm[t] = v;
  __syncthreads();
  for (int s=128; s>0; s>>=1){
    if (t < s){
      float a = sm[t], b = sm[t+s];
      sm[t] = ismin ? fminf(a,b) : (ismax ? fmaxf(a,b) : a + b);
    }
    __syncthreads();
  }
  if (t == 0) g_facc[col] = sm[0];
}

// ------------------------ 11: final scalar losses --------------------------
__global__ void k_final(float* __restrict__ out){
  if (threadIdx.x != 0 || blockIdx.x != 0) return;
  float S_ll = g_facc[0], S_sq4 = g_facc[1], S_bce = g_facc[2];
  float kl = 0.5f*g_facc[132];
  float S_lz = g_facc[133];
  float mean_ll = S_ll / 5242880.0f;
  float elbo = kl/32768.0f - mean_ll;
  float l_reg = (S_sq4/32.0f) / (4.0f*32768.0f + 1e-6f);
  float l_cls = (S_bce/32.0f) / (32768.0f + 1e-6f);
  float l_rec = l_reg + l_cls;
  float Sk = 0.f, pin = 0.f;
  for (int d=0; d<32; d++){
    float kdv = g_facc[36+d];
    Sk += kdv;
    pin += g_facc[4+d] / (kdv + 1e-6f) / (g_facc[100+d] - g_facc[68+d] + 1e-6f);
  }
  float picp  = Sk / 5242880.0f;
  float pinaw = pin / 32.0f;
  float l_pi  = pinaw - sqrtf(5.0f)*picp;
  float l_z   = S_lz / 20971520.0f;
  float dag   = 0.0f;   // exact: diag((I+ac)^5) == 1 for strictly-upper ac
  float total = powf(elbo*l_rec*l_pi*l_z*(dag + 1e-6f), 0.2f);
  out[OFF_LOSS+0] = total;
  out[OFF_LOSS+1] = elbo;
  out[OFF_LOSS+2] = l_rec;
  out[OFF_LOSS+3] = l_pi;
  out[OFF_LOSS+4] = l_z;
  out[OFF_LOSS+5] = dag;
}

// ------------------------------ launcher -----------------------------------
extern "C" void kernel_launch(void* const* d_in, const int* in_sizes, int n_in,
                              void* d_out, int out_size){
  const float* x       = (const float*)d_in[0];
  const float* y_true  = (const float*)d_in[1];
  const float* ew      = (const float*)d_in[2];
  const float* hist    = (const float*)d_in[3];
  const float* enc_W1  = (const float*)d_in[4];
  const float* enc_b1  = (const float*)d_in[5];
  const float* enc_W2  = (const float*)d_in[6];
  const float* enc_b2  = (const float*)d_in[7];
  const float* gcn_W   = (const float*)d_in[8];
  const float* gcn_b   = (const float*)d_in[9];
  const float* mu_W    = (const float*)d_in[10];
  const float* mu_b    = (const float*)d_in[11];
  const float* sig_W   = (const float*)d_in[12];
  const float* sig_b   = (const float*)d_in[13];
  const float* gru_Wih = (const float*)d_in[14];
  const float* gru_Whh = (const float*)d_in[15];
  const float* gru_bih = (const float*)d_in[16];
  const float* gru_bhh = (const float*)d_in[17];
  const float* cm      = (const float*)d_in[18];
  const float* cm_W1   = (const float*)d_in[19];
  const float* cm_b1   = (const float*)d_in[20];
  const float* cm_W2   = (const float*)d_in[21];
  const float* cm_b2   = (const float*)d_in[22];
  const float* dec_W1  = (const float*)d_in[23];
  const float* dec_b1  = (const float*)d_in[24];
  const float* dec_W2  = (const float*)d_in[25];
  const float* dec_b2  = (const float*)d_in[26];
  const int*   esrc    = (const int*)d_in[27];
  const int*   edst    = (const int*)d_in[28];
  float* out = (float*)d_out;

  float *p;
  cudaGetSymbolAddress((void**)&p, g_Wp_enc1);
  k_pack_kn<<<(5*32*128+255)/256,256>>>(enc_W1, p, 32, 128, 5*32*128);
  cudaGetSymbolAddress((void**)&p, g_Wp_enc2);
  k_pack_kn<<<(5*128*128+255)/256,256>>>(enc_W2, p, 128, 128, 5*128*128);
  cudaGetSymbolAddress((void**)&p, g_Wp_gcn);
  k_pack_kn<<<(2*128*128+255)/256,256>>>(gcn_W, p, 128, 128, 2*128*128);
  cudaGetSymbolAddress((void**)&p, g_Wp_mu);
  k_pack_kn<<<(128*128+255)/256,256>>>(mu_W, p, 128, 128, 128*128);
  cudaGetSymbolAddress((void**)&p, g_Wp_sig);
  k_pack_kn<<<(128*128+255)/256,256>>>(sig_W, p, 128, 128, 128*128);
  cudaGetSymbolAddress((void**)&p, g_Wp_cm1);
  k_pack_kn<<<(128*128+255)/256,256>>>(cm_W1, p, 128, 128, 128*128);
  cudaGetSymbolAddress((void**)&p, g_Wp_cm2);
  k_pack_kn<<<(128*128+255)/256,256>>>(cm_W2, p, 128, 128, 128*128);
  cudaGetSymbolAddress((void**)&p, g_Wp_dec1);
  k_pack_kn<<<(5*128*128+255)/256,256>>>(dec_W1, p, 128, 128, 5*128*128);
  cudaGetSymbolAddress((void**)&p, g_Wp_dec2);
  k_pack_kn<<<(5*128*64+255)/256,256>>>(dec_W2, p, 128, 64, 5*128*64);
  cudaGetSymbolAddress((void**)&p, g_Wp_gi);
  k_pack_nk<<<(2*128*384+255)/256,256>>>(gru_Wih, p, 128, 384, 2*128*384);
  cudaGetSymbolAddress((void**)&p, g_Wp_gh);
  k_pack_nk<<<(2*128*384+255)/256,256>>>(gru_Whh, p, 128, 384, 2*128*384);

  k_enc<<<dim3(BQ/32, NND), 128>>>(x, enc_b1, enc_b2);
  k_gcn<<<BQ/4, 128>>>(0, ew, esrc, edst, gcn_b);
  k_gcn<<<BQ/4, 128>>>(1, ew, esrc, edst, gcn_b);
  k_musig<<<BQ/4, 128>>>(mu_b, sig_b);

  float *gf, *gi_w, *gh_w, *gi_b, *gh_b;
  cudaGetSymbolAddress((void**)&gf, g_gf);
  cudaGetSymbolAddress((void**)&gi_w, g_Wp_gi);
  cudaGetSymbolAddress((void**)&gh_w, g_Wp_gh);
  cudaGetSymbolAddress((void**)&gi_b, g_gi);
  cudaGetSymbolAddress((void**)&gh_b, g_gh);

  k_grug<<<dim3(BQ/32,3), 128>>>(gf, gi_w, gi_b);
  k_grug<<<dim3(BQ/32,3), 128>>>(hist, gh_w, gh_b);
  k_gates<<<BQ*32/256, 256>>>(0, hist, gru_bih, gru_bhh, out + OFF_HID);
  k_grug<<<dim3(BQ/32,3), 128>>>(out + OFF_HID, gi_w + 64*768, gi_b);
  k_grug<<<dim3(BQ/32,3), 128>>>(hist + BQ*128, gh_w + 64*768, gh_b);
  k_gates<<<BQ*32/256, 256>>>(1, hist, gru_bih, gru_bhh, out + OFF_HID + BQ*128);

  k_causal<<<BQ, 128>>>(ew, cm, esrc, edst);
  k_cm1<<<(BQ*NND)/32, 128>>>(cm_b1);
  k_cm2<<<(BQ*NND)/32, 128>>>(cm_b2);
  k_dec1<<<dim3(BQ/32, NND), 128>>>(dec_b1);
  k_dec2<<<dim3(BQ/32, NND), 128>>>(dec_b2, y_true, out);
  k_reduce1<<<134, 256>>>();
  k_final<<<1, 32>>>(out);
}

// round 5
// speedup vs baseline: 2.9859x; 1.8260x over previous
#include <cuda_runtime.h>
#include <cuda_bf16.h>
#include <math.h>

#define BQ   32768
#define NND  5
#define HDIM 128
#define NE   10

#define OFF_V    (BQ*NND*32)
#define OFF_HID  (2*BQ*NND*32)
#define OFF_LOSS (OFF_HID + 2*BQ*HDIM)

#define ZALPHA 1.959963984540054f

// fragment arena offsets (uint2 units)
#define WF_ENC1 0
#define WF_ENC2 10240
#define WF_GCN  51200
#define WF_MU   67584
#define WF_SIG  75776
#define WF_CM1  83968
#define WF_CM2  92160
#define WF_DEC1 100352
#define WF_DEC2 141312
#define WF_GI   161792
#define WF_GH   210944
#define WF_TOT  260096

// ----------------------------- device scratch -----------------------------
__device__ float g_bufA[BQ*NND*HDIM];
__device__ float g_bufB[BQ*NND*HDIM];
__device__ float g_mean[BQ*NND*HDIM];
__device__ float g_z  [BQ*NND*HDIM];
__device__ float g_ps [BQ*NND*HDIM];
__device__ float g_d1 [BQ*NND*HDIM];
__device__ float g_gf [BQ*HDIM];
__device__ float g_gi [BQ*3*HDIM];
__device__ float g_gh [BQ*3*HDIM];
__device__ uint2 g_Wf [WF_TOT];
__device__ float g_klpart[2560];
__device__ float g_lzpart[2560];
__device__ float g_losspart[2560*132];
__device__ float g_facc[134];

// ------------------------------- helpers ----------------------------------
__device__ __forceinline__ float warp_sum(float v){
#pragma unroll
  for (int o=16;o>0;o>>=1) v += __shfl_xor_sync(0xffffffffu, v, o);
  return v;
}
__device__ __forceinline__ float softplusf(float x){
  return fmaxf(x,0.f) + log1pf(expf(-fabsf(x)));
}
__device__ __forceinline__ float mishf(float x){ return x*tanhf(softplusf(x)); }
__device__ __forceinline__ float sigmf(float x){ return 1.f/(1.f+expf(-x)); }

#define BLOCK_REDUCE_TO(part, val)                                      \
  do {                                                                  \
    float _v = warp_sum(val);                                           \
    __shared__ float _sred[4];                                          \
    if ((threadIdx.x & 31) == 0) _sred[threadIdx.x >> 5] = _v;          \
    __syncthreads();                                                    \
    if (threadIdx.x == 0)                                               \
      part[blockIdx.x] = (_sred[0]+_sred[1]) + (_sred[2]+_sred[3]);     \
  } while (0)

__device__ __forceinline__ unsigned pkh(float x, float y){
  unsigned short a = __bfloat16_as_ushort(__float2bfloat16_rn(x));
  unsigned short b = __bfloat16_as_ushort(__float2bfloat16_rn(y));
  return ((unsigned)b<<16) | (unsigned)a;
}
__device__ __forceinline__ float bf16f(float x){
  return __bfloat162float(__float2bfloat16_rn(x));
}
__device__ __forceinline__ unsigned sptr(const void* p){
  return (unsigned)__cvta_generic_to_shared(p);
}
__device__ __forceinline__ void ldsm4(unsigned a, unsigned &r0, unsigned &r1,
                                      unsigned &r2, unsigned &r3){
  asm volatile("ldmatrix.sync.aligned.m8n8.x4.shared.b16 {%0,%1,%2,%3}, [%4];"
               : "=r"(r0),"=r"(r1),"=r"(r2),"=r"(r3) : "r"(a));
}
__device__ __forceinline__ void mma16816(float* c, const unsigned* a,
                                         unsigned b0, unsigned b1){
  asm volatile("mma.sync.aligned.m16n8k16.row.col.f32.bf16.bf16.f32 "
      "{%0,%1,%2,%3},{%4,%5,%6,%7},{%8,%9},{%0,%1,%2,%3};"
      : "+f"(c[0]),"+f"(c[1]),"+f"(c[2]),"+f"(c[3])
      : "r"(a[0]),"r"(a[1]),"r"(a[2]),"r"(a[3]),"r"(b0),"r"(b1));
}

// stage 64 x KC fp32 -> split bf16 hi/lo smem (row stride LDA bf16)
template<int KC, int LDA>
__device__ __forceinline__ void stage_split(const float* __restrict__ A, int arst,
    __nv_bfloat16* sh, __nv_bfloat16* sl, int t){
  const int C4 = KC/4;
  for (int f=t; f<64*C4; f+=128){
    int r = f/C4, c4 = (f%C4)*4;
    float4 v = *(const float4*)&A[(long)r*arst + c4];
    unsigned h0 = pkh(v.x, v.y), h1 = pkh(v.z, v.w);
    unsigned l0 = pkh(v.x-bf16f(v.x), v.y-bf16f(v.y));
    unsigned l1 = pkh(v.z-bf16f(v.z), v.w-bf16f(v.w));
    *(uint2*)&sh[r*LDA+c4] = make_uint2(h0,h1);
    *(uint2*)&sl[r*LDA+c4] = make_uint2(l0,l1);
  }
}

// 3-term bf16 split mainloop: block M=64, warp covers NT n8-tiles
template<int KT, int NT, int NTOT, int LDA>
__device__ __forceinline__ void hmma_main(const __nv_bfloat16* sh,
    const __nv_bfloat16* sl, const uint2* __restrict__ Wf,
    int warp, int lane, float (&c)[4][NT][4]){
#pragma unroll
  for (int mt=0;mt<4;mt++)
#pragma unroll
    for (int nt=0;nt<NT;nt++)
#pragma unroll
      for (int i=0;i<4;i++) c[mt][nt][i] = 0.f;
  int sub = lane>>3;
  int m_off = ((sub&1)<<3) + (lane&7);
  int k_off = (sub>>1)<<3;
#pragma unroll 1
  for (int kt=0; kt<KT; kt++){
    uint2 bh[NT], bl[NT];
#pragma unroll
    for (int nt=0;nt<NT;nt++){
      const uint2* wp = Wf + (((kt*NTOT + warp*NT + nt)*2)<<5) + lane;
      bh[nt] = wp[0];
      bl[nt] = wp[32];
    }
    unsigned ah[4][4], al[4][4];
#pragma unroll
    for (int mt=0;mt<4;mt++){
      int ro = (mt*16 + m_off)*LDA + kt*16 + k_off;
      ldsm4(sptr(&sh[ro]), ah[mt][0],ah[mt][1],ah[mt][2],ah[mt][3]);
      ldsm4(sptr(&sl[ro]), al[mt][0],al[mt][1],al[mt][2],al[mt][3]);
    }
#pragma unroll
    for (int mt=0;mt<4;mt++)
#pragma unroll
      for (int nt=0;nt<NT;nt++){
        mma16816(c[mt][nt], ah[mt], bh[nt].x, bh[nt].y);
        mma16816(c[mt][nt], al[mt], bh[nt].x, bh[nt].y);
        mma16816(c[mt][nt], ah[mt], bl[nt].x, bl[nt].y);
      }
  }
}

// --------------------------- weight pack -----------------------------------
// dst[m][kt][n8][term][lane] = uint2{b0,b1} B-fragments (hi term0, lo term1)
__global__ void k_pack(const float* __restrict__ src, uint2* __restrict__ dst,
                       int K, int N, int count, int mstride, int trans){
  int frags = (K/16)*(N/8)*64;
  int idx = blockIdx.x*256 + threadIdx.x;
  if (idx >= count*frags) return;
  int m = idx / frags, r = idx % frags;
  int lane = r & 31, term = (r>>5)&1;
  int n8 = (r>>6) % (N>>3);
  int kt = (r>>6) / (N>>3);
  int n = n8*8 + (lane>>2);
  int k0 = kt*16 + ((lane&3)<<1);
  const float* S = src + (long)m*mstride;
  float w0,w1,w2,w3;
  if (trans){
    w0=S[n*K+k0]; w1=S[n*K+k0+1]; w2=S[n*K+k0+8]; w3=S[n*K+k0+9];
  } else {
    w0=S[k0*N+n]; w1=S[(k0+1)*N+n]; w2=S[(k0+8)*N+n]; w3=S[(k0+9)*N+n];
  }
  unsigned b0, b1;
  if (term==0){ b0 = pkh(w0,w1); b1 = pkh(w2,w3); }
  else {
    b0 = pkh(w0-bf16f(w0), w1-bf16f(w1));
    b1 = pkh(w2-bf16f(w2), w3-bf16f(w3));
  }
  dst[idx] = make_uint2(b0,b1);
}

// --------------------------- generic GEMM ----------------------------------
// ACT: 0 none, 1 relu, 2 mish
template<int ACT>
__global__ __launch_bounds__(128) void k_gemm(
    const float* __restrict__ A, int arst, int aofs,
    const uint2* __restrict__ Wf, int wofs,
    const float* __restrict__ bias, int bofs,
    float* __restrict__ Out, int orst, int oofs){
  __shared__ __align__(16) __nv_bfloat16 sh[64*136], sl[64*136];
  int t = threadIdx.x, lane = t&31, warp = t>>5;
  long b0 = (long)blockIdx.x*64;
  A   += (long)blockIdx.y*aofs;
  Wf  += (long)blockIdx.y*wofs;
  if (bias) bias += blockIdx.y*bofs;
  Out += (long)blockIdx.y*oofs;
  stage_split<128,136>(A + b0*arst, arst, sh, sl, t);
  __syncthreads();
  float c[4][4][4];
  hmma_main<8,4,16,136>(sh, sl, Wf, warp, lane, c);
#pragma unroll
  for (int mt=0;mt<4;mt++){
    long r0 = b0 + mt*16 + (lane>>2);
#pragma unroll
    for (int nt=0;nt<4;nt++){
      int col = (warp*4+nt)*8 + ((lane&3)<<1);
      float bx=0.f, by=0.f;
      if (bias){ float2 bb = *(const float2*)&bias[col]; bx=bb.x; by=bb.y; }
      float v00=c[mt][nt][0]+bx, v01=c[mt][nt][1]+by;
      float v10=c[mt][nt][2]+bx, v11=c[mt][nt][3]+by;
      if (ACT==1){ v00=fmaxf(v00,0.f); v01=fmaxf(v01,0.f);
                   v10=fmaxf(v10,0.f); v11=fmaxf(v11,0.f); }
      if (ACT==2){ v00=mishf(v00); v01=mishf(v01);
                   v10=mishf(v10); v11=mishf(v11); }
      *(float2*)&Out[r0*orst + col]     = make_float2(v00,v01);
      *(float2*)&Out[(r0+8)*orst + col] = make_float2(v10,v11);
    }
  }
}

// ------------------------------ encoder ------------------------------------
__global__ __launch_bounds__(128) void k_enc(
    const float* __restrict__ x, const float* __restrict__ b1,
    const float* __restrict__ b2){
  __shared__ __align__(16) __nv_bfloat16 xh[64*40], xl[64*40];
  __shared__ __align__(16) __nv_bfloat16 hh[64*136], hl[64*136];
  int t = threadIdx.x, lane = t&31, warp = t>>5;
  int n = blockIdx.y;
  long b0 = (long)blockIdx.x*64;
  stage_split<32,40>(x + b0*160 + n*32, 160, xh, xl, t);
  __syncthreads();
  float c[4][4][4];
  hmma_main<2,4,16,40>(xh, xl, &g_Wf[WF_ENC1 + n*2048], warp, lane, c);
#pragma unroll
  for (int mt=0;mt<4;mt++){
    int r0 = mt*16 + (lane>>2);
#pragma unroll
    for (int nt=0;nt<4;nt++){
      int col = (warp*4+nt)*8 + ((lane&3)<<1);
      float2 bb = *(const float2*)&b1[n*128 + col];
      float v00=fmaxf(c[mt][nt][0]+bb.x,0.f), v01=fmaxf(c[mt][nt][1]+bb.y,0.f);
      float v10=fmaxf(c[mt][nt][2]+bb.x,0.f), v11=fmaxf(c[mt][nt][3]+bb.y,0.f);
      *(unsigned*)&hh[r0*136+col] = pkh(v00,v01);
      *(unsigned*)&hl[r0*136+col] = pkh(v00-bf16f(v00), v01-bf16f(v01));
      *(unsigned*)&hh[(r0+8)*136+col] = pkh(v10,v11);
      *(unsigned*)&hl[(r0+8)*136+col] = pkh(v10-bf16f(v10), v11-bf16f(v11));
    }
  }
  __syncthreads();
  hmma_main<8,4,16,136>(hh, hl, &g_Wf[WF_ENC2 + n*8192], warp, lane, c);
#pragma unroll
  for (int mt=0;mt<4;mt++){
    long r0 = b0 + mt*16 + (lane>>2);
#pragma unroll
    for (int nt=0;nt<4;nt++){
      int col = (warp*4+nt)*8 + ((lane&3)<<1);
      float2 bb = *(const float2*)&b2[n*128 + col];
      *(float2*)&g_bufA[r0*640 + n*128 + col] =
          make_float2(c[mt][nt][0]+bb.x, c[mt][nt][1]+bb.y);
      *(float2*)&g_bufA[(r0+8)*640 + n*128 + col] =
          make_float2(c[mt][nt][2]+bb.x, c[mt][nt][3]+bb.y);
    }
  }
}

// --------------------------- GCN aggregation -------------------------------
__global__ void k_agg(const float* __restrict__ in, float* __restrict__ outb,
                      const float* __restrict__ ew,
                      const int* __restrict__ esrc, const int* __restrict__ edst){
  int idx = blockIdx.x*256 + threadIdx.x;      // BQ*32
  int b = idx>>5, c4 = (idx&31)<<2;
  float4 g0 = *(const float4*)&in[b*640 + 0*128 + c4];
  float4 g1 = *(const float4*)&in[b*640 + 1*128 + c4];
  float4 g2 = *(const float4*)&in[b*640 + 2*128 + c4];
  float4 g3 = *(const float4*)&in[b*640 + 3*128 + c4];
  float4 g4 = *(const float4*)&in[b*640 + 4*128 + c4];
  *(float4*)&outb[b*640 + c4] = g0;
#pragma unroll
  for (int v=1; v<5; v++){
    float4 a = (v==1)?g1:((v==2)?g2:((v==3)?g3:g4));
#pragma unroll
    for (int e=0;e<NE;e++){
      if (edst[e] == v){
        int s = esrc[e];
        float4 gs = (s==0)?g0:((s==1)?g1:((s==2)?g2:g3));
        float w = ew[b*NE+e];
        a.x += w*gs.x; a.y += w*gs.y; a.z += w*gs.z; a.w += w*gs.w;
      }
    }
    *(float4*)&outb[b*640 + v*128 + c4] = a;
  }
}

// ----------------------- mu/sig heads + KL ---------------------------------
__global__ __launch_bounds__(128) void k_musig(
    const float* __restrict__ mub, const float* __restrict__ sigb){
  __shared__ __align__(16) __nv_bfloat16 sh[64*136], sl[64*136];
  int t = threadIdx.x, lane = t&31, warp = t>>5;
  long b0 = (long)blockIdx.x*64;
  stage_split<128,136>(g_bufA + b0*128, 128, sh, sl, t);
  __syncthreads();
  float c[4][4][4];
  float kll = 0.f;
  hmma_main<8,4,16,136>(sh, sl, &g_Wf[WF_MU], warp, lane, c);
#pragma unroll
  for (int mt=0;mt<4;mt++){
    long r0 = b0 + mt*16 + (lane>>2);
#pragma unroll
    for (int nt=0;nt<4;nt++){
      int col = (warp*4+nt)*8 + ((lane&3)<<1);
      float2 bb = *(const float2*)&mub[col];
      float m00=c[mt][nt][0]+bb.x, m01=c[mt][nt][1]+bb.y;
      float m10=c[mt][nt][2]+bb.x, m11=c[mt][nt][3]+bb.y;
      *(float2*)&g_mean[r0*128 + col]     = make_float2(m00,m01);
      *(float2*)&g_mean[(r0+8)*128 + col] = make_float2(m10,m11);
      kll += m00*m00 + m01*m01 + m10*m10 + m11*m11;
    }
  }
  hmma_main<8,4,16,136>(sh, sl, &g_Wf[WF_SIG], warp, lane, c);
#pragma unroll
  for (int mt=0;mt<4;mt++)
#pragma unroll
    for (int nt=0;nt<4;nt++){
      int col = (warp*4+nt)*8 + ((lane&3)<<1);
      float2 bb = *(const float2*)&sigb[col];
#pragma unroll
      for (int i=0;i<4;i++){
        float sp = softplusf(c[mt][nt][i] + ((i&1)?bb.y:bb.x));
        float var = sp*sp;
        kll += var - logf(var + 1e-8f) - 1.f;
      }
    }
  BLOCK_REDUCE_TO(g_klpart, kll);
}

// ------------------------------ graph feat ---------------------------------
__global__ void k_gf(){
  int idx = blockIdx.x*256 + threadIdx.x;      // BQ*32
  int b = idx>>5, c4 = (idx&31)<<2;
  float4 s = *(const float4*)&g_mean[b*640 + c4];
#pragma unroll
  for (int v=1;v<5;v++){
    float4 m = *(const float4*)&g_mean[b*640 + v*128 + c4];
    s.x+=m.x; s.y+=m.y; s.z+=m.z; s.w+=m.w;
  }
  s.x*=0.2f; s.y*=0.2f; s.z*=0.2f; s.w*=0.2f;
  *(float4*)&g_gf[b*128 + c4] = s;
}

// ------------------------------ GRU gates ----------------------------------
__global__ void k_gates(int l, const float* __restrict__ hist,
    const float* __restrict__ bih, const float* __restrict__ bhh,
    float* __restrict__ hout){
  int idx = blockIdx.x*256 + threadIdx.x;      // BQ*32
  int b = idx>>5, h4 = (idx&31)<<2;
  float4 gir = *(const float4*)&g_gi[b*384 + h4];
  float4 giz = *(const float4*)&g_gi[b*384 + 128 + h4];
  float4 gin_= *(const float4*)&g_gi[b*384 + 256 + h4];
  float4 ghr = *(const float4*)&g_gh[b*384 + h4];
  float4 ghz = *(const float4*)&g_gh[b*384 + 128 + h4];
  float4 ghn = *(const float4*)&g_gh[b*384 + 256 + h4];
  float4 hp  = *(const float4*)&hist[l*BQ*128 + b*128 + h4];
  float4 bir = *(const float4*)&bih[l*384 + h4];
  float4 biz = *(const float4*)&bih[l*384 + 128 + h4];
  float4 bin_= *(const float4*)&bih[l*384 + 256 + h4];
  float4 bhr = *(const float4*)&bhh[l*384 + h4];
  float4 bhz = *(const float4*)&bhh[l*384 + 128 + h4];
  float4 bhn = *(const float4*)&bhh[l*384 + 256 + h4];
  float4 o;
  { float r=sigmf(gir.x+bir.x+ghr.x+bhr.x), z=sigmf(giz.x+biz.x+ghz.x+bhz.x);
    float nn=tanhf(gin_.x+bin_.x + r*(ghn.x+bhn.x)); o.x=(1.f-z)*nn+z*hp.x; }
  { float r=sigmf(gir.y+bir.y+ghr.y+bhr.y), z=sigmf(giz.y+biz.y+ghz.y+bhz.y);
    float nn=tanhf(gin_.y+bin_.y + r*(ghn.y+bhn.y)); o.y=(1.f-z)*nn+z*hp.y; }
  { float r=sigmf(gir.z+bir.z+ghr.z+bhr.z), z=sigmf(giz.z+biz.z+ghz.z+bhz.z);
    float nn=tanhf(gin_.z+bin_.z + r*(ghn.z+bhn.z)); o.z=(1.f-z)*nn+z*hp.z; }
  { float r=sigmf(gir.w+bir.w+ghr.w+bhr.w), z=sigmf(giz.w+biz.w+ghz.w+bhz.w);
    float nn=tanhf(gin_.w+bin_.w + r*(ghn.w+bhn.w)); o.w=(1.f-z)*nn+z*hp.w; }
  *(float4*)&hout[b*128 + h4] = o;
}

// --------------------- causal solve + parent_sum ---------------------------
__global__ __launch_bounds__(128) void k_causal(
    const float* __restrict__ ew, const float* __restrict__ cm,
    const int* __restrict__ esrc, const int* __restrict__ edst){
  int b = blockIdx.x, t = threadIdx.x;
  __shared__ float s_ew[NE], s_cm[NND*NND];
  __shared__ int s_src[NE], s_dst[NE];
  if (t < NE){ s_ew[t] = ew[b*NE + t]; s_src[t] = esrc[t]; s_dst[t] = edst[t]; }
  if (t < NND*NND) s_cm[t] = cm[t];
  __syncthreads();
  int base = b*NND*HDIM + t;
  float z[NND];
#pragma unroll
  for (int j=0;j<NND;j++) z[j] = g_mean[base + j*HDIM];
#pragma unroll
  for (int j=1;j<NND;j++){
    float add = 0.f;
#pragma unroll
    for (int e=0;e<NE;e++){
      if (s_dst[e] == j){
        int s = s_src[e];
        float zs = (s==0)?z[0]:((s==1)?z[1]:((s==2)?z[2]:z[3]));
        add += s_ew[e]*s_cm[s*NND + j]*zs;
      }
    }
    z[j] += add;
  }
#pragma unroll
  for (int j=0;j<NND;j++) g_z[base + j*HDIM] = z[j];
#pragma unroll
  for (int j=0;j<NND;j++){
    float ps = 0.f;
#pragma unroll
    for (int i=0;i<NND;i++)
      if (s_cm[i*NND + j] != 0.f) ps += z[i];
    g_ps[base + j*HDIM] = ps;
  }
}

// --------------------------- cm layer 2 + l_z ------------------------------
__global__ __launch_bounds__(128) void k_cm2(const float* __restrict__ b2){
  __shared__ __align__(16) __nv_bfloat16 sh[64*136], sl[64*136];
  int t = threadIdx.x, lane = t&31, warp = t>>5;
  long b0 = (long)blockIdx.x*64;
  stage_split<128,136>(g_bufB + b0*128, 128, sh, sl, t);
  __syncthreads();
  float c[4][4][4];
  hmma_main<8,4,16,136>(sh, sl, &g_Wf[WF_CM2], warp, lane, c);
  float lz = 0.f;
#pragma unroll
  for (int mt=0;mt<4;mt++){
    long r0 = b0 + mt*16 + (lane>>2);
#pragma unroll
    for (int nt=0;nt<4;nt++){
      int col = (warp*4+nt)*8 + ((lane&3)<<1);
      float2 bb = *(const float2*)&b2[col];
      float2 z0 = *(const float2*)&g_z[r0*128 + col];
      float2 z1 = *(const float2*)&g_z[(r0+8)*128 + col];
      float d0 = z0.x - (c[mt][nt][0]+bb.x);
      float d1 = z0.y - (c[mt][nt][1]+bb.y);
      float d2 = z1.x - (c[mt][nt][2]+bb.x);
      float d3 = z1.y - (c[mt][nt][3]+bb.y);
      lz += d0*d0 + d1*d1 + d2*d2 + d3*d3;
    }
  }
  BLOCK_REDUCE_TO(g_lzpart, lz);
}

// --------------------- decoder layer 2 + losses ----------------------------
__global__ __launch_bounds__(128) void k_dec2(
    const float* __restrict__ b2, const float* __restrict__ yt_g,
    float* __restrict__ out){
  __shared__ __align__(16) __nv_bfloat16 sh[64*136], sl[64*136];
  __shared__ float s_piw[4][32], s_kd[4][32], s_mn[4][32], s_mx[4][32];
  __shared__ float s_sc[3][4];
  float* s_out = (float*)sh;     // 64*66 floats, aliases sh after mainloop
  int t = threadIdx.x, lane = t&31, warp = t>>5;
  int n = blockIdx.y;
  long b0 = (long)blockIdx.x*64;
  stage_split<128,136>(g_d1 + b0*640 + n*128, 640, sh, sl, t);
  __syncthreads();
  float c[4][2][4];
  hmma_main<8,2,8,136>(sh, sl, &g_Wf[WF_DEC2 + n*4096], warp, lane, c);
  __syncthreads();   // everyone done reading sh before aliasing as s_out
#pragma unroll
  for (int mt=0;mt<4;mt++){
    int r = mt*16 + (lane>>2);
#pragma unroll
    for (int nt=0;nt<2;nt++){
      int col = warp*16 + nt*8 + ((lane&3)<<1);
      float2 bb = *(const float2*)&b2[n*64 + col];
      float v00=c[mt][nt][0]+bb.x, v01=c[mt][nt][1]+bb.y;
      float v10=c[mt][nt][2]+bb.x, v11=c[mt][nt][3]+bb.y;
      if (col >= 32){ v00=expf(v00); v01=expf(v01); v10=expf(v10); v11=expf(v11); }
      s_out[r*66+col]=v00;     s_out[r*66+col+1]=v01;
      s_out[(r+8)*66+col]=v10; s_out[(r+8)*66+col+1]=v11;
      long gb0, gb1;
      if (col < 32){
        gb0 = (b0+r)*160 + n*32 + col;
        gb1 = (b0+r+8)*160 + n*32 + col;
      } else {
        gb0 = (long)OFF_V + (b0+r)*160 + n*32 + col-32;
        gb1 = (long)OFF_V + (b0+r+8)*160 + n*32 + col-32;
      }
      *(float2*)&out[gb0] = make_float2(v00,v01);
      *(float2*)&out[gb1] = make_float2(v10,v11);
    }
  }
  __syncthreads();
  // loss phase: thread -> d = lane, rows = warp + 4i
  int d = lane;
  float ll=0.f, sq4=0.f, bce=0.f;
  float piw=0.f, kd=0.f, mn=1e30f, mx=-1e30f;
#pragma unroll
  for (int i=0;i<16;i++){
    int row = warp + 4*i;
    float ym = s_out[row*66 + d];
    float yv = s_out[row*66 + 32 + d];
    float yt = yt_g[(b0+row)*160 + n*32 + d];
    float vs = yv + 1e-6f;
    float df = yt - ym;
    ll += -0.5f*(df*df/vs + logf(6.2831853071795864f*vs));
    if (n < 4) sq4 += df*df;
    if (n == 4) bce += fmaxf(ym,0.f) - ym*yt + log1pf(expf(-fabsf(ym)));
    float s  = sqrtf(vs);
    float lo_ = ym - ZALPHA*s, up_ = ym + ZALPHA*s;
    float kf = (yt >= lo_ && yt <= up_) ? 1.f : 0.f;
    kd  += kf;
    piw += (up_-lo_)*kf;
    mn = fminf(mn, yt);
    mx = fmaxf(mx, yt);
  }
  ll  = warp_sum(ll);
  sq4 = warp_sum(sq4);
  bce = warp_sum(bce);
  if (lane == 0){ s_sc[0][warp]=ll; s_sc[1][warp]=sq4; s_sc[2][warp]=bce; }
  s_piw[warp][d]=piw; s_kd[warp][d]=kd; s_mn[warp][d]=mn; s_mx[warp][d]=mx;
  __syncthreads();
  int blk = blockIdx.y*gridDim.x + blockIdx.x;
  float* P = g_losspart + blk*132;
  if (t == 0){
    P[0] = (s_sc[0][0]+s_sc[0][1]) + (s_sc[0][2]+s_sc[0][3]);
    P[1] = (s_sc[1][0]+s_sc[1][1]) + (s_sc[1][2]+s_sc[1][3]);
    P[2] = (s_sc[2][0]+s_sc[2][1]) + (s_sc[2][2]+s_sc[2][3]);
    P[3] = 0.f;
  }
  if (t < 32){
    P[4+t]   = (s_piw[0][t]+s_piw[1][t]) + (s_piw[2][t]+s_piw[3][t]);
    P[36+t]  = (s_kd[0][t]+s_kd[1][t]) + (s_kd[2][t]+s_kd[3][t]);
    P[68+t]  = fminf(fminf(s_mn[0][t],s_mn[1][t]), fminf(s_mn[2][t],s_mn[3][t]));
    P[100+t] = fmaxf(fmaxf(s_mx[0][t],s_mx[1][t]), fmaxf(s_mx[2][t],s_mx[3][t]));
  }
}

// ---------------------- stage-1 reduce + final -----------------------------
__global__ void k_reduce1(){
  int col = blockIdx.x, t = threadIdx.x;
  bool ismin = (col >= 68 && col < 100);
  bool ismax = (col >= 100 && col < 132);
  float v = ismin ? 1e30f : (ismax ? -1e30f : 0.f);
  if (col < 132){
    for (int i=t; i<2560; i+=256){
      float x = g_losspart[i*132 + col];
      v = ismin ? fminf(v,x) : (ismax ? fmaxf(v,x) : v + x);
    }
  } else if (col == 132){
    for (int i=t; i<2560; i+=256) v += g_klpart[i];
  } else {
    for (int i=t; i<2560; i+=256) v += g_lzpart[i];
  }
  __shared__ float sm[256];
  sm[t] = v;
  __syncthreads();
  for (int s=128; s>0; s>>=1){
    if (t < s){
      float a = sm[t], b = sm[t+s];
      sm[t] = ismin ? fminf(a,b) : (ismax ? fmaxf(a,b) : a + b);
    }
    __syncthreads();
  }
  if (t == 0) g_facc[col] = sm[0];
}

__global__ void k_final(float* __restrict__ out){
  if (threadIdx.x != 0 || blockIdx.x != 0) return;
  float S_ll = g_facc[0], S_sq4 = g_facc[1], S_bce = g_facc[2];
  float kl = 0.5f*g_facc[132];
  float S_lz = g_facc[133];
  float mean_ll = S_ll / 5242880.0f;
  float elbo = kl/32768.0f - mean_ll;
  float l_reg = (S_sq4/32.0f) / (4.0f*32768.0f + 1e-6f);
  float l_cls = (S_bce/32.0f) / (32768.0f + 1e-6f);
  float l_rec = l_reg + l_cls;
  float Sk = 0.f, pin = 0.f;
  for (int d=0; d<32; d++){
    float kdv = g_facc[36+d];
    Sk += kdv;
    pin += g_facc[4+d] / (kdv + 1e-6f) / (g_facc[100+d] - g_facc[68+d] + 1e-6f);
  }
  float picp  = Sk / 5242880.0f;
  float pinaw = pin / 32.0f;
  float l_pi  = pinaw - sqrtf(5.0f)*picp;
  float l_z   = S_lz / 20971520.0f;
  float dag   = 0.0f;  // exact: diag((I+ac)^5)==1 for strictly-upper ac
  float total = powf(elbo*l_rec*l_pi*l_z*(dag + 1e-6f), 0.2f);
  out[OFF_LOSS+0] = total;
  out[OFF_LOSS+1] = elbo;
  out[OFF_LOSS+2] = l_rec;
  out[OFF_LOSS+3] = l_pi;
  out[OFF_LOSS+4] = l_z;
  out[OFF_LOSS+5] = dag;
}

// ------------------------------ launcher -----------------------------------
extern "C" void kernel_launch(void* const* d_in, const int* in_sizes, int n_in,
                              void* d_out, int out_size){
  const float* x       = (const float*)d_in[0];
  const float* y_true  = (const float*)d_in[1];
  const float* ew      = (const float*)d_in[2];
  const float* hist    = (const float*)d_in[3];
  const float* enc_W1  = (const float*)d_in[4];
  const float* enc_b1  = (const float*)d_in[5];
  const float* enc_W2  = (const float*)d_in[6];
  const float* enc_b2  = (const float*)d_in[7];
  const float* gcn_W   = (const float*)d_in[8];
  const float* gcn_b   = (const float*)d_in[9];
  const float* mu_W    = (const float*)d_in[10];
  const float* mu_b    = (const float*)d_in[11];
  const float* sig_W   = (const float*)d_in[12];
  const float* sig_b   = (const float*)d_in[13];
  const float* gru_Wih = (const float*)d_in[14];
  const float* gru_Whh = (const float*)d_in[15];
  const float* gru_bih = (const float*)d_in[16];
  const float* gru_bhh = (const float*)d_in[17];
  const float* cm      = (const float*)d_in[18];
  const float* cm_W1   = (const float*)d_in[19];
  const float* cm_b1   = (const float*)d_in[20];
  const float* cm_W2   = (const float*)d_in[21];
  const float* cm_b2   = (const float*)d_in[22];
  const float* dec_W1  = (const float*)d_in[23];
  const float* dec_b1  = (const float*)d_in[24];
  const float* dec_W2  = (const float*)d_in[25];
  const float* dec_b2  = (const float*)d_in[26];
  const int*   esrc    = (const int*)d_in[27];
  const int*   edst    = (const int*)d_in[28];
  float* out = (float*)d_out;

  uint2* wf;   cudaGetSymbolAddress((void**)&wf, g_Wf);
  float *bufA, *bufB, *ps, *zb, *d1b, *gfp, *gib, *ghb;
  cudaGetSymbolAddress((void**)&bufA, g_bufA);
  cudaGetSymbolAddress((void**)&bufB, g_bufB);
  cudaGetSymbolAddress((void**)&ps,   g_ps);
  cudaGetSymbolAddress((void**)&zb,   g_z);
  cudaGetSymbolAddress((void**)&d1b,  g_d1);
  cudaGetSymbolAddress((void**)&gfp,  g_gf);
  cudaGetSymbolAddress((void**)&gib,  g_gi);
  cudaGetSymbolAddress((void**)&ghb,  g_gh);

  // weight packing
  k_pack<<<(5*2048+255)/256,256>>>(enc_W1, wf+WF_ENC1, 32,128,5,4096,0);
  k_pack<<<(5*8192+255)/256,256>>>(enc_W2, wf+WF_ENC2,128,128,5,16384,0);
  k_pack<<<(2*8192+255)/256,256>>>(gcn_W,  wf+WF_GCN, 128,128,2,16384,0);
  k_pack<<<(8192+255)/256,256>>>(mu_W,   wf+WF_MU,  128,128,1,16384,0);
  k_pack<<<(8192+255)/256,256>>>(sig_W,  wf+WF_SIG, 128,128,1,16384,0);
  k_pack<<<(8192+255)/256,256>>>(cm_W1,  wf+WF_CM1, 128,128,1,16384,0);
  k_pack<<<(8192+255)/256,256>>>(cm_W2,  wf+WF_CM2, 128,128,1,16384,0);
  k_pack<<<(5*8192+255)/256,256>>>(dec_W1, wf+WF_DEC1,128,128,5,16384,0);
  k_pack<<<(5*4096+255)/256,256>>>(dec_W2, wf+WF_DEC2,128, 64,5, 8192,0);
  k_pack<<<(6*8192+255)/256,256>>>(gru_Wih, wf+WF_GI, 128,128,6,16384,1);
  k_pack<<<(6*8192+255)/256,256>>>(gru_Whh, wf+WF_GH, 128,128,6,16384,1);

  // encoder
  k_enc<<<dim3(BQ/64, NND), 128>>>(x, enc_b1, enc_b2);
  // GCN x2
  k_agg<<<BQ*32/256, 256>>>(bufA, bufB, ew, esrc, edst);
  k_gemm<1><<<2560, 128>>>(bufB,128,0, wf+WF_GCN,0, gcn_b,0, bufA,128,0);
  k_agg<<<BQ*32/256, 256>>>(bufA, bufB, ew, esrc, edst);
  k_gemm<1><<<2560, 128>>>(bufB,128,0, wf+WF_GCN+8192,0, gcn_b+128,0, bufA,128,0);
  // heads
  k_musig<<<2560, 128>>>(mu_b, sig_b);
  k_gf<<<BQ*32/256, 256>>>();
  // GRU
  k_gemm<0><<<dim3(BQ/64,3), 128>>>(gfp,128,0, wf+WF_GI,8192, nullptr,0, gib,384,128);
  k_gemm<0><<<dim3(BQ/64,3), 128>>>(hist,128,0, wf+WF_GH,8192, nullptr,0, ghb,384,128);
  k_gates<<<BQ*32/256, 256>>>(0, hist, gru_bih, gru_bhh, out + OFF_HID);
  k_gemm<0><<<dim3(BQ/64,3), 128>>>(out+OFF_HID,128,0, wf+WF_GI+24576,8192, nullptr,0, gib,384,128);
  k_gemm<0><<<dim3(BQ/64,3), 128>>>(hist+BQ*128,128,0, wf+WF_GH+24576,8192, nullptr,0, ghb,384,128);
  k_gates<<<BQ*32/256, 256>>>(1, hist, gru_bih, gru_bhh, out + OFF_HID + BQ*128);
  // causal + cm
  k_causal<<<BQ, 128>>>(ew, cm, esrc, edst);
  k_gemm<2><<<2560, 128>>>(ps,128,0, wf+WF_CM1,0, cm_b1,0, bufB,128,0);
  k_cm2<<<2560, 128>>>(cm_b2);
  // decoder
  k_gemm<2><<<dim3(BQ/64, NND), 128>>>(zb,640,128, wf+WF_DEC1,8192, dec_b1,128, d1b,640,128);
  k_dec2<<<dim3(BQ/64, NND), 128>>>(dec_b2, y_true, out);
  // reductions
  k_reduce1<<<134, 256>>>();
  k_final<<<1, 32>>>(out);
}

// round 6
// speedup vs baseline: 3.2028x; 1.0726x over previous
#include <cuda_runtime.h>
#include <cuda_bf16.h>
#include <math.h>

#define BQ   32768
#define NND  5
#define HDIM 128
#define NE   10

#define OFF_V    (BQ*NND*32)
#define OFF_HID  (2*BQ*NND*32)
#define OFF_LOSS (OFF_HID + 2*BQ*HDIM)

#define ZALPHA 1.959963984540054f

// fragment arena offsets (uint2 units)
#define WF_ENC1 0
#define WF_ENC2 10240
#define WF_GCN  51200
#define WF_MU   67584
#define WF_SIG  75776
#define WF_CM1  83968
#define WF_CM2  92160
#define WF_DEC1 100352
#define WF_DEC2 141312
#define WF_GI   161792
#define WF_GH   210944
#define WF_TOT  260096

// ----------------------------- device scratch -----------------------------
__device__ float g_bufA[BQ*NND*HDIM];
__device__ float g_bufB[BQ*NND*HDIM];
__device__ float g_mean[BQ*NND*HDIM];
__device__ float g_z  [BQ*NND*HDIM];
__device__ float g_ps [BQ*NND*HDIM];
__device__ uint2 g_Wf [WF_TOT];
__device__ float g_klpart[2560];
__device__ float g_lzpart[2560];
__device__ float g_losspart[2560*132];
__device__ float g_facc[134];

// ------------------------------- helpers ----------------------------------
__device__ __forceinline__ float warp_sum(float v){
#pragma unroll
  for (int o=16;o>0;o>>=1) v += __shfl_xor_sync(0xffffffffu, v, o);
  return v;
}
__device__ __forceinline__ float softplusf(float x){
  return fmaxf(x,0.f) + log1pf(expf(-fabsf(x)));
}
__device__ __forceinline__ float mishf(float x){ return x*tanhf(softplusf(x)); }
__device__ __forceinline__ float sigmf(float x){ return 1.f/(1.f+expf(-x)); }

#define BLOCK_REDUCE_TO(part, val)                                      \
  do {                                                                  \
    float _v = warp_sum(val);                                           \
    __shared__ float _sred[4];                                          \
    if ((threadIdx.x & 31) == 0) _sred[threadIdx.x >> 5] = _v;          \
    __syncthreads();                                                    \
    if (threadIdx.x == 0)                                               \
      part[blockIdx.x] = (_sred[0]+_sred[1]) + (_sred[2]+_sred[3]);     \
  } while (0)

__device__ __forceinline__ unsigned pkh(float x, float y){
  unsigned short a = __bfloat16_as_ushort(__float2bfloat16_rn(x));
  unsigned short b = __bfloat16_as_ushort(__float2bfloat16_rn(y));
  return ((unsigned)b<<16) | (unsigned)a;
}
__device__ __forceinline__ float bf16f(float x){
  return __bfloat162float(__float2bfloat16_rn(x));
}
__device__ __forceinline__ unsigned sptr(const void* p){
  return (unsigned)__cvta_generic_to_shared(p);
}
__device__ __forceinline__ void ldsm4(unsigned a, unsigned &r0, unsigned &r1,
                                      unsigned &r2, unsigned &r3){
  asm volatile("ldmatrix.sync.aligned.m8n8.x4.shared.b16 {%0,%1,%2,%3}, [%4];"
               : "=r"(r0),"=r"(r1),"=r"(r2),"=r"(r3) : "r"(a));
}
__device__ __forceinline__ void mma16816(float* c, const unsigned* a,
                                         unsigned b0, unsigned b1){
  asm volatile("mma.sync.aligned.m16n8k16.row.col.f32.bf16.bf16.f32 "
      "{%0,%1,%2,%3},{%4,%5,%6,%7},{%8,%9},{%0,%1,%2,%3};"
      : "+f"(c[0]),"+f"(c[1]),"+f"(c[2]),"+f"(c[3])
      : "r"(a[0]),"r"(a[1]),"r"(a[2]),"r"(a[3]),"r"(b0),"r"(b1));
}
// 3-term accumulate: AhBh + AlBh + AhBl
__device__ __forceinline__ void mma3(float* c, const unsigned* ah,
    const unsigned* al, uint2 bh, uint2 bl){
  mma16816(c, ah, bh.x, bh.y);
  mma16816(c, al, bh.x, bh.y);
  mma16816(c, ah, bl.x, bl.y);
}

__device__ __forceinline__ void split_st(float4 v, __nv_bfloat16* sh,
    __nv_bfloat16* sl, int off){
  *(uint2*)&sh[off] = make_uint2(pkh(v.x,v.y), pkh(v.z,v.w));
  *(uint2*)&sl[off] = make_uint2(pkh(v.x-bf16f(v.x), v.y-bf16f(v.y)),
                                 pkh(v.z-bf16f(v.z), v.w-bf16f(v.w)));
}

// stage 64 x KC fp32 -> split bf16 hi/lo smem (row stride LDA bf16)
template<int KC, int LDA, int NT_>
__device__ __forceinline__ void stage_split(const float* __restrict__ A, int arst,
    __nv_bfloat16* sh, __nv_bfloat16* sl, int t){
  const int C4 = KC/4;
  for (int f=t; f<64*C4; f+=NT_){
    int r = f/C4, c4 = (f%C4)*4;
    float4 v = *(const float4*)&A[(long)r*arst + c4];
    split_st(v, sh, sl, r*LDA+c4);
  }
}

// 3-term bf16 split mainloop: block M=64, warp covers NT n8-tiles
template<int KT, int NT, int NTOT, int LDA>
__device__ __forceinline__ void hmma_main(const __nv_bfloat16* sh,
    const __nv_bfloat16* sl, const uint2* __restrict__ Wf,
    int warp, int lane, float (&c)[4][NT][4]){
#pragma unroll
  for (int mt=0;mt<4;mt++)
#pragma unroll
    for (int nt=0;nt<NT;nt++)
#pragma unroll
      for (int i=0;i<4;i++) c[mt][nt][i] = 0.f;
  int sub = lane>>3;
  int m_off = ((sub&1)<<3) + (lane&7);
  int k_off = (sub>>1)<<3;
#pragma unroll 1
  for (int kt=0; kt<KT; kt++){
    uint2 bh[NT], bl[NT];
#pragma unroll
    for (int nt=0;nt<NT;nt++){
      const uint2* wp = Wf + (((kt*NTOT + warp*NT + nt)*2)<<5) + lane;
      bh[nt] = wp[0];
      bl[nt] = wp[32];
    }
    unsigned ah[4][4], al[4][4];
#pragma unroll
    for (int mt=0;mt<4;mt++){
      int ro = (mt*16 + m_off)*LDA + kt*16 + k_off;
      ldsm4(sptr(&sh[ro]), ah[mt][0],ah[mt][1],ah[mt][2],ah[mt][3]);
      ldsm4(sptr(&sl[ro]), al[mt][0],al[mt][1],al[mt][2],al[mt][3]);
    }
#pragma unroll
    for (int mt=0;mt<4;mt++)
#pragma unroll
      for (int nt=0;nt<NT;nt++)
        mma3(c[mt][nt], ah[mt], al[mt], bh[nt], bl[nt]);
  }
}

// --------------------------- single pack kernel ----------------------------
__global__ void k_packall(
    const float* __restrict__ encW1, const float* __restrict__ encW2,
    const float* __restrict__ gcnW,  const float* __restrict__ muW,
    const float* __restrict__ sigW,  const float* __restrict__ cmW1,
    const float* __restrict__ cmW2,  const float* __restrict__ decW1,
    const float* __restrict__ decW2, const float* __restrict__ giW,
    const float* __restrict__ ghW){
  int idx = blockIdx.x*256 + threadIdx.x;
  if (idx >= WF_TOT) return;
  const float* src; int K, N, trans, base, per, mst;
  if      (idx < WF_ENC2){ src=encW1; K=32; N=128; trans=0; base=WF_ENC1; per=2048; mst=4096; }
  else if (idx < WF_GCN ){ src=encW2; K=128;N=128; trans=0; base=WF_ENC2; per=8192; mst=16384;}
  else if (idx < WF_MU  ){ src=gcnW;  K=128;N=128; trans=0; base=WF_GCN;  per=8192; mst=16384;}
  else if (idx < WF_SIG ){ src=muW;   K=128;N=128; trans=0; base=WF_MU;   per=8192; mst=16384;}
  else if (idx < WF_CM1 ){ src=sigW;  K=128;N=128; trans=0; base=WF_SIG;  per=8192; mst=16384;}
  else if (idx < WF_CM2 ){ src=cmW1;  K=128;N=128; trans=0; base=WF_CM1;  per=8192; mst=16384;}
  else if (idx < WF_DEC1){ src=cmW2;  K=128;N=128; trans=0; base=WF_CM2;  per=8192; mst=16384;}
  else if (idx < WF_DEC2){ src=decW1; K=128;N=128; trans=0; base=WF_DEC1; per=8192; mst=16384;}
  else if (idx < WF_GI  ){ src=decW2; K=128;N=64;  trans=0; base=WF_DEC2; per=4096; mst=8192; }
  else if (idx < WF_GH  ){ src=giW;   K=128;N=128; trans=1; base=WF_GI;   per=8192; mst=16384;}
  else                   { src=ghW;   K=128;N=128; trans=1; base=WF_GH;   per=8192; mst=16384;}
  int rr = idx - base;
  int m = rr / per, r = rr % per;
  int lane = r & 31, term = (r>>5)&1;
  int n8 = (r>>6) % (N>>3);
  int kt = (r>>6) / (N>>3);
  int n = n8*8 + (lane>>2);
  int k0 = kt*16 + ((lane&3)<<1);
  const float* S = src + (long)m*mst;
  float w0,w1,w2,w3;
  if (trans){
    w0=S[n*K+k0]; w1=S[n*K+k0+1]; w2=S[n*K+k0+8]; w3=S[n*K+k0+9];
  } else {
    w0=S[k0*N+n]; w1=S[(k0+1)*N+n]; w2=S[(k0+8)*N+n]; w3=S[(k0+9)*N+n];
  }
  uint2 o;
  if (term==0){ o = make_uint2(pkh(w0,w1), pkh(w2,w3)); }
  else {
    o = make_uint2(pkh(w0-bf16f(w0), w1-bf16f(w1)),
                   pkh(w2-bf16f(w2), w3-bf16f(w3)));
  }
  g_Wf[idx] = o;
}

// ------------------------------ encoder ------------------------------------
__global__ __launch_bounds__(128) void k_enc(
    const float* __restrict__ x, const float* __restrict__ b1,
    const float* __restrict__ b2){
  __shared__ __align__(16) __nv_bfloat16 xh[64*40], xl[64*40];
  __shared__ __align__(16) __nv_bfloat16 hh[64*136], hl[64*136];
  int t = threadIdx.x, lane = t&31, warp = t>>5;
  int n = blockIdx.y;
  long b0 = (long)blockIdx.x*64;
  stage_split<32,40,128>(x + b0*160 + n*32, 160, xh, xl, t);
  __syncthreads();
  float c[4][4][4];
  hmma_main<2,4,16,40>(xh, xl, &g_Wf[WF_ENC1 + n*2048], warp, lane, c);
#pragma unroll
  for (int mt=0;mt<4;mt++){
    int r0 = mt*16 + (lane>>2);
#pragma unroll
    for (int nt=0;nt<4;nt++){
      int col = (warp*4+nt)*8 + ((lane&3)<<1);
      float2 bb = *(const float2*)&b1[n*128 + col];
      float v00=fmaxf(c[mt][nt][0]+bb.x,0.f), v01=fmaxf(c[mt][nt][1]+bb.y,0.f);
      float v10=fmaxf(c[mt][nt][2]+bb.x,0.f), v11=fmaxf(c[mt][nt][3]+bb.y,0.f);
      *(unsigned*)&hh[r0*136+col] = pkh(v00,v01);
      *(unsigned*)&hl[r0*136+col] = pkh(v00-bf16f(v00), v01-bf16f(v01));
      *(unsigned*)&hh[(r0+8)*136+col] = pkh(v10,v11);
      *(unsigned*)&hl[(r0+8)*136+col] = pkh(v10-bf16f(v10), v11-bf16f(v11));
    }
  }
  __syncthreads();
  hmma_main<8,4,16,136>(hh, hl, &g_Wf[WF_ENC2 + n*8192], warp, lane, c);
#pragma unroll
  for (int mt=0;mt<4;mt++){
    long r0 = b0 + mt*16 + (lane>>2);
#pragma unroll
    for (int nt=0;nt<4;nt++){
      int col = (warp*4+nt)*8 + ((lane&3)<<1);
      float2 bb = *(const float2*)&b2[n*128 + col];
      *(float2*)&g_bufA[r0*640 + n*128 + col] =
          make_float2(c[mt][nt][0]+bb.x, c[mt][nt][1]+bb.y);
      *(float2*)&g_bufA[(r0+8)*640 + n*128 + col] =
          make_float2(c[mt][nt][2]+bb.x, c[mt][nt][3]+bb.y);
    }
  }
}

// ------------------- GCN: fused aggregation + GEMM -------------------------
__global__ __launch_bounds__(128) void k_gcn(
    int l, const float* __restrict__ ew,
    const int* __restrict__ esrc, const int* __restrict__ edst,
    const float* __restrict__ bias){
  __shared__ __align__(16) __nv_bfloat16 sh[64*136], sl[64*136];
  __shared__ int s_src[NE], s_dst[NE];
  int t = threadIdx.x, lane = t&31, warp = t>>5;
  const float* gin  = (l==0) ? g_bufA : g_bufB;
  float*       gout = (l==0) ? g_bufB : g_bufA;
  long b0 = (long)blockIdx.x*64;
  if (t < NE){ s_src[t] = esrc[t]; s_dst[t] = edst[t]; }
  __syncthreads();
  // stage with on-the-fly aggregation
  for (int f=t; f<64*32; f+=128){
    int r = f>>5, c4 = (f&31)<<2;
    long R = b0 + r;
    int b = (int)(R/5), v = (int)(R - 5l*b);
    const float* row = gin + (long)b*640;
    float4 a = *(const float4*)&row[v*128 + c4];
#pragma unroll
    for (int e=0;e<NE;e++){
      if (s_dst[e] == v){
        float w = __ldg(&ew[b*NE + e]);
        float4 g = *(const float4*)&row[s_src[e]*128 + c4];
        a.x += w*g.x; a.y += w*g.y; a.z += w*g.z; a.w += w*g.w;
      }
    }
    split_st(a, sh, sl, r*136+c4);
  }
  __syncthreads();
  float c[4][4][4];
  hmma_main<8,4,16,136>(sh, sl, &g_Wf[WF_GCN + l*8192], warp, lane, c);
#pragma unroll
  for (int mt=0;mt<4;mt++){
    long r0 = b0 + mt*16 + (lane>>2);
#pragma unroll
    for (int nt=0;nt<4;nt++){
      int col = (warp*4+nt)*8 + ((lane&3)<<1);
      float2 bb = *(const float2*)&bias[l*128 + col];
      *(float2*)&gout[r0*128 + col] = make_float2(
          fmaxf(c[mt][nt][0]+bb.x,0.f), fmaxf(c[mt][nt][1]+bb.y,0.f));
      *(float2*)&gout[(r0+8)*128 + col] = make_float2(
          fmaxf(c[mt][nt][2]+bb.x,0.f), fmaxf(c[mt][nt][3]+bb.y,0.f));
    }
  }
}

// ----------------------- mu/sig heads + KL ---------------------------------
__global__ __launch_bounds__(128) void k_musig(
    const float* __restrict__ mub, const float* __restrict__ sigb){
  __shared__ __align__(16) __nv_bfloat16 sh[64*136], sl[64*136];
  int t = threadIdx.x, lane = t&31, warp = t>>5;
  long b0 = (long)blockIdx.x*64;
  stage_split<128,136,128>(g_bufA + b0*128, 128, sh, sl, t);
  __syncthreads();
  float c[4][4][4];
  float kll = 0.f;
  hmma_main<8,4,16,136>(sh, sl, &g_Wf[WF_MU], warp, lane, c);
#pragma unroll
  for (int mt=0;mt<4;mt++){
    long r0 = b0 + mt*16 + (lane>>2);
#pragma unroll
    for (int nt=0;nt<4;nt++){
      int col = (warp*4+nt)*8 + ((lane&3)<<1);
      float2 bb = *(const float2*)&mub[col];
      float m00=c[mt][nt][0]+bb.x, m01=c[mt][nt][1]+bb.y;
      float m10=c[mt][nt][2]+bb.x, m11=c[mt][nt][3]+bb.y;
      *(float2*)&g_mean[r0*128 + col]     = make_float2(m00,m01);
      *(float2*)&g_mean[(r0+8)*128 + col] = make_float2(m10,m11);
      kll += m00*m00 + m01*m01 + m10*m10 + m11*m11;
    }
  }
  hmma_main<8,4,16,136>(sh, sl, &g_Wf[WF_SIG], warp, lane, c);
#pragma unroll
  for (int mt=0;mt<4;mt++)
#pragma unroll
    for (int nt=0;nt<4;nt++){
      int col = (warp*4+nt)*8 + ((lane&3)<<1);
      float2 bb = *(const float2*)&sigb[col];
#pragma unroll
      for (int i=0;i<4;i++){
        float sp = softplusf(c[mt][nt][i] + ((i&1)?bb.y:bb.x));
        float var = sp*sp;
        kll += var - logf(var + 1e-8f) - 1.f;
      }
    }
  BLOCK_REDUCE_TO(g_klpart, kll);
}

// ------------- GRU: fused dual-GEMM + gates (one kernel per layer) ---------
__global__ __launch_bounds__(256) void k_gru(
    int l, const float* __restrict__ xin, const float* __restrict__ hist,
    const float* __restrict__ bih, const float* __restrict__ bhh,
    float* __restrict__ hout){
  __shared__ __align__(16) __nv_bfloat16 xh[32*136], xl[32*136];
  __shared__ __align__(16) __nv_bfloat16 hhs[32*136], hls[32*136];
  int t = threadIdx.x, lane = t&31, warp = t>>5;   // 8 warps
  long b0 = (long)blockIdx.x*32;
  // stage x (or graph_feat = mean over nodes) and hidden
  for (int f=t; f<32*32; f+=256){
    int r = f>>5, c4 = (f&31)<<2;
    long b = b0 + r;
    float4 v;
    if (xin){
      v = *(const float4*)&xin[b*128 + c4];
    } else {
      v = *(const float4*)&g_mean[b*640 + c4];
#pragma unroll
      for (int vv=1; vv<5; vv++){
        float4 m = *(const float4*)&g_mean[b*640 + vv*128 + c4];
        v.x+=m.x; v.y+=m.y; v.z+=m.z; v.w+=m.w;
      }
      v.x*=0.2f; v.y*=0.2f; v.z*=0.2f; v.w*=0.2f;
    }
    split_st(v, xh, xl, r*136+c4);
    float4 hv = *(const float4*)&hist[((long)l*BQ + b)*128 + c4];
    split_st(hv, hhs, hls, r*136+c4);
  }
  __syncthreads();
  float cr[2][2][4], cz[2][2][4], cin[2][2][4], chn[2][2][4];
#pragma unroll
  for (int mt=0;mt<2;mt++)
#pragma unroll
    for (int nt=0;nt<2;nt++)
#pragma unroll
      for (int i=0;i<4;i++){ cr[mt][nt][i]=0.f; cz[mt][nt][i]=0.f;
                             cin[mt][nt][i]=0.f; chn[mt][nt][i]=0.f; }
  int sub = lane>>3;
  int m_off = ((sub&1)<<3) + (lane&7);
  int k_off = (sub>>1)<<3;
  const uint2* Wi = &g_Wf[WF_GI + l*3*8192];
  const uint2* Wh = &g_Wf[WF_GH + l*3*8192];
#pragma unroll 1
  for (int kt=0; kt<8; kt++){
    unsigned axh[2][4], axl[2][4], ahh[2][4], ahl[2][4];
#pragma unroll
    for (int mt=0;mt<2;mt++){
      int ro = (mt*16 + m_off)*136 + kt*16 + k_off;
      ldsm4(sptr(&xh[ro]),  axh[mt][0],axh[mt][1],axh[mt][2],axh[mt][3]);
      ldsm4(sptr(&xl[ro]),  axl[mt][0],axl[mt][1],axl[mt][2],axl[mt][3]);
      ldsm4(sptr(&hhs[ro]), ahh[mt][0],ahh[mt][1],ahh[mt][2],ahh[mt][3]);
      ldsm4(sptr(&hls[ro]), ahl[mt][0],ahl[mt][1],ahl[mt][2],ahl[mt][3]);
    }
#pragma unroll
    for (int nt=0;nt<2;nt++){
      int fo = (((kt*16 + warp*2 + nt)*2)<<5) + lane;
      // r gate (gi + gh into same acc)
      { uint2 bh=Wi[fo], bl=Wi[fo+32];
        uint2 ch=Wh[fo], cl=Wh[fo+32];
#pragma unroll
        for (int mt=0;mt<2;mt++){
          mma3(cr[mt][nt], axh[mt], axl[mt], bh, bl);
          mma3(cr[mt][nt], ahh[mt], ahl[mt], ch, cl);
        } }
      // z gate
      { uint2 bh=Wi[8192+fo], bl=Wi[8192+fo+32];
        uint2 ch=Wh[8192+fo], cl=Wh[8192+fo+32];
#pragma unroll
        for (int mt=0;mt<2;mt++){
          mma3(cz[mt][nt], axh[mt], axl[mt], bh, bl);
          mma3(cz[mt][nt], ahh[mt], ahl[mt], ch, cl);
        } }
      // n gate (separate accs)
      { uint2 bh=Wi[16384+fo], bl=Wi[16384+fo+32];
        uint2 ch=Wh[16384+fo], cl=Wh[16384+fo+32];
#pragma unroll
        for (int mt=0;mt<2;mt++){
          mma3(cin[mt][nt], axh[mt], axl[mt], bh, bl);
          mma3(chn[mt][nt], ahh[mt], ahl[mt], ch, cl);
        } }
    }
  }
  // gates epilogue
#pragma unroll
  for (int mt=0;mt<2;mt++){
    long gb = b0 + mt*16 + (lane>>2);
#pragma unroll
    for (int nt=0;nt<2;nt++){
      int col = warp*16 + nt*8 + ((lane&3)<<1);
      float2 bir = *(const float2*)&bih[l*384 + col];
      float2 biz = *(const float2*)&bih[l*384 + 128 + col];
      float2 bin_= *(const float2*)&bih[l*384 + 256 + col];
      float2 bhr = *(const float2*)&bhh[l*384 + col];
      float2 bhz = *(const float2*)&bhh[l*384 + 128 + col];
      float2 bhn = *(const float2*)&bhh[l*384 + 256 + col];
      float2 hp0 = *(const float2*)&hist[((long)l*BQ + gb)*128 + col];
      float2 hp1 = *(const float2*)&hist[((long)l*BQ + gb + 8)*128 + col];
      float r0=sigmf(cr[mt][nt][0]+bir.x+bhr.x);
      float r1=sigmf(cr[mt][nt][1]+bir.y+bhr.y);
      float r2=sigmf(cr[mt][nt][2]+bir.x+bhr.x);
      float r3=sigmf(cr[mt][nt][3]+bir.y+bhr.y);
      float z0=sigmf(cz[mt][nt][0]+biz.x+bhz.x);
      float z1=sigmf(cz[mt][nt][1]+biz.y+bhz.y);
      float z2=sigmf(cz[mt][nt][2]+biz.x+bhz.x);
      float z3=sigmf(cz[mt][nt][3]+biz.y+bhz.y);
      float n0=tanhf(cin[mt][nt][0]+bin_.x + r0*(chn[mt][nt][0]+bhn.x));
      float n1=tanhf(cin[mt][nt][1]+bin_.y + r1*(chn[mt][nt][1]+bhn.y));
      float n2=tanhf(cin[mt][nt][2]+bin_.x + r2*(chn[mt][nt][2]+bhn.x));
      float n3=tanhf(cin[mt][nt][3]+bin_.y + r3*(chn[mt][nt][3]+bhn.y));
      *(float2*)&hout[gb*128 + col] =
          make_float2((1.f-z0)*n0 + z0*hp0.x, (1.f-z1)*n1 + z1*hp0.y);
      *(float2*)&hout[(gb+8)*128 + col] =
          make_float2((1.f-z2)*n2 + z2*hp1.x, (1.f-z3)*n3 + z3*hp1.y);
    }
  }
}

// --------------------- causal solve + parent_sum ---------------------------
__global__ __launch_bounds__(128) void k_causal(
    const float* __restrict__ ew, const float* __restrict__ cm,
    const int* __restrict__ esrc, const int* __restrict__ edst){
  int b = blockIdx.x, t = threadIdx.x;
  __shared__ float s_ew[NE], s_cm[NND*NND];
  __shared__ int s_src[NE], s_dst[NE];
  if (t < NE){ s_ew[t] = ew[b*NE + t]; s_src[t] = esrc[t]; s_dst[t] = edst[t]; }
  if (t < NND*NND) s_cm[t] = cm[t];
  __syncthreads();
  int base = b*NND*HDIM + t;
  float z[NND];
#pragma unroll
  for (int j=0;j<NND;j++) z[j] = g_mean[base + j*HDIM];
#pragma unroll
  for (int j=1;j<NND;j++){
    float add = 0.f;
#pragma unroll
    for (int e=0;e<NE;e++){
      if (s_dst[e] == j){
        int s = s_src[e];
        float zs = (s==0)?z[0]:((s==1)?z[1]:((s==2)?z[2]:z[3]));
        add += s_ew[e]*s_cm[s*NND + j]*zs;
      }
    }
    z[j] += add;
  }
#pragma unroll
  for (int j=0;j<NND;j++) g_z[base + j*HDIM] = z[j];
#pragma unroll
  for (int j=0;j<NND;j++){
    float ps = 0.f;
#pragma unroll
    for (int i=0;i<NND;i++)
      if (s_cm[i*NND + j] != 0.f) ps += z[i];
    g_ps[base + j*HDIM] = ps;
  }
}

// ------------------- cm MLP fused (2 GEMMs) + l_z --------------------------
__global__ __launch_bounds__(128) void k_cm(
    const float* __restrict__ b1, const float* __restrict__ b2){
  __shared__ __align__(16) __nv_bfloat16 sh[64*136], sl[64*136];
  int t = threadIdx.x, lane = t&31, warp = t>>5;
  long b0 = (long)blockIdx.x*64;
  stage_split<128,136,128>(g_ps + b0*128, 128, sh, sl, t);
  __syncthreads();
  float c[4][4][4];
  hmma_main<8,4,16,136>(sh, sl, &g_Wf[WF_CM1], warp, lane, c);
  __syncthreads();   // all reads of sh/sl done before overwrite
#pragma unroll
  for (int mt=0;mt<4;mt++){
    int r0 = mt*16 + (lane>>2);
#pragma unroll
    for (int nt=0;nt<4;nt++){
      int col = (warp*4+nt)*8 + ((lane&3)<<1);
      float2 bb = *(const float2*)&b1[col];
      float v00=mishf(c[mt][nt][0]+bb.x), v01=mishf(c[mt][nt][1]+bb.y);
      float v10=mishf(c[mt][nt][2]+bb.x), v11=mishf(c[mt][nt][3]+bb.y);
      *(unsigned*)&sh[r0*136+col] = pkh(v00,v01);
      *(unsigned*)&sl[r0*136+col] = pkh(v00-bf16f(v00), v01-bf16f(v01));
      *(unsigned*)&sh[(r0+8)*136+col] = pkh(v10,v11);
      *(unsigned*)&sl[(r0+8)*136+col] = pkh(v10-bf16f(v10), v11-bf16f(v11));
    }
  }
  __syncthreads();
  hmma_main<8,4,16,136>(sh, sl, &g_Wf[WF_CM2], warp, lane, c);
  float lz = 0.f;
#pragma unroll
  for (int mt=0;mt<4;mt++){
    long r0 = b0 + mt*16 + (lane>>2);
#pragma unroll
    for (int nt=0;nt<4;nt++){
      int col = (warp*4+nt)*8 + ((lane&3)<<1);
      float2 bb = *(const float2*)&b2[col];
      float2 z0 = *(const float2*)&g_z[r0*128 + col];
      float2 z1 = *(const float2*)&g_z[(r0+8)*128 + col];
      float d0 = z0.x - (c[mt][nt][0]+bb.x);
      float d1 = z0.y - (c[mt][nt][1]+bb.y);
      float d2 = z1.x - (c[mt][nt][2]+bb.x);
      float d3 = z1.y - (c[mt][nt][3]+bb.y);
      lz += d0*d0 + d1*d1 + d2*d2 + d3*d3;
    }
  }
  BLOCK_REDUCE_TO(g_lzpart, lz);
}

// ----------------- decoder fused (2 GEMMs) + losses ------------------------
__global__ __launch_bounds__(128) void k_dec(
    const float* __restrict__ b1, const float* __restrict__ b2,
    const float* __restrict__ yt_g, float* __restrict__ out){
  __shared__ __align__(16) __nv_bfloat16 sh[64*136], sl[64*136];
  __shared__ float s_piw[4][32], s_kd[4][32], s_mn[4][32], s_mx[4][32];
  __shared__ float s_sc[3][4];
  float* s_out = (float*)sh;     // aliases sh after GEMM2
  int t = threadIdx.x, lane = t&31, warp = t>>5;
  int n = blockIdx.y;
  long b0 = (long)blockIdx.x*64;
  stage_split<128,136,128>(g_z + b0*640 + n*128, 640, sh, sl, t);
  __syncthreads();
  float c[4][4][4];
  hmma_main<8,4,16,136>(sh, sl, &g_Wf[WF_DEC1 + n*8192], warp, lane, c);
  __syncthreads();
#pragma unroll
  for (int mt=0;mt<4;mt++){
    int r0 = mt*16 + (lane>>2);
#pragma unroll
    for (int nt=0;nt<4;nt++){
      int col = (warp*4+nt)*8 + ((lane&3)<<1);
      float2 bb = *(const float2*)&b1[n*128 + col];
      float v00=mishf(c[mt][nt][0]+bb.x), v01=mishf(c[mt][nt][1]+bb.y);
      float v10=mishf(c[mt][nt][2]+bb.x), v11=mishf(c[mt][nt][3]+bb.y);
      *(unsigned*)&sh[r0*136+col] = pkh(v00,v01);
      *(unsigned*)&sl[r0*136+col] = pkh(v00-bf16f(v00), v01-bf16f(v01));
      *(unsigned*)&sh[(r0+8)*136+col] = pkh(v10,v11);
      *(unsigned*)&sl[(r0+8)*136+col] = pkh(v10-bf16f(v10), v11-bf16f(v11));
    }
  }
  __syncthreads();
  float c2[4][2][4];
  hmma_main<8,2,8,136>(sh, sl, &g_Wf[WF_DEC2 + n*4096], warp, lane, c2);
  __syncthreads();   // all reads of sh done before aliasing as s_out
#pragma unroll
  for (int mt=0;mt<4;mt++){
    int r = mt*16 + (lane>>2);
#pragma unroll
    for (int nt=0;nt<2;nt++){
      int col = warp*16 + nt*8 + ((lane&3)<<1);
      float2 bb = *(const float2*)&b2[n*64 + col];
      float v00=c2[mt][nt][0]+bb.x, v01=c2[mt][nt][1]+bb.y;
      float v10=c2[mt][nt][2]+bb.x, v11=c2[mt][nt][3]+bb.y;
      if (col >= 32){ v00=expf(v00); v01=expf(v01); v10=expf(v10); v11=expf(v11); }
      s_out[r*66+col]=v00;     s_out[r*66+col+1]=v01;
      s_out[(r+8)*66+col]=v10; s_out[(r+8)*66+col+1]=v11;
      long gb0, gb1;
      if (col < 32){
        gb0 = (b0+r)*160 + n*32 + col;
        gb1 = (b0+r+8)*160 + n*32 + col;
      } else {
        gb0 = (long)OFF_V + (b0+r)*160 + n*32 + col-32;
        gb1 = (long)OFF_V + (b0+r+8)*160 + n*32 + col-32;
      }
      *(float2*)&out[gb0] = make_float2(v00,v01);
      *(float2*)&out[gb1] = make_float2(v10,v11);
    }
  }
  __syncthreads();
  int d = lane;
  float ll=0.f, sq4=0.f, bce=0.f;
  float piw=0.f, kd=0.f, mn=1e30f, mx=-1e30f;
#pragma unroll
  for (int i=0;i<16;i++){
    int row = warp + 4*i;
    float ym = s_out[row*66 + d];
    float yv = s_out[row*66 + 32 + d];
    float yt = yt_g[(b0+row)*160 + n*32 + d];
    float vs = yv + 1e-6f;
    float df = yt - ym;
    ll += -0.5f*(df*df/vs + logf(6.2831853071795864f*vs));
    if (n < 4) sq4 += df*df;
    if (n == 4) bce += fmaxf(ym,0.f) - ym*yt + log1pf(expf(-fabsf(ym)));
    float s  = sqrtf(vs);
    float lo_ = ym - ZALPHA*s, up_ = ym + ZALPHA*s;
    float kf = (yt >= lo_ && yt <= up_) ? 1.f : 0.f;
    kd  += kf;
    piw += (up_-lo_)*kf;
    mn = fminf(mn, yt);
    mx = fmaxf(mx, yt);
  }
  ll  = warp_sum(ll);
  sq4 = warp_sum(sq4);
  bce = warp_sum(bce);
  if (lane == 0){ s_sc[0][warp]=ll; s_sc[1][warp]=sq4; s_sc[2][warp]=bce; }
  s_piw[warp][d]=piw; s_kd[warp][d]=kd; s_mn[warp][d]=mn; s_mx[warp][d]=mx;
  __syncthreads();
  int blk = blockIdx.y*gridDim.x + blockIdx.x;
  float* P = g_losspart + blk*132;
  if (t == 0){
    P[0] = (s_sc[0][0]+s_sc[0][1]) + (s_sc[0][2]+s_sc[0][3]);
    P[1] = (s_sc[1][0]+s_sc[1][1]) + (s_sc[1][2]+s_sc[1][3]);
    P[2] = (s_sc[2][0]+s_sc[2][1]) + (s_sc[2][2]+s_sc[2][3]);
    P[3] = 0.f;
  }
  if (t < 32){
    P[4+t]   = (s_piw[0][t]+s_piw[1][t]) + (s_piw[2][t]+s_piw[3][t]);
    P[36+t]  = (s_kd[0][t]+s_kd[1][t]) + (s_kd[2][t]+s_kd[3][t]);
    P[68+t]  = fminf(fminf(s_mn[0][t],s_mn[1][t]), fminf(s_mn[2][t],s_mn[3][t]));
    P[100+t] = fmaxf(fmaxf(s_mx[0][t],s_mx[1][t]), fmaxf(s_mx[2][t],s_mx[3][t]));
  }
}

// ---------------------- stage-1 reduce + final -----------------------------
__global__ void k_reduce1(){
  int col = blockIdx.x, t = threadIdx.x;
  bool ismin = (col >= 68 && col < 100);
  bool ismax = (col >= 100 && col < 132);
  float v = ismin ? 1e30f : (ismax ? -1e30f : 0.f);
  if (col < 132){
    for (int i=t; i<2560; i+=256){
      float x = g_losspart[i*132 + col];
      v = ismin ? fminf(v,x) : (ismax ? fmaxf(v,x) : v + x);
    }
  } else if (col == 132){
    for (int i=t; i<2560; i+=256) v += g_klpart[i];
  } else {
    for (int i=t; i<2560; i+=256) v += g_lzpart[i];
  }
  __shared__ float sm[256];
  sm[t] = v;
  __syncthreads();
  for (int s=128; s>0; s>>=1){
    if (t < s){
      float a = sm[t], b = sm[t+s];
      sm[t] = ismin ? fminf(a,b) : (ismax ? fmaxf(a,b) : a + b);
    }
    __syncthreads();
  }
  if (t == 0) g_facc[col] = sm[0];
}

__global__ void k_final(float* __restrict__ out){
  if (threadIdx.x != 0 || blockIdx.x != 0) return;
  float S_ll = g_facc[0], S_sq4 = g_facc[1], S_bce = g_facc[2];
  float kl = 0.5f*g_facc[132];
  float S_lz = g_facc[133];
  float mean_ll = S_ll / 5242880.0f;
  float elbo = kl/32768.0f - mean_ll;
  float l_reg = (S_sq4/32.0f) / (4.0f*32768.0f + 1e-6f);
  float l_cls = (S_bce/32.0f) / (32768.0f + 1e-6f);
  float l_rec = l_reg + l_cls;
  float Sk = 0.f, pin = 0.f;
  for (int d=0; d<32; d++){
    float kdv = g_facc[36+d];
    Sk += kdv;
    pin += g_facc[4+d] / (kdv + 1e-6f) / (g_facc[100+d] - g_facc[68+d] + 1e-6f);
  }
  float picp  = Sk / 5242880.0f;
  float pinaw = pin / 32.0f;
  float l_pi  = pinaw - sqrtf(5.0f)*picp;
  float l_z   = S_lz / 20971520.0f;
  float dag   = 0.0f;  // exact: diag((I+ac)^5)==1 for strictly-upper ac
  float total = powf(elbo*l_rec*l_pi*l_z*(dag + 1e-6f), 0.2f);
  out[OFF_LOSS+0] = total;
  out[OFF_LOSS+1] = elbo;
  out[OFF_LOSS+2] = l_rec;
  out[OFF_LOSS+3] = l_pi;
  out[OFF_LOSS+4] = l_z;
  out[OFF_LOSS+5] = dag;
}

// ------------------------------ launcher -----------------------------------
extern "C" void kernel_launch(void* const* d_in, const int* in_sizes, int n_in,
                              void* d_out, int out_size){
  const float* x       = (const float*)d_in[0];
  const float* y_true  = (const float*)d_in[1];
  const float* ew      = (const float*)d_in[2];
  const float* hist    = (const float*)d_in[3];
  const float* enc_W1  = (const float*)d_in[4];
  const float* enc_b1  = (const float*)d_in[5];
  const float* enc_W2  = (const float*)d_in[6];
  const float* enc_b2  = (const float*)d_in[7];
  const float* gcn_W   = (const float*)d_in[8];
  const float* gcn_b   = (const float*)d_in[9];
  const float* mu_W    = (const float*)d_in[10];
  const float* mu_b    = (const float*)d_in[11];
  const float* sig_W   = (const float*)d_in[12];
  const float* sig_b   = (const float*)d_in[13];
  const float* gru_Wih = (const float*)d_in[14];
  const float* gru_Whh = (const float*)d_in[15];
  const float* gru_bih = (const float*)d_in[16];
  const float* gru_bhh = (const float*)d_in[17];
  const float* cm      = (const float*)d_in[18];
  const float* cm_W1   = (const float*)d_in[19];
  const float* cm_b1   = (const float*)d_in[20];
  const float* cm_W2   = (const float*)d_in[21];
  const float* cm_b2   = (const float*)d_in[22];
  const float* dec_W1  = (const float*)d_in[23];
  const float* dec_b1  = (const float*)d_in[24];
  const float* dec_W2  = (const float*)d_in[25];
  const float* dec_b2  = (const float*)d_in[26];
  const int*   esrc    = (const int*)d_in[27];
  const int*   edst    = (const int*)d_in[28];
  float* out = (float*)d_out;

  k_packall<<<(WF_TOT+255)/256, 256>>>(enc_W1, enc_W2, gcn_W, mu_W, sig_W,
                                       cm_W1, cm_W2, dec_W1, dec_W2,
                                       gru_Wih, gru_Whh);
  k_enc<<<dim3(BQ/64, NND), 128>>>(x, enc_b1, enc_b2);
  k_gcn<<<2560, 128>>>(0, ew, esrc, edst, gcn_b);
  k_gcn<<<2560, 128>>>(1, ew, esrc, edst, gcn_b);
  k_musig<<<2560, 128>>>(mu_b, sig_b);
  k_gru<<<BQ/32, 256>>>(0, nullptr, hist, gru_bih, gru_bhh, out + OFF_HID);
  k_gru<<<BQ/32, 256>>>(1, out + OFF_HID, hist, gru_bih, gru_bhh,
                        out + OFF_HID + BQ*HDIM);
  k_causal<<<BQ, 128>>>(ew, cm, esrc, edst);
  k_cm<<<2560, 128>>>(cm_b1, cm_b2);
  k_dec<<<dim3(BQ/64, NND), 128>>>(dec_b1, dec_b2, y_true, out);
  k_reduce1<<<134, 256>>>();
  k_final<<<1, 32>>>(out);
}

// round 7
// speedup vs baseline: 3.5257x; 1.1008x over previous
#include <cuda_runtime.h>
#include <cuda_bf16.h>
#include <math.h>

#define BQ   32768
#define NND  5
#define HDIM 128
#define NE   10

#define OFF_V    (BQ*NND*32)
#define OFF_HID  (2*BQ*NND*32)
#define OFF_LOSS (OFF_HID + 2*BQ*HDIM)

#define ZALPHA 1.959963984540054f

// fragment arena offsets (uint2 units)
#define WF_ENC1 0
#define WF_ENC2 10240
#define WF_GCN  51200
#define WF_MU   67584
#define WF_SIG  75776
#define WF_CM1  83968
#define WF_CM2  92160
#define WF_DEC1 100352
#define WF_DEC2 141312
#define WF_GI   161792
#define WF_GH   210944
#define WF_TOT  260096

// ----------------------------- device scratch -----------------------------
__device__ float g_bufA[BQ*NND*HDIM];
__device__ float g_bufB[BQ*NND*HDIM];
__device__ float g_mean[BQ*NND*HDIM];
__device__ float g_z  [BQ*NND*HDIM];
__device__ float g_ps [BQ*NND*HDIM];
__device__ uint2 g_Wf [WF_TOT];
__device__ float g_klpart[5120];
__device__ float g_lzpart[5120];
__device__ float g_losspart[5120*132];
__device__ float g_facc[134];

// ------------------------------- helpers ----------------------------------
__device__ __forceinline__ float warp_sum(float v){
#pragma unroll
  for (int o=16;o>0;o>>=1) v += __shfl_xor_sync(0xffffffffu, v, o);
  return v;
}
__device__ __forceinline__ float softplusf(float x){
  return fmaxf(x,0.f) + log1pf(expf(-fabsf(x)));
}
__device__ __forceinline__ float mishf(float x){ return x*tanhf(softplusf(x)); }
__device__ __forceinline__ float sigmf(float x){ return 1.f/(1.f+expf(-x)); }

// 8-warp deterministic block reduce
#define BLOCK_REDUCE8_TO(part, val)                                     \
  do {                                                                  \
    float _v = warp_sum(val);                                           \
    __shared__ float _sred[8];                                          \
    if ((threadIdx.x & 31) == 0) _sred[threadIdx.x >> 5] = _v;          \
    __syncthreads();                                                    \
    if (threadIdx.x == 0)                                               \
      part[blockIdx.x] = ((_sred[0]+_sred[1]) + (_sred[2]+_sred[3]))    \
                       + ((_sred[4]+_sred[5]) + (_sred[6]+_sred[7]));   \
  } while (0)

__device__ __forceinline__ unsigned pkh(float x, float y){
  unsigned short a = __bfloat16_as_ushort(__float2bfloat16_rn(x));
  unsigned short b = __bfloat16_as_ushort(__float2bfloat16_rn(y));
  return ((unsigned)b<<16) | (unsigned)a;
}
__device__ __forceinline__ float bf16f(float x){
  return __bfloat162float(__float2bfloat16_rn(x));
}
__device__ __forceinline__ unsigned sptr(const void* p){
  return (unsigned)__cvta_generic_to_shared(p);
}
__device__ __forceinline__ void ldsm4(unsigned a, unsigned &r0, unsigned &r1,
                                      unsigned &r2, unsigned &r3){
  asm volatile("ldmatrix.sync.aligned.m8n8.x4.shared.b16 {%0,%1,%2,%3}, [%4];"
               : "=r"(r0),"=r"(r1),"=r"(r2),"=r"(r3) : "r"(a));
}
__device__ __forceinline__ void mma16816(float* c, const unsigned* a,
                                         unsigned b0, unsigned b1){
  asm volatile("mma.sync.aligned.m16n8k16.row.col.f32.bf16.bf16.f32 "
      "{%0,%1,%2,%3},{%4,%5,%6,%7},{%8,%9},{%0,%1,%2,%3};"
      : "+f"(c[0]),"+f"(c[1]),"+f"(c[2]),"+f"(c[3])
      : "r"(a[0]),"r"(a[1]),"r"(a[2]),"r"(a[3]),"r"(b0),"r"(b1));
}
__device__ __forceinline__ void mma3(float* c, const unsigned* ah,
    const unsigned* al, uint2 bh, uint2 bl){
  mma16816(c, ah, bh.x, bh.y);
  mma16816(c, al, bh.x, bh.y);
  mma16816(c, ah, bl.x, bl.y);
}

__device__ __forceinline__ void split_st(float4 v, __nv_bfloat16* sh,
    __nv_bfloat16* sl, int off){
  *(uint2*)&sh[off] = make_uint2(pkh(v.x,v.y), pkh(v.z,v.w));
  *(uint2*)&sl[off] = make_uint2(pkh(v.x-bf16f(v.x), v.y-bf16f(v.y)),
                                 pkh(v.z-bf16f(v.z), v.w-bf16f(v.w)));
}

// stage ROWS x KC fp32 -> split bf16 hi/lo smem (row stride LDA bf16)
template<int ROWS, int KC, int LDA, int NT_>
__device__ __forceinline__ void stage_split(const float* __restrict__ A, int arst,
    __nv_bfloat16* sh, __nv_bfloat16* sl, int t){
  const int C4 = KC/4;
  for (int f=t; f<ROWS*C4; f+=NT_){
    int r = f/C4, c4 = (f%C4)*4;
    float4 v = *(const float4*)&A[(long)r*arst + c4];
    split_st(v, sh, sl, r*LDA+c4);
  }
}

// 3-term bf16 split mainloop, 1 m16-tile per warp, NT n8-tiles
template<int KT, int NT, int NTOT, int LDA>
__device__ __forceinline__ void hmma_row(const __nv_bfloat16* sh,
    const __nv_bfloat16* sl, const uint2* __restrict__ Wf,
    int n8base, int rowbase, int lane, float (&c)[NT][4]){
#pragma unroll
  for (int nt=0;nt<NT;nt++)
#pragma unroll
    for (int i=0;i<4;i++) c[nt][i] = 0.f;
  int sub = lane>>3;
  int m_off = ((sub&1)<<3) + (lane&7);
  int k_off = (sub>>1)<<3;
#pragma unroll 1
  for (int kt=0; kt<KT; kt++){
    uint2 bh[NT], bl[NT];
#pragma unroll
    for (int nt=0;nt<NT;nt++){
      const uint2* wp = Wf + (((kt*NTOT + n8base + nt)*2)<<5) + lane;
      bh[nt] = wp[0];
      bl[nt] = wp[32];
    }
    unsigned ah[4], al[4];
    int ro = (rowbase + m_off)*LDA + kt*16 + k_off;
    ldsm4(sptr(&sh[ro]), ah[0],ah[1],ah[2],ah[3]);
    ldsm4(sptr(&sl[ro]), al[0],al[1],al[2],al[3]);
#pragma unroll
    for (int nt=0;nt<NT;nt++)
      mma3(c[nt], ah, al, bh[nt], bl[nt]);
  }
}

// --------------------------- single pack kernel ----------------------------
__global__ void k_packall(
    const float* __restrict__ encW1, const float* __restrict__ encW2,
    const float* __restrict__ gcnW,  const float* __restrict__ muW,
    const float* __restrict__ sigW,  const float* __restrict__ cmW1,
    const float* __restrict__ cmW2,  const float* __restrict__ decW1,
    const float* __restrict__ decW2, const float* __restrict__ giW,
    const float* __restrict__ ghW){
  int idx = blockIdx.x*256 + threadIdx.x;
  if (idx >= WF_TOT) return;
  const float* src; int K, N, trans, base, per, mst;
  if      (idx < WF_ENC2){ src=encW1; K=32; N=128; trans=0; base=WF_ENC1; per=2048; mst=4096; }
  else if (idx < WF_GCN ){ src=encW2; K=128;N=128; trans=0; base=WF_ENC2; per=8192; mst=16384;}
  else if (idx < WF_MU  ){ src=gcnW;  K=128;N=128; trans=0; base=WF_GCN;  per=8192; mst=16384;}
  else if (idx < WF_SIG ){ src=muW;   K=128;N=128; trans=0; base=WF_MU;   per=8192; mst=16384;}
  else if (idx < WF_CM1 ){ src=sigW;  K=128;N=128; trans=0; base=WF_SIG;  per=8192; mst=16384;}
  else if (idx < WF_CM2 ){ src=cmW1;  K=128;N=128; trans=0; base=WF_CM1;  per=8192; mst=16384;}
  else if (idx < WF_DEC1){ src=cmW2;  K=128;N=128; trans=0; base=WF_CM2;  per=8192; mst=16384;}
  else if (idx < WF_DEC2){ src=decW1; K=128;N=128; trans=0; base=WF_DEC1; per=8192; mst=16384;}
  else if (idx < WF_GI  ){ src=decW2; K=128;N=64;  trans=0; base=WF_DEC2; per=4096; mst=8192; }
  else if (idx < WF_GH  ){ src=giW;   K=128;N=128; trans=1; base=WF_GI;   per=8192; mst=16384;}
  else                   { src=ghW;   K=128;N=128; trans=1; base=WF_GH;   per=8192; mst=16384;}
  int rr = idx - base;
  int m = rr / per, r = rr % per;
  int lane = r & 31, term = (r>>5)&1;
  int n8 = (r>>6) % (N>>3);
  int kt = (r>>6) / (N>>3);
  int n = n8*8 + (lane>>2);
  int k0 = kt*16 + ((lane&3)<<1);
  const float* S = src + (long)m*mst;
  float w0,w1,w2,w3;
  if (trans){
    w0=S[n*K+k0]; w1=S[n*K+k0+1]; w2=S[n*K+k0+8]; w3=S[n*K+k0+9];
  } else {
    w0=S[k0*N+n]; w1=S[(k0+1)*N+n]; w2=S[(k0+8)*N+n]; w3=S[(k0+9)*N+n];
  }
  uint2 o;
  if (term==0){ o = make_uint2(pkh(w0,w1), pkh(w2,w3)); }
  else {
    o = make_uint2(pkh(w0-bf16f(w0), w1-bf16f(w1)),
                   pkh(w2-bf16f(w2), w3-bf16f(w3)));
  }
  g_Wf[idx] = o;
}

// ------------------------------ encoder ------------------------------------
__global__ __launch_bounds__(256,4) void k_enc(
    const float* __restrict__ x, const float* __restrict__ b1,
    const float* __restrict__ b2){
  __shared__ __align__(16) __nv_bfloat16 xh[32*40], xl[32*40];
  __shared__ __align__(16) __nv_bfloat16 hh[32*136], hl[32*136];
  int t = threadIdx.x, lane = t&31, warp = t>>5;
  int wrow = warp>>2, wcol = warp&3;
  int n = blockIdx.y;
  long b0 = (long)blockIdx.x*32;
  stage_split<32,32,40,256>(x + b0*160 + n*32, 160, xh, xl, t);
  __syncthreads();
  float c[4][4];
  hmma_row<2,4,16,40>(xh, xl, &g_Wf[WF_ENC1 + n*2048], wcol*4, wrow*16, lane, c);
  __syncthreads();
  {
    int r0 = wrow*16 + (lane>>2);
#pragma unroll
    for (int nt=0;nt<4;nt++){
      int col = (wcol*4+nt)*8 + ((lane&3)<<1);
      float2 bb = *(const float2*)&b1[n*128 + col];
      float v00=fmaxf(c[nt][0]+bb.x,0.f), v01=fmaxf(c[nt][1]+bb.y,0.f);
      float v10=fmaxf(c[nt][2]+bb.x,0.f), v11=fmaxf(c[nt][3]+bb.y,0.f);
      *(unsigned*)&hh[r0*136+col] = pkh(v00,v01);
      *(unsigned*)&hl[r0*136+col] = pkh(v00-bf16f(v00), v01-bf16f(v01));
      *(unsigned*)&hh[(r0+8)*136+col] = pkh(v10,v11);
      *(unsigned*)&hl[(r0+8)*136+col] = pkh(v10-bf16f(v10), v11-bf16f(v11));
    }
  }
  __syncthreads();
  hmma_row<8,4,16,136>(hh, hl, &g_Wf[WF_ENC2 + n*8192], wcol*4, wrow*16, lane, c);
  {
    long r0 = b0 + wrow*16 + (lane>>2);
#pragma unroll
    for (int nt=0;nt<4;nt++){
      int col = (wcol*4+nt)*8 + ((lane&3)<<1);
      float2 bb = *(const float2*)&b2[n*128 + col];
      *(float2*)&g_bufA[r0*640 + n*128 + col] =
          make_float2(c[nt][0]+bb.x, c[nt][1]+bb.y);
      *(float2*)&g_bufA[(r0+8)*640 + n*128 + col] =
          make_float2(c[nt][2]+bb.x, c[nt][3]+bb.y);
    }
  }
}

// ------------------- GCN: fused aggregation + GEMM -------------------------
__global__ __launch_bounds__(256,4) void k_gcn(
    int l, const float* __restrict__ ew,
    const int* __restrict__ esrc, const int* __restrict__ edst,
    const float* __restrict__ bias){
  __shared__ __align__(16) __nv_bfloat16 sh[32*136], sl[32*136];
  __shared__ int s_src[NE], s_dst[NE];
  int t = threadIdx.x, lane = t&31, warp = t>>5;
  int wrow = warp>>2, wcol = warp&3;
  const float* gin  = (l==0) ? g_bufA : g_bufB;
  float*       gout = (l==0) ? g_bufB : g_bufA;
  long b0 = (long)blockIdx.x*32;
  if (t < NE){ s_src[t] = esrc[t]; s_dst[t] = edst[t]; }
  __syncthreads();
  for (int f=t; f<32*32; f+=256){
    int r = f>>5, c4 = (f&31)<<2;
    long R = b0 + r;
    int b = (int)(R/5), v = (int)(R - 5l*b);
    const float* row = gin + (long)b*640;
    float4 a = *(const float4*)&row[v*128 + c4];
#pragma unroll
    for (int e=0;e<NE;e++){
      if (s_dst[e] == v){
        float w = __ldg(&ew[b*NE + e]);
        float4 g = *(const float4*)&row[s_src[e]*128 + c4];
        a.x += w*g.x; a.y += w*g.y; a.z += w*g.z; a.w += w*g.w;
      }
    }
    split_st(a, sh, sl, r*136+c4);
  }
  __syncthreads();
  float c[4][4];
  hmma_row<8,4,16,136>(sh, sl, &g_Wf[WF_GCN + l*8192], wcol*4, wrow*16, lane, c);
  {
    long r0 = b0 + wrow*16 + (lane>>2);
#pragma unroll
    for (int nt=0;nt<4;nt++){
      int col = (wcol*4+nt)*8 + ((lane&3)<<1);
      float2 bb = *(const float2*)&bias[l*128 + col];
      *(float2*)&gout[r0*128 + col] = make_float2(
          fmaxf(c[nt][0]+bb.x,0.f), fmaxf(c[nt][1]+bb.y,0.f));
      *(float2*)&gout[(r0+8)*128 + col] = make_float2(
          fmaxf(c[nt][2]+bb.x,0.f), fmaxf(c[nt][3]+bb.y,0.f));
    }
  }
}

// ----------------------- mu/sig heads + KL ---------------------------------
__global__ __launch_bounds__(256,4) void k_musig(
    const float* __restrict__ mub, const float* __restrict__ sigb){
  __shared__ __align__(16) __nv_bfloat16 sh[32*136], sl[32*136];
  int t = threadIdx.x, lane = t&31, warp = t>>5;
  int wrow = warp>>2, wcol = warp&3;
  long b0 = (long)blockIdx.x*32;
  stage_split<32,128,136,256>(g_bufA + b0*128, 128, sh, sl, t);
  __syncthreads();
  float c[4][4];
  float kll = 0.f;
  hmma_row<8,4,16,136>(sh, sl, &g_Wf[WF_MU], wcol*4, wrow*16, lane, c);
  {
    long r0 = b0 + wrow*16 + (lane>>2);
#pragma unroll
    for (int nt=0;nt<4;nt++){
      int col = (wcol*4+nt)*8 + ((lane&3)<<1);
      float2 bb = *(const float2*)&mub[col];
      float m00=c[nt][0]+bb.x, m01=c[nt][1]+bb.y;
      float m10=c[nt][2]+bb.x, m11=c[nt][3]+bb.y;
      *(float2*)&g_mean[r0*128 + col]     = make_float2(m00,m01);
      *(float2*)&g_mean[(r0+8)*128 + col] = make_float2(m10,m11);
      kll += m00*m00 + m01*m01 + m10*m10 + m11*m11;
    }
  }
  hmma_row<8,4,16,136>(sh, sl, &g_Wf[WF_SIG], wcol*4, wrow*16, lane, c);
#pragma unroll
  for (int nt=0;nt<4;nt++){
    int col = (wcol*4+nt)*8 + ((lane&3)<<1);
    float2 bb = *(const float2*)&sigb[col];
#pragma unroll
    for (int i=0;i<4;i++){
      float sp = softplusf(c[nt][i] + ((i&1)?bb.y:bb.x));
      float var = sp*sp;
      kll += var - logf(var + 1e-8f) - 1.f;
    }
  }
  BLOCK_REDUCE8_TO(g_klpart, kll);
}

// ------------- GRU: fused dual-GEMM + gates (one kernel per layer) ---------
__global__ __launch_bounds__(256) void k_gru(
    int l, const float* __restrict__ xin, const float* __restrict__ hist,
    const float* __restrict__ bih, const float* __restrict__ bhh,
    float* __restrict__ hout){
  __shared__ __align__(16) __nv_bfloat16 xh[32*136], xl[32*136];
  __shared__ __align__(16) __nv_bfloat16 hhs[32*136], hls[32*136];
  int t = threadIdx.x, lane = t&31, warp = t>>5;   // 8 warps
  long b0 = (long)blockIdx.x*32;
  for (int f=t; f<32*32; f+=256){
    int r = f>>5, c4 = (f&31)<<2;
    long b = b0 + r;
    float4 v;
    if (xin){
      v = *(const float4*)&xin[b*128 + c4];
    } else {
      v = *(const float4*)&g_mean[b*640 + c4];
#pragma unroll
      for (int vv=1; vv<5; vv++){
        float4 m = *(const float4*)&g_mean[b*640 + vv*128 + c4];
        v.x+=m.x; v.y+=m.y; v.z+=m.z; v.w+=m.w;
      }
      v.x*=0.2f; v.y*=0.2f; v.z*=0.2f; v.w*=0.2f;
    }
    split_st(v, xh, xl, r*136+c4);
    float4 hv = *(const float4*)&hist[((long)l*BQ + b)*128 + c4];
    split_st(hv, hhs, hls, r*136+c4);
  }
  __syncthreads();
  float cr[2][2][4], cz[2][2][4], cin[2][2][4], chn[2][2][4];
#pragma unroll
  for (int mt=0;mt<2;mt++)
#pragma unroll
    for (int nt=0;nt<2;nt++)
#pragma unroll
      for (int i=0;i<4;i++){ cr[mt][nt][i]=0.f; cz[mt][nt][i]=0.f;
                             cin[mt][nt][i]=0.f; chn[mt][nt][i]=0.f; }
  int sub = lane>>3;
  int m_off = ((sub&1)<<3) + (lane&7);
  int k_off = (sub>>1)<<3;
  const uint2* Wi = &g_Wf[WF_GI + l*3*8192];
  const uint2* Wh = &g_Wf[WF_GH + l*3*8192];
#pragma unroll 1
  for (int kt=0; kt<8; kt++){
    unsigned axh[2][4], axl[2][4], ahh[2][4], ahl[2][4];
#pragma unroll
    for (int mt=0;mt<2;mt++){
      int ro = (mt*16 + m_off)*136 + kt*16 + k_off;
      ldsm4(sptr(&xh[ro]),  axh[mt][0],axh[mt][1],axh[mt][2],axh[mt][3]);
      ldsm4(sptr(&xl[ro]),  axl[mt][0],axl[mt][1],axl[mt][2],axl[mt][3]);
      ldsm4(sptr(&hhs[ro]), ahh[mt][0],ahh[mt][1],ahh[mt][2],ahh[mt][3]);
      ldsm4(sptr(&hls[ro]), ahl[mt][0],ahl[mt][1],ahl[mt][2],ahl[mt][3]);
    }
#pragma unroll
    for (int nt=0;nt<2;nt++){
      int fo = (((kt*16 + warp*2 + nt)*2)<<5) + lane;
      { uint2 bh=Wi[fo], bl=Wi[fo+32];
        uint2 ch=Wh[fo], cl=Wh[fo+32];
#pragma unroll
        for (int mt=0;mt<2;mt++){
          mma3(cr[mt][nt], axh[mt], axl[mt], bh, bl);
          mma3(cr[mt][nt], ahh[mt], ahl[mt], ch, cl);
        } }
      { uint2 bh=Wi[8192+fo], bl=Wi[8192+fo+32];
        uint2 ch=Wh[8192+fo], cl=Wh[8192+fo+32];
#pragma unroll
        for (int mt=0;mt<2;mt++){
          mma3(cz[mt][nt], axh[mt], axl[mt], bh, bl);
          mma3(cz[mt][nt], ahh[mt], ahl[mt], ch, cl);
        } }
      { uint2 bh=Wi[16384+fo], bl=Wi[16384+fo+32];
        uint2 ch=Wh[16384+fo], cl=Wh[16384+fo+32];
#pragma unroll
        for (int mt=0;mt<2;mt++){
          mma3(cin[mt][nt], axh[mt], axl[mt], bh, bl);
          mma3(chn[mt][nt], ahh[mt], ahl[mt], ch, cl);
        } }
    }
  }
#pragma unroll
  for (int mt=0;mt<2;mt++){
    long gb = b0 + mt*16 + (lane>>2);
#pragma unroll
    for (int nt=0;nt<2;nt++){
      int col = warp*16 + nt*8 + ((lane&3)<<1);
      float2 bir = *(const float2*)&bih[l*384 + col];
      float2 biz = *(const float2*)&bih[l*384 + 128 + col];
      float2 bin_= *(const float2*)&bih[l*384 + 256 + col];
      float2 bhr = *(const float2*)&bhh[l*384 + col];
      float2 bhz = *(const float2*)&bhh[l*384 + 128 + col];
      float2 bhn = *(const float2*)&bhh[l*384 + 256 + col];
      float2 hp0 = *(const float2*)&hist[((long)l*BQ + gb)*128 + col];
      float2 hp1 = *(const float2*)&hist[((long)l*BQ + gb + 8)*128 + col];
      float r0=sigmf(cr[mt][nt][0]+bir.x+bhr.x);
      float r1=sigmf(cr[mt][nt][1]+bir.y+bhr.y);
      float r2=sigmf(cr[mt][nt][2]+bir.x+bhr.x);
      float r3=sigmf(cr[mt][nt][3]+bir.y+bhr.y);
      float z0=sigmf(cz[mt][nt][0]+biz.x+bhz.x);
      float z1=sigmf(cz[mt][nt][1]+biz.y+bhz.y);
      float z2=sigmf(cz[mt][nt][2]+biz.x+bhz.x);
      float z3=sigmf(cz[mt][nt][3]+biz.y+bhz.y);
      float n0=tanhf(cin[mt][nt][0]+bin_.x + r0*(chn[mt][nt][0]+bhn.x));
      float n1=tanhf(cin[mt][nt][1]+bin_.y + r1*(chn[mt][nt][1]+bhn.y));
      float n2=tanhf(cin[mt][nt][2]+bin_.x + r2*(chn[mt][nt][2]+bhn.x));
      float n3=tanhf(cin[mt][nt][3]+bin_.y + r3*(chn[mt][nt][3]+bhn.y));
      *(float2*)&hout[gb*128 + col] =
          make_float2((1.f-z0)*n0 + z0*hp0.x, (1.f-z1)*n1 + z1*hp0.y);
      *(float2*)&hout[(gb+8)*128 + col] =
          make_float2((1.f-z2)*n2 + z2*hp1.x, (1.f-z3)*n3 + z3*hp1.y);
    }
  }
}

// --------------------- causal solve + parent_sum ---------------------------
__global__ __launch_bounds__(128) void k_causal(
    const float* __restrict__ ew, const float* __restrict__ cm,
    const int* __restrict__ esrc, const int* __restrict__ edst){
  int b = blockIdx.x, t = threadIdx.x;
  __shared__ float s_ew[NE], s_cm[NND*NND];
  __shared__ int s_src[NE], s_dst[NE];
  if (t < NE){ s_ew[t] = ew[b*NE + t]; s_src[t] = esrc[t]; s_dst[t] = edst[t]; }
  if (t < NND*NND) s_cm[t] = cm[t];
  __syncthreads();
  int base = b*NND*HDIM + t;
  float z[NND];
#pragma unroll
  for (int j=0;j<NND;j++) z[j] = g_mean[base + j*HDIM];
#pragma unroll
  for (int j=1;j<NND;j++){
    float add = 0.f;
#pragma unroll
    for (int e=0;e<NE;e++){
      if (s_dst[e] == j){
        int s = s_src[e];
        float zs = (s==0)?z[0]:((s==1)?z[1]:((s==2)?z[2]:z[3]));
        add += s_ew[e]*s_cm[s*NND + j]*zs;
      }
    }
    z[j] += add;
  }
#pragma unroll
  for (int j=0;j<NND;j++) g_z[base + j*HDIM] = z[j];
#pragma unroll
  for (int j=0;j<NND;j++){
    float ps = 0.f;
#pragma unroll
    for (int i=0;i<NND;i++)
      if (s_cm[i*NND + j] != 0.f) ps += z[i];
    g_ps[base + j*HDIM] = ps;
  }
}

// ------------------- cm MLP fused (2 GEMMs) + l_z --------------------------
__global__ __launch_bounds__(256,4) void k_cm(
    const float* __restrict__ b1, const float* __restrict__ b2){
  __shared__ __align__(16) __nv_bfloat16 sh[32*136], sl[32*136];
  int t = threadIdx.x, lane = t&31, warp = t>>5;
  int wrow = warp>>2, wcol = warp&3;
  long b0 = (long)blockIdx.x*32;
  stage_split<32,128,136,256>(g_ps + b0*128, 128, sh, sl, t);
  __syncthreads();
  float c[4][4];
  hmma_row<8,4,16,136>(sh, sl, &g_Wf[WF_CM1], wcol*4, wrow*16, lane, c);
  __syncthreads();
  {
    int r0 = wrow*16 + (lane>>2);
#pragma unroll
    for (int nt=0;nt<4;nt++){
      int col = (wcol*4+nt)*8 + ((lane&3)<<1);
      float2 bb = *(const float2*)&b1[col];
      float v00=mishf(c[nt][0]+bb.x), v01=mishf(c[nt][1]+bb.y);
      float v10=mishf(c[nt][2]+bb.x), v11=mishf(c[nt][3]+bb.y);
      *(unsigned*)&sh[r0*136+col] = pkh(v00,v01);
      *(unsigned*)&sl[r0*136+col] = pkh(v00-bf16f(v00), v01-bf16f(v01));
      *(unsigned*)&sh[(r0+8)*136+col] = pkh(v10,v11);
      *(unsigned*)&sl[(r0+8)*136+col] = pkh(v10-bf16f(v10), v11-bf16f(v11));
    }
  }
  __syncthreads();
  hmma_row<8,4,16,136>(sh, sl, &g_Wf[WF_CM2], wcol*4, wrow*16, lane, c);
  float lz = 0.f;
  {
    long r0 = b0 + wrow*16 + (lane>>2);
#pragma unroll
    for (int nt=0;nt<4;nt++){
      int col = (wcol*4+nt)*8 + ((lane&3)<<1);
      float2 bb = *(const float2*)&b2[col];
      float2 z0 = *(const float2*)&g_z[r0*128 + col];
      float2 z1 = *(const float2*)&g_z[(r0+8)*128 + col];
      float d0 = z0.x - (c[nt][0]+bb.x);
      float d1 = z0.y - (c[nt][1]+bb.y);
      float d2 = z1.x - (c[nt][2]+bb.x);
      float d3 = z1.y - (c[nt][3]+bb.y);
      lz += d0*d0 + d1*d1 + d2*d2 + d3*d3;
    }
  }
  BLOCK_REDUCE8_TO(g_lzpart, lz);
}

// ----------------- decoder fused (2 GEMMs) + losses ------------------------
__global__ __launch_bounds__(256,4) void k_dec(
    const float* __restrict__ b1, const float* __restrict__ b2,
    const float* __restrict__ yt_g, float* __restrict__ out){
  __shared__ __align__(16) __nv_bfloat16 sh[32*136], sl[32*136];
  __shared__ float s_piw[8][32], s_kd[8][32], s_mn[8][32], s_mx[8][32];
  __shared__ float s_sc[3][8];
  float* s_out = (float*)sh;     // 32*66 floats = 8448B <= 8704B ✓
  int t = threadIdx.x, lane = t&31, warp = t>>5;
  int wrow = warp>>2, wcol = warp&3;
  int n = blockIdx.y;
  long b0 = (long)blockIdx.x*32;
  stage_split<32,128,136,256>(g_z + b0*640 + n*128, 640, sh, sl, t);
  __syncthreads();
  float c[4][4];
  hmma_row<8,4,16,136>(sh, sl, &g_Wf[WF_DEC1 + n*8192], wcol*4, wrow*16, lane, c);
  __syncthreads();
  {
    int r0 = wrow*16 + (lane>>2);
#pragma unroll
    for (int nt=0;nt<4;nt++){
      int col = (wcol*4+nt)*8 + ((lane&3)<<1);
      float2 bb = *(const float2*)&b1[n*128 + col];
      float v00=mishf(c[nt][0]+bb.x), v01=mishf(c[nt][1]+bb.y);
      float v10=mishf(c[nt][2]+bb.x), v11=mishf(c[nt][3]+bb.y);
      *(unsigned*)&sh[r0*136+col] = pkh(v00,v01);
      *(unsigned*)&sl[r0*136+col] = pkh(v00-bf16f(v00), v01-bf16f(v01));
      *(unsigned*)&sh[(r0+8)*136+col] = pkh(v10,v11);
      *(unsigned*)&sl[(r0+8)*136+col] = pkh(v10-bf16f(v10), v11-bf16f(v11));
    }
  }
  __syncthreads();
  float c2[2][4];
  hmma_row<8,2,8,136>(sh, sl, &g_Wf[WF_DEC2 + n*4096], wcol*2, wrow*16, lane, c2);
  __syncthreads();   // all reads of sh done before aliasing as s_out
  {
    int r = wrow*16 + (lane>>2);
#pragma unroll
    for (int nt=0;nt<2;nt++){
      int col = (wcol*2+nt)*8 + ((lane&3)<<1);
      float2 bb = *(const float2*)&b2[n*64 + col];
      float v00=c2[nt][0]+bb.x, v01=c2[nt][1]+bb.y;
      float v10=c2[nt][2]+bb.x, v11=c2[nt][3]+bb.y;
      if (col >= 32){ v00=expf(v00); v01=expf(v01); v10=expf(v10); v11=expf(v11); }
      s_out[r*66+col]=v00;     s_out[r*66+col+1]=v01;
      s_out[(r+8)*66+col]=v10; s_out[(r+8)*66+col+1]=v11;
      long gb0, gb1;
      if (col < 32){
        gb0 = (b0+r)*160 + n*32 + col;
        gb1 = (b0+r+8)*160 + n*32 + col;
      } else {
        gb0 = (long)OFF_V + (b0+r)*160 + n*32 + col-32;
        gb1 = (long)OFF_V + (b0+r+8)*160 + n*32 + col-32;
      }
      *(float2*)&out[gb0] = make_float2(v00,v01);
      *(float2*)&out[gb1] = make_float2(v10,v11);
    }
  }
  __syncthreads();
  int d = lane;
  float ll=0.f, sq4=0.f, bce=0.f;
  float piw=0.f, kd=0.f, mn=1e30f, mx=-1e30f;
#pragma unroll
  for (int i=0;i<4;i++){
    int row = warp + 8*i;
    float ym = s_out[row*66 + d];
    float yv = s_out[row*66 + 32 + d];
    float yt = yt_g[(b0+row)*160 + n*32 + d];
    float vs = yv + 1e-6f;
    float df = yt - ym;
    ll += -0.5f*(df*df/vs + logf(6.2831853071795864f*vs));
    if (n < 4) sq4 += df*df;
    if (n == 4) bce += fmaxf(ym,0.f) - ym*yt + log1pf(expf(-fabsf(ym)));
    float s  = sqrtf(vs);
    float lo_ = ym - ZALPHA*s, up_ = ym + ZALPHA*s;
    float kf = (yt >= lo_ && yt <= up_) ? 1.f : 0.f;
    kd  += kf;
    piw += (up_-lo_)*kf;
    mn = fminf(mn, yt);
    mx = fmaxf(mx, yt);
  }
  ll  = warp_sum(ll);
  sq4 = warp_sum(sq4);
  bce = warp_sum(bce);
  if (lane == 0){ s_sc[0][warp]=ll; s_sc[1][warp]=sq4; s_sc[2][warp]=bce; }
  s_piw[warp][d]=piw; s_kd[warp][d]=kd; s_mn[warp][d]=mn; s_mx[warp][d]=mx;
  __syncthreads();
  int blk = blockIdx.y*gridDim.x + blockIdx.x;
  float* P = g_losspart + blk*132;
  if (t == 0){
    P[0] = ((s_sc[0][0]+s_sc[0][1]) + (s_sc[0][2]+s_sc[0][3]))
         + ((s_sc[0][4]+s_sc[0][5]) + (s_sc[0][6]+s_sc[0][7]));
    P[1] = ((s_sc[1][0]+s_sc[1][1]) + (s_sc[1][2]+s_sc[1][3]))
         + ((s_sc[1][4]+s_sc[1][5]) + (s_sc[1][6]+s_sc[1][7]));
    P[2] = ((s_sc[2][0]+s_sc[2][1]) + (s_sc[2][2]+s_sc[2][3]))
         + ((s_sc[2][4]+s_sc[2][5]) + (s_sc[2][6]+s_sc[2][7]));
    P[3] = 0.f;
  }
  if (t < 32){
    float p=0.f, k=0.f, m=1e30f, xx=-1e30f;
#pragma unroll
    for (int g=0; g<8; g++){
      p += s_piw[g][t]; k += s_kd[g][t];
      m = fminf(m, s_mn[g][t]); xx = fmaxf(xx, s_mx[g][t]);
    }
    P[4+t] = p; P[36+t] = k; P[68+t] = m; P[100+t] = xx;
  }
}

// ---------------------- stage-1 reduce + final -----------------------------
__global__ void k_reduce1(){
  int col = blockIdx.x, t = threadIdx.x;
  bool ismin = (col >= 68 && col < 100);
  bool ismax = (col >= 100 && col < 132);
  float v = ismin ? 1e30f : (ismax ? -1e30f : 0.f);
  if (col < 132){
    for (int i=t; i<5120; i+=256){
      float x = g_losspart[i*132 + col];
      v = ismin ? fminf(v,x) : (ismax ? fmaxf(v,x) : v + x);
    }
  } else if (col == 132){
    for (int i=t; i<5120; i+=256) v += g_klpart[i];
  } else {
    for (int i=t; i<5120; i+=256) v += g_lzpart[i];
  }
  __shared__ float sm[256];
  sm[t] = v;
  __syncthreads();
  for (int s=128; s>0; s>>=1){
    if (t < s){
      float a = sm[t], b = sm[t+s];
      sm[t] = ismin ? fminf(a,b) : (ismax ? fmaxf(a,b) : a + b);
    }
    __syncthreads();
  }
  if (t == 0) g_facc[col] = sm[0];
}

__global__ void k_final(float* __restrict__ out){
  if (threadIdx.x != 0 || blockIdx.x != 0) return;
  float S_ll = g_facc[0], S_sq4 = g_facc[1], S_bce = g_facc[2];
  float kl = 0.5f*g_facc[132];
  float S_lz = g_facc[133];
  float mean_ll = S_ll / 5242880.0f;
  float elbo = kl/32768.0f - mean_ll;
  float l_reg = (S_sq4/32.0f) / (4.0f*32768.0f + 1e-6f);
  float l_cls = (S_bce/32.0f) / (32768.0f + 1e-6f);
  float l_rec = l_reg + l_cls;
  float Sk = 0.f, pin = 0.f;
  for (int d=0; d<32; d++){
    float kdv = g_facc[36+d];
    Sk += kdv;
    pin += g_facc[4+d] / (kdv + 1e-6f) / (g_facc[100+d] - g_facc[68+d] + 1e-6f);
  }
  float picp  = Sk / 5242880.0f;
  float pinaw = pin / 32.0f;
  float l_pi  = pinaw - sqrtf(5.0f)*picp;
  float l_z   = S_lz / 20971520.0f;
  float dag   = 0.0f;  // exact: diag((I+ac)^5)==1 for strictly-upper ac
  float total = powf(elbo*l_rec*l_pi*l_z*(dag + 1e-6f), 0.2f);
  out[OFF_LOSS+0] = total;
  out[OFF_LOSS+1] = elbo;
  out[OFF_LOSS+2] = l_rec;
  out[OFF_LOSS+3] = l_pi;
  out[OFF_LOSS+4] = l_z;
  out[OFF_LOSS+5] = dag;
}

// ------------------------------ launcher -----------------------------------
extern "C" void kernel_launch(void* const* d_in, const int* in_sizes, int n_in,
                              void* d_out, int out_size){
  const float* x       = (const float*)d_in[0];
  const float* y_true  = (const float*)d_in[1];
  const float* ew      = (const float*)d_in[2];
  const float* hist    = (const float*)d_in[3];
  const float* enc_W1  = (const float*)d_in[4];
  const float* enc_b1  = (const float*)d_in[5];
  const float* enc_W2  = (const float*)d_in[6];
  const float* enc_b2  = (const float*)d_in[7];
  const float* gcn_W   = (const float*)d_in[8];
  const float* gcn_b   = (const float*)d_in[9];
  const float* mu_W    = (const float*)d_in[10];
  const float* mu_b    = (const float*)d_in[11];
  const float* sig_W   = (const float*)d_in[12];
  const float* sig_b   = (const float*)d_in[13];
  const float* gru_Wih = (const float*)d_in[14];
  const float* gru_Whh = (const float*)d_in[15];
  const float* gru_bih = (const float*)d_in[16];
  const float* gru_bhh = (const float*)d_in[17];
  const float* cm      = (const float*)d_in[18];
  const float* cm_W1   = (const float*)d_in[19];
  const float* cm_b1   = (const float*)d_in[20];
  const float* cm_W2   = (const float*)d_in[21];
  const float* cm_b2   = (const float*)d_in[22];
  const float* dec_W1  = (const float*)d_in[23];
  const float* dec_b1  = (const float*)d_in[24];
  const float* dec_W2  = (const float*)d_in[25];
  const float* dec_b2  = (const float*)d_in[26];
  const int*   esrc    = (const int*)d_in[27];
  const int*   edst    = (const int*)d_in[28];
  float* out = (float*)d_out;

  k_packall<<<(WF_TOT+255)/256, 256>>>(enc_W1, enc_W2, gcn_W, mu_W, sig_W,
                                       cm_W1, cm_W2, dec_W1, dec_W2,
                                       gru_Wih, gru_Whh);
  k_enc<<<dim3(BQ/32, NND), 256>>>(x, enc_b1, enc_b2);
  k_gcn<<<5120, 256>>>(0, ew, esrc, edst, gcn_b);
  k_gcn<<<5120, 256>>>(1, ew, esrc, edst, gcn_b);
  k_musig<<<5120, 256>>>(mu_b, sig_b);
  k_gru<<<BQ/32, 256>>>(0, nullptr, hist, gru_bih, gru_bhh, out + OFF_HID);
  k_gru<<<BQ/32, 256>>>(1, out + OFF_HID, hist, gru_bih, gru_bhh,
                        out + OFF_HID + BQ*HDIM);
  k_causal<<<BQ, 128>>>(ew, cm, esrc, edst);
  k_cm<<<5120, 256>>>(cm_b1, cm_b2);
  k_dec<<<dim3(BQ/32, NND), 256>>>(dec_b1, dec_b2, y_true, out);
  k_reduce1<<<134, 256>>>();
  k_final<<<1, 32>>>(out);
}